// round 1
// baseline (speedup 1.0000x reference)
#include <cuda_runtime.h>
#include <math.h>

#define SEQ   2048
#define BATCH 2
#define NH    16
#define HD    64
#define EMB   1024
#define E3    3072
#define NROWS (BATCH*SEQ)          // 4096
#define NBIAS (2*SEQ-1)            // 4095

// Scratch (allocation-free rule: __device__ globals)
__device__ float g_qkv[(size_t)NROWS * E3];   // 48 MB
__device__ float g_attn[(size_t)NROWS * EMB]; // 16 MB
__device__ float g_bias[NH * NBIAS];          // 256 KB

// ---------------------------------------------------------------------------
// Bias table: bias[h][d + SEQ-1] = rel_emb[bucket(d)][h],  d = k - q
// ---------------------------------------------------------------------------
__global__ void bias_kernel(const float* __restrict__ rel_emb) {
    int i = blockIdx.x * blockDim.x + threadIdx.x;
    if (i >= NBIAS) return;
    int d  = i - (SEQ - 1);
    int rb = (d > 0) ? 16 : 0;     // num_buckets//2 offset for positive side
    int ad = d < 0 ? -d : d;
    int bucket;
    if (ad < 8) {
        bucket = ad;
    } else {
        // log(ad/8)/log(16) * 8, truncated, capped at 15
        float v  = logf((float)ad * 0.125f) / 2.7725887f;
        int   lg = 8 + (int)(v * 8.0f);
        bucket = lg < 15 ? lg : 15;
    }
    int idx = rb + bucket;
    #pragma unroll
    for (int h = 0; h < NH; h++)
        g_bias[h * NBIAS + i] = rel_emb[idx * NH + h];
}

// ---------------------------------------------------------------------------
// SGEMM: C[M,N] = A[M,K] @ B[K,N], all row-major. 128x128 tile, BK=16,
// 256 threads, 8x8 per thread. M,N,K all multiples of the tile sizes here.
// ---------------------------------------------------------------------------
__global__ __launch_bounds__(256) void sgemm_kernel(
    const float* __restrict__ A, const float* __restrict__ B,
    float* __restrict__ C, int M, int N, int K)
{
    __shared__ float As[16][132];   // transposed A tile, +4 pad (2-way max)
    __shared__ float Bs[16][128];
    const int tid = threadIdx.x;
    const int tr = tid >> 4, tc = tid & 15;

    const float* Ab = A + (size_t)blockIdx.y * 128 * K;
    const float* Bb = B + (size_t)blockIdx.x * 128;

    float acc[8][8];
    #pragma unroll
    for (int i = 0; i < 8; i++)
        #pragma unroll
        for (int j = 0; j < 8; j++) acc[i][j] = 0.f;

    for (int k0 = 0; k0 < K; k0 += 16) {
        #pragma unroll
        for (int it = 0; it < 2; it++) {              // A: 128x16, float4 loads
            int i4 = tid + it * 256;                  // 0..511
            int m  = i4 >> 2, c4 = (i4 & 3) << 2;
            float4 v = *(const float4*)(Ab + (size_t)m * K + k0 + c4);
            As[c4 + 0][m] = v.x; As[c4 + 1][m] = v.y;
            As[c4 + 2][m] = v.z; As[c4 + 3][m] = v.w;
        }
        #pragma unroll
        for (int it = 0; it < 2; it++) {              // B: 16x128, float4
            int i4 = tid + it * 256;
            int kk = i4 >> 5, n4 = (i4 & 31) << 2;
            *(float4*)&Bs[kk][n4] = *(const float4*)(Bb + (size_t)(k0 + kk) * N + n4);
        }
        __syncthreads();
        #pragma unroll
        for (int kk = 0; kk < 16; kk++) {
            __align__(16) float a[8], b[8];
            *(float4*)&a[0] = *(const float4*)&As[kk][tr * 8];
            *(float4*)&a[4] = *(const float4*)&As[kk][tr * 8 + 4];
            *(float4*)&b[0] = *(const float4*)&Bs[kk][tc * 8];
            *(float4*)&b[4] = *(const float4*)&Bs[kk][tc * 8 + 4];
            #pragma unroll
            for (int i = 0; i < 8; i++)
                #pragma unroll
                for (int j = 0; j < 8; j++)
                    acc[i][j] = fmaf(a[i], b[j], acc[i][j]);
        }
        __syncthreads();
    }

    float* Cb = C + (size_t)(blockIdx.y * 128 + tr * 8) * N + blockIdx.x * 128 + tc * 8;
    #pragma unroll
    for (int i = 0; i < 8; i++) {
        *(float4*)(Cb + (size_t)i * N)     = make_float4(acc[i][0], acc[i][1], acc[i][2], acc[i][3]);
        *(float4*)(Cb + (size_t)i * N + 4) = make_float4(acc[i][4], acc[i][5], acc[i][6], acc[i][7]);
    }
}

// ---------------------------------------------------------------------------
// Flash attention: one block = 64 q-rows of one (b,h). 256 threads = 16x16
// grid, 4x4 outputs per thread. Online softmax, K staged d-major (+1 pad).
// ---------------------------------------------------------------------------
#define ATTN_SMEM ((64*64*3 + 64*65) * 4)

__global__ __launch_bounds__(256) void attn_kernel() {
    extern __shared__ float sm[];
    float* Qs = sm;                 // [64][64] row-major (q-row, d)
    float* Kt = sm + 4096;          // [64][65] d-major   (d, k-row)
    float* Vs = Kt + 64 * 65;       // [64][64] row-major (k-row, d)
    float* Ps = Vs + 4096;          // [64][64] row-major (q-row, k-col)

    const int tid = threadIdx.x;
    const int tr = tid >> 4, tc = tid & 15;
    const int q0 = blockIdx.x * 64;
    const int b = blockIdx.y >> 4, h = blockIdx.y & 15;
    const size_t rowbase = (size_t)b * SEQ;

    // Load Q tile
    const float* Qg = g_qkv + (rowbase + q0) * E3 + h * HD;
    #pragma unroll
    for (int it = 0; it < 4; it++) {
        int i4 = tid + it * 256;
        int r = i4 >> 4, c4 = (i4 & 15) << 2;
        *(float4*)(Qs + r * 64 + c4) = *(const float4*)(Qg + (size_t)r * E3 + c4);
    }

    float m_i[4], l_i[4], acc[4][4];
    #pragma unroll
    for (int i = 0; i < 4; i++) {
        m_i[i] = -INFINITY; l_i[i] = 0.f;
        #pragma unroll
        for (int j = 0; j < 4; j++) acc[i][j] = 0.f;
    }
    const float* bias_h = g_bias + h * NBIAS;

    for (int kt = 0; kt < SEQ / 64; kt++) {
        __syncthreads();   // previous tile fully consumed (also orders Q stores, iter 0)
        const float* Kg = g_qkv + (rowbase + kt * 64) * E3 + EMB + h * HD;
        #pragma unroll
        for (int it = 0; it < 4; it++) {
            int i4 = tid + it * 256;
            int r = i4 >> 4, c4 = (i4 & 15) << 2;
            float4 kv = *(const float4*)(Kg + (size_t)r * E3 + c4);
            Kt[(c4 + 0) * 65 + r] = kv.x;
            Kt[(c4 + 1) * 65 + r] = kv.y;
            Kt[(c4 + 2) * 65 + r] = kv.z;
            Kt[(c4 + 3) * 65 + r] = kv.w;
            *(float4*)(Vs + r * 64 + c4) = *(const float4*)(Kg + EMB + (size_t)r * E3 + c4);
        }
        __syncthreads();

        // Scores S = Q @ K^T  (4x4 per thread)
        __align__(16) float s[4][4];
        #pragma unroll
        for (int i = 0; i < 4; i++)
            #pragma unroll
            for (int j = 0; j < 4; j++) s[i][j] = 0.f;

        #pragma unroll
        for (int d0 = 0; d0 < 64; d0 += 4) {
            __align__(16) float q[4][4];
            #pragma unroll
            for (int i = 0; i < 4; i++)
                *(float4*)q[i] = *(const float4*)(Qs + (tr * 4 + i) * 64 + d0);
            #pragma unroll
            for (int dd = 0; dd < 4; dd++) {
                float kj[4];
                #pragma unroll
                for (int j = 0; j < 4; j++) kj[j] = Kt[(d0 + dd) * 65 + tc * 4 + j];
                #pragma unroll
                for (int i = 0; i < 4; i++)
                    #pragma unroll
                    for (int j = 0; j < 4; j++)
                        s[i][j] = fmaf(q[i][dd], kj[j], s[i][j]);
            }
        }

        // Bias + online softmax (16 lanes of same tr form a contiguous shfl group)
        int coloff = kt * 64 + tc * 4 - q0 - tr * 4 + (SEQ - 1);
        #pragma unroll
        for (int i = 0; i < 4; i++) {
            const float* bp = bias_h + coloff - i;
            float mx = -INFINITY;
            #pragma unroll
            for (int j = 0; j < 4; j++) { s[i][j] += bp[j]; mx = fmaxf(mx, s[i][j]); }
            mx = fmaxf(mx, __shfl_xor_sync(0xffffffffu, mx, 1));
            mx = fmaxf(mx, __shfl_xor_sync(0xffffffffu, mx, 2));
            mx = fmaxf(mx, __shfl_xor_sync(0xffffffffu, mx, 4));
            mx = fmaxf(mx, __shfl_xor_sync(0xffffffffu, mx, 8));
            float mnew = fmaxf(m_i[i], mx);
            float corr = expf(m_i[i] - mnew);   // first tile: exp(-inf)=0
            float rs = 0.f;
            #pragma unroll
            for (int j = 0; j < 4; j++) { s[i][j] = expf(s[i][j] - mnew); rs += s[i][j]; }
            rs += __shfl_xor_sync(0xffffffffu, rs, 1);
            rs += __shfl_xor_sync(0xffffffffu, rs, 2);
            rs += __shfl_xor_sync(0xffffffffu, rs, 4);
            rs += __shfl_xor_sync(0xffffffffu, rs, 8);
            l_i[i] = l_i[i] * corr + rs;
            m_i[i] = mnew;
            #pragma unroll
            for (int j = 0; j < 4; j++) acc[i][j] *= corr;
            *(float4*)(Ps + (tr * 4 + i) * 64 + tc * 4) = *(float4*)s[i];
        }
        __syncthreads();

        // O += P @ V
        #pragma unroll
        for (int k0 = 0; k0 < 64; k0 += 4) {
            __align__(16) float p[4][4];
            #pragma unroll
            for (int i = 0; i < 4; i++)
                *(float4*)p[i] = *(const float4*)(Ps + (tr * 4 + i) * 64 + k0);
            #pragma unroll
            for (int kk = 0; kk < 4; kk++) {
                float4 v4 = *(const float4*)(Vs + (k0 + kk) * 64 + tc * 4);
                #pragma unroll
                for (int i = 0; i < 4; i++) {
                    acc[i][0] = fmaf(p[i][kk], v4.x, acc[i][0]);
                    acc[i][1] = fmaf(p[i][kk], v4.y, acc[i][1]);
                    acc[i][2] = fmaf(p[i][kk], v4.z, acc[i][2]);
                    acc[i][3] = fmaf(p[i][kk], v4.w, acc[i][3]);
                }
            }
        }
    }

    // Epilogue: normalize and write [B,S,H,D] -> flat [B*S, 1024]
    float* Og = g_attn + (rowbase + q0) * EMB + h * HD;
    #pragma unroll
    for (int i = 0; i < 4; i++) {
        float inv = 1.f / l_i[i];
        *(float4*)(Og + (size_t)(tr * 4 + i) * EMB + tc * 4) =
            make_float4(acc[i][0] * inv, acc[i][1] * inv, acc[i][2] * inv, acc[i][3] * inv);
    }
}

// ---------------------------------------------------------------------------
extern "C" void kernel_launch(void* const* d_in, const int* in_sizes, int n_in,
                              void* d_out, int out_size) {
    const float* hidden = (const float*)d_in[0];   // [4096, 1024]
    const float* W_qkv  = (const float*)d_in[1];   // [1024, 3072]
    const float* W_out  = (const float*)d_in[2];   // [1024, 1024]
    const float* rel    = (const float*)d_in[3];   // [32, 16]
    float* out = (float*)d_out;                    // [4096, 1024]

    float *qkv_p, *attn_p;
    cudaGetSymbolAddress((void**)&qkv_p,  g_qkv);
    cudaGetSymbolAddress((void**)&attn_p, g_attn);
    cudaFuncSetAttribute(attn_kernel, cudaFuncAttributeMaxDynamicSharedMemorySize, ATTN_SMEM);

    bias_kernel<<<(NBIAS + 255) / 256, 256>>>(rel);
    sgemm_kernel<<<dim3(E3 / 128, NROWS / 128), 256>>>(hidden, W_qkv, qkv_p, NROWS, E3, EMB);
    attn_kernel<<<dim3(SEQ / 64, BATCH * NH), 256, ATTN_SMEM>>>();
    sgemm_kernel<<<dim3(EMB / 128, NROWS / 128), 256>>>(attn_p, W_out, out, NROWS, EMB, EMB);
}

// round 3
// speedup vs baseline: 1.2247x; 1.2247x over previous
#include <cuda_runtime.h>
#include <cuda_bf16.h>
#include <math.h>
#include <cstdint>

#define SEQ   2048
#define BATCH 2
#define NH    16
#define HD    64
#define EMB   1024
#define E3    3072
#define NROWS (BATCH*SEQ)          // 4096
#define NBIAS (2*SEQ-1)            // 4095

// ---------------- scratch (__device__ globals; no allocs allowed) ----------
__device__ float g_qkv[(size_t)NROWS * E3];   // 48 MB
__device__ float g_attn[(size_t)NROWS * EMB]; // 16 MB
__device__ float g_bias[NH * NBIAS];

// ---------------- mma.sync helpers (base-target ISA, no tcgen05) -----------
__device__ __forceinline__ uint32_t smem_u32(const void* p) {
    uint32_t a;
    asm("{ .reg .u64 t; cvta.to.shared.u64 t, %1; cvt.u32.u64 %0, t; }" : "=r"(a) : "l"(p));
    return a;
}
#define LDSM_X4(r, a) \
    asm volatile("ldmatrix.sync.aligned.m8n8.x4.shared.b16 {%0,%1,%2,%3}, [%4];" \
        : "=r"((r)[0]), "=r"((r)[1]), "=r"((r)[2]), "=r"((r)[3]) : "r"(a))
#define LDSM_X4T(r, a) \
    asm volatile("ldmatrix.sync.aligned.m8n8.x4.trans.shared.b16 {%0,%1,%2,%3}, [%4];" \
        : "=r"((r)[0]), "=r"((r)[1]), "=r"((r)[2]), "=r"((r)[3]) : "r"(a))
#define MMA16816(d, a, b0, b1) \
    asm volatile("mma.sync.aligned.m16n8k16.row.col.f32.bf16.bf16.f32 " \
        "{%0,%1,%2,%3}, {%4,%5,%6,%7}, {%8,%9}, {%0,%1,%2,%3};" \
        : "+f"((d)[0]), "+f"((d)[1]), "+f"((d)[2]), "+f"((d)[3]) \
        : "r"((a)[0]), "r"((a)[1]), "r"((a)[2]), "r"((a)[3]), "r"(b0), "r"(b1))

__device__ __forceinline__ void cvt_split2(float x, float y, uint32_t& h, uint32_t& l) {
    __nv_bfloat16 hx = __float2bfloat16(x);
    __nv_bfloat16 hy = __float2bfloat16(y);
    __nv_bfloat16 lx = __float2bfloat16(x - __bfloat162float(hx));
    __nv_bfloat16 ly = __float2bfloat16(y - __bfloat162float(hy));
    h = (uint32_t)__bfloat16_as_ushort(hx) | ((uint32_t)__bfloat16_as_ushort(hy) << 16);
    l = (uint32_t)__bfloat16_as_ushort(lx) | ((uint32_t)__bfloat16_as_ushort(ly) << 16);
}

// ---------------------------------------------------------------------------
// Bias table
// ---------------------------------------------------------------------------
__global__ void bias_kernel(const float* __restrict__ rel_emb) {
    int i = blockIdx.x * blockDim.x + threadIdx.x;
    if (i >= NBIAS) return;
    int d  = i - (SEQ - 1);
    int rb = (d > 0) ? 16 : 0;
    int ad = d < 0 ? -d : d;
    int bucket;
    if (ad < 8) bucket = ad;
    else {
        float v  = logf((float)ad * 0.125f) / 2.7725887f;
        int   lg = 8 + (int)(v * 8.0f);
        bucket = lg < 15 ? lg : 15;
    }
    int idx = rb + bucket;
    #pragma unroll
    for (int h = 0; h < NH; h++)
        g_bias[h * NBIAS + i] = rel_emb[idx * NH + h];
}

// ---------------------------------------------------------------------------
// HMMA GEMM, split-bf16 (3 terms): C[M,N] = A[M,K] @ B[K,N], fp32 in/out.
// 128x128 tile, BK=32, 8 warps (4x2), warp tile 32x64.
// A smem [128][40] bf16 (hi+lo), B smem [32][136] bf16 (hi+lo).
// ---------------------------------------------------------------------------
#define A_STRIDE 40
#define B_STRIDE 136
#define SM_AH 0
#define SM_AL (SM_AH + 128*A_STRIDE*2)        // 10240
#define SM_BH (SM_AL + 128*A_STRIDE*2)        // 20480
#define SM_BL (SM_BH + 32*B_STRIDE*2)         // 29184
#define GEMM_SMEM (SM_BL + 32*B_STRIDE*2)     // 37888

__global__ __launch_bounds__(256) void mma_gemm_kernel(
    const float* __restrict__ A, const float* __restrict__ B,
    float* __restrict__ C, int K, int N)
{
    __shared__ __align__(16) uint8_t smem[GEMM_SMEM];
    const uint32_t sb = smem_u32(smem);
    const int tid = threadIdx.x, wid = tid >> 5, lane = tid & 31;
    const int wm = wid & 3, wn = wid >> 2;
    const size_t m0 = (size_t)blockIdx.y * 128, n0 = (size_t)blockIdx.x * 128;

    float acc[2][8][4];
    #pragma unroll
    for (int i = 0; i < 2; i++)
        #pragma unroll
        for (int j = 0; j < 8; j++)
            #pragma unroll
            for (int r = 0; r < 4; r++) acc[i][j][r] = 0.f;

    // ldmatrix base addresses (per thread)
    // A: row = wm*32 + i*16 + (lane&15), chunk = (lane>>4)*16B, +ks*32B
    const uint32_t a_base = sb + (wm * 32 + (lane & 15)) * (A_STRIDE * 2) + (lane >> 4) * 16;
    // B: row = ks*16 + (lane&15), col byte = nh*64 + j16*32 + (lane>>4)*16
    const uint32_t b_base = sb + SM_BH + (lane & 15) * (B_STRIDE * 2) + wn * 128 + (lane >> 4) * 16;

    for (int k0 = 0; k0 < K; k0 += 32) {
        __syncthreads();
        // ---- stage A tile 128x32 (split hi/lo) ----
        #pragma unroll
        for (int it = 0; it < 4; it++) {
            int i4 = tid + it * 256;          // 0..1023
            int r = i4 >> 3, c4 = (i4 & 7) << 2;
            float4 v = *(const float4*)(A + (m0 + r) * K + k0 + c4);
            uint32_t h01, l01, h23, l23;
            cvt_split2(v.x, v.y, h01, l01);
            cvt_split2(v.z, v.w, h23, l23);
            int off = r * (A_STRIDE * 2) + c4 * 2;
            *(uint2*)(smem + SM_AH + off) = make_uint2(h01, h23);
            *(uint2*)(smem + SM_AL + off) = make_uint2(l01, l23);
        }
        // ---- stage B tile 32x128 (split hi/lo) ----
        #pragma unroll
        for (int it = 0; it < 4; it++) {
            int i4 = tid + it * 256;
            int r = i4 >> 5, c4 = (i4 & 31) << 2;
            float4 v = *(const float4*)(B + (size_t)(k0 + r) * N + n0 + c4);
            uint32_t h01, l01, h23, l23;
            cvt_split2(v.x, v.y, h01, l01);
            cvt_split2(v.z, v.w, h23, l23);
            int off = r * (B_STRIDE * 2) + c4 * 2;
            *(uint2*)(smem + SM_BH + off) = make_uint2(h01, h23);
            *(uint2*)(smem + SM_BL + off) = make_uint2(l01, l23);
        }
        __syncthreads();

        #pragma unroll
        for (int ks = 0; ks < 2; ks++) {
            uint32_t ah[2][4], al[2][4];
            #pragma unroll
            for (int i = 0; i < 2; i++) {
                uint32_t aa = a_base + i * 16 * (A_STRIDE * 2) + ks * 32;
                LDSM_X4(ah[i], SM_AH + aa);
                LDSM_X4(al[i], SM_AL + aa);
            }
            #pragma unroll
            for (int nh = 0; nh < 2; nh++) {
                uint32_t bh[2][4], bl[2][4];
                #pragma unroll
                for (int j16 = 0; j16 < 2; j16++) {
                    uint32_t ba = b_base + ks * 16 * (B_STRIDE * 2) + nh * 64 + j16 * 32;
                    LDSM_X4T(bh[j16], ba);
                    LDSM_X4T(bl[j16], ba + (SM_BL - SM_BH));
                }
                #pragma unroll
                for (int j16 = 0; j16 < 2; j16++) {
                    int nf = nh * 4 + j16 * 2;
                    #pragma unroll
                    for (int i = 0; i < 2; i++) {
                        MMA16816(acc[i][nf],     ah[i], bh[j16][0], bh[j16][1]);
                        MMA16816(acc[i][nf + 1], ah[i], bh[j16][2], bh[j16][3]);
                        MMA16816(acc[i][nf],     ah[i], bl[j16][0], bl[j16][1]);
                        MMA16816(acc[i][nf + 1], ah[i], bl[j16][2], bl[j16][3]);
                        MMA16816(acc[i][nf],     al[i], bh[j16][0], bh[j16][1]);
                        MMA16816(acc[i][nf + 1], al[i], bh[j16][2], bh[j16][3]);
                    }
                }
            }
        }
    }

    // ---- epilogue ----
    const int row_in = lane >> 2, col_in = (lane & 3) * 2;
    #pragma unroll
    for (int i = 0; i < 2; i++) {
        #pragma unroll
        for (int nf = 0; nf < 8; nf++) {
            float* p = C + (m0 + wm * 32 + i * 16 + row_in) * N + n0 + wn * 64 + nf * 8 + col_in;
            *(float2*)p             = make_float2(acc[i][nf][0], acc[i][nf][1]);
            *(float2*)(p + 8 * (size_t)N) = make_float2(acc[i][nf][2], acc[i][nf][3]);
        }
    }
}

// ---------------------------------------------------------------------------
// Flash attention (unchanged, known-good): 64 q-rows per block, scalar fp32.
// ---------------------------------------------------------------------------
#define ATTN_SMEM ((64*64*3 + 64*65) * 4)

__global__ __launch_bounds__(256) void attn_kernel() {
    extern __shared__ float sm[];
    float* Qs = sm;
    float* Kt = sm + 4096;
    float* Vs = Kt + 64 * 65;
    float* Ps = Vs + 4096;

    const int tid = threadIdx.x;
    const int tr = tid >> 4, tc = tid & 15;
    const int q0 = blockIdx.x * 64;
    const int b = blockIdx.y >> 4, h = blockIdx.y & 15;
    const size_t rowbase = (size_t)b * SEQ;

    const float* Qg = g_qkv + (rowbase + q0) * E3 + h * HD;
    #pragma unroll
    for (int it = 0; it < 4; it++) {
        int i4 = tid + it * 256;
        int r = i4 >> 4, c4 = (i4 & 15) << 2;
        *(float4*)(Qs + r * 64 + c4) = *(const float4*)(Qg + (size_t)r * E3 + c4);
    }

    float m_i[4], l_i[4], acc[4][4];
    #pragma unroll
    for (int i = 0; i < 4; i++) {
        m_i[i] = -INFINITY; l_i[i] = 0.f;
        #pragma unroll
        for (int j = 0; j < 4; j++) acc[i][j] = 0.f;
    }
    const float* bias_h = g_bias + h * NBIAS;

    for (int kt = 0; kt < SEQ / 64; kt++) {
        __syncthreads();
        const float* Kg = g_qkv + (rowbase + kt * 64) * E3 + EMB + h * HD;
        #pragma unroll
        for (int it = 0; it < 4; it++) {
            int i4 = tid + it * 256;
            int r = i4 >> 4, c4 = (i4 & 15) << 2;
            float4 kv = *(const float4*)(Kg + (size_t)r * E3 + c4);
            Kt[(c4 + 0) * 65 + r] = kv.x;
            Kt[(c4 + 1) * 65 + r] = kv.y;
            Kt[(c4 + 2) * 65 + r] = kv.z;
            Kt[(c4 + 3) * 65 + r] = kv.w;
            *(float4*)(Vs + r * 64 + c4) = *(const float4*)(Kg + EMB + (size_t)r * E3 + c4);
        }
        __syncthreads();

        __align__(16) float s[4][4];
        #pragma unroll
        for (int i = 0; i < 4; i++)
            #pragma unroll
            for (int j = 0; j < 4; j++) s[i][j] = 0.f;

        #pragma unroll
        for (int d0 = 0; d0 < 64; d0 += 4) {
            __align__(16) float q[4][4];
            #pragma unroll
            for (int i = 0; i < 4; i++)
                *(float4*)q[i] = *(const float4*)(Qs + (tr * 4 + i) * 64 + d0);
            #pragma unroll
            for (int dd = 0; dd < 4; dd++) {
                float kj[4];
                #pragma unroll
                for (int j = 0; j < 4; j++) kj[j] = Kt[(d0 + dd) * 65 + tc * 4 + j];
                #pragma unroll
                for (int i = 0; i < 4; i++)
                    #pragma unroll
                    for (int j = 0; j < 4; j++)
                        s[i][j] = fmaf(q[i][dd], kj[j], s[i][j]);
            }
        }

        int coloff = kt * 64 + tc * 4 - q0 - tr * 4 + (SEQ - 1);
        #pragma unroll
        for (int i = 0; i < 4; i++) {
            const float* bp = bias_h + coloff - i;
            float mx = -INFINITY;
            #pragma unroll
            for (int j = 0; j < 4; j++) { s[i][j] += bp[j]; mx = fmaxf(mx, s[i][j]); }
            mx = fmaxf(mx, __shfl_xor_sync(0xffffffffu, mx, 1));
            mx = fmaxf(mx, __shfl_xor_sync(0xffffffffu, mx, 2));
            mx = fmaxf(mx, __shfl_xor_sync(0xffffffffu, mx, 4));
            mx = fmaxf(mx, __shfl_xor_sync(0xffffffffu, mx, 8));
            float mnew = fmaxf(m_i[i], mx);
            float corr = expf(m_i[i] - mnew);
            float rs = 0.f;
            #pragma unroll
            for (int j = 0; j < 4; j++) { s[i][j] = expf(s[i][j] - mnew); rs += s[i][j]; }
            rs += __shfl_xor_sync(0xffffffffu, rs, 1);
            rs += __shfl_xor_sync(0xffffffffu, rs, 2);
            rs += __shfl_xor_sync(0xffffffffu, rs, 4);
            rs += __shfl_xor_sync(0xffffffffu, rs, 8);
            l_i[i] = l_i[i] * corr + rs;
            m_i[i] = mnew;
            #pragma unroll
            for (int j = 0; j < 4; j++) acc[i][j] *= corr;
            *(float4*)(Ps + (tr * 4 + i) * 64 + tc * 4) = *(float4*)s[i];
        }
        __syncthreads();

        #pragma unroll
        for (int k0 = 0; k0 < 64; k0 += 4) {
            __align__(16) float p[4][4];
            #pragma unroll
            for (int i = 0; i < 4; i++)
                *(float4*)p[i] = *(const float4*)(Ps + (tr * 4 + i) * 64 + k0);
            #pragma unroll
            for (int kk = 0; kk < 4; kk++) {
                float4 v4 = *(const float4*)(Vs + (k0 + kk) * 64 + tc * 4);
                #pragma unroll
                for (int i = 0; i < 4; i++) {
                    acc[i][0] = fmaf(p[i][kk], v4.x, acc[i][0]);
                    acc[i][1] = fmaf(p[i][kk], v4.y, acc[i][1]);
                    acc[i][2] = fmaf(p[i][kk], v4.z, acc[i][2]);
                    acc[i][3] = fmaf(p[i][kk], v4.w, acc[i][3]);
                }
            }
        }
    }

    float* Og = g_attn + (rowbase + q0) * EMB + h * HD;
    #pragma unroll
    for (int i = 0; i < 4; i++) {
        float inv = 1.f / l_i[i];
        *(float4*)(Og + (size_t)(tr * 4 + i) * EMB + tc * 4) =
            make_float4(acc[i][0] * inv, acc[i][1] * inv, acc[i][2] * inv, acc[i][3] * inv);
    }
}

// ---------------------------------------------------------------------------
extern "C" void kernel_launch(void* const* d_in, const int* in_sizes, int n_in,
                              void* d_out, int out_size) {
    const float* hidden = (const float*)d_in[0];   // [4096, 1024]
    const float* W_qkv  = (const float*)d_in[1];   // [1024, 3072]
    const float* W_out  = (const float*)d_in[2];   // [1024, 1024]
    const float* rel    = (const float*)d_in[3];   // [32, 16]
    float* out = (float*)d_out;                    // [4096, 1024]

    float *qkv_p, *attn_p;
    cudaGetSymbolAddress((void**)&qkv_p,  g_qkv);
    cudaGetSymbolAddress((void**)&attn_p, g_attn);
    cudaFuncSetAttribute(attn_kernel, cudaFuncAttributeMaxDynamicSharedMemorySize, ATTN_SMEM);

    bias_kernel<<<(NBIAS + 255) / 256, 256>>>(rel);

    // QKV projection: [4096,1024] @ [1024,3072]
    mma_gemm_kernel<<<dim3(E3 / 128, NROWS / 128), 256>>>(hidden, W_qkv, qkv_p, EMB, E3);

    // attention
    attn_kernel<<<dim3(SEQ / 64, BATCH * NH), 256, ATTN_SMEM>>>();

    // output projection: [4096,1024] @ [1024,1024]
    mma_gemm_kernel<<<dim3(EMB / 128, NROWS / 128), 256>>>(attn_p, W_out, out, EMB, EMB);
}

// round 4
// speedup vs baseline: 1.8530x; 1.5130x over previous
#include <cuda_runtime.h>
#include <cuda_bf16.h>
#include <math.h>
#include <cstdint>

#define SEQ   2048
#define BATCH 2
#define NH    16
#define HD    64
#define EMB   1024
#define E3    3072
#define NROWS (BATCH*SEQ)          // 4096
#define NBIAS (2*SEQ-1)            // 4095
#define L2E   1.4426950408889634f

// ---------------- scratch (__device__ globals; no allocs allowed) ----------
__device__ float g_qkv[(size_t)NROWS * E3];   // 48 MB
__device__ float g_attn[(size_t)NROWS * EMB]; // 16 MB
__device__ float g_bias[NH * NBIAS];

// ---------------- mma.sync helpers (base-target ISA) -----------------------
__device__ __forceinline__ uint32_t smem_u32(const void* p) {
    uint32_t a;
    asm("{ .reg .u64 t; cvta.to.shared.u64 t, %1; cvt.u32.u64 %0, t; }" : "=r"(a) : "l"(p));
    return a;
}
#define LDSM_X4(r, a) \
    asm volatile("ldmatrix.sync.aligned.m8n8.x4.shared.b16 {%0,%1,%2,%3}, [%4];" \
        : "=r"((r)[0]), "=r"((r)[1]), "=r"((r)[2]), "=r"((r)[3]) : "r"(a))
#define LDSM_X4T(r, a) \
    asm volatile("ldmatrix.sync.aligned.m8n8.x4.trans.shared.b16 {%0,%1,%2,%3}, [%4];" \
        : "=r"((r)[0]), "=r"((r)[1]), "=r"((r)[2]), "=r"((r)[3]) : "r"(a))
#define MMA16816(d, a, b0, b1) \
    asm volatile("mma.sync.aligned.m16n8k16.row.col.f32.bf16.bf16.f32 " \
        "{%0,%1,%2,%3}, {%4,%5,%6,%7}, {%8,%9}, {%0,%1,%2,%3};" \
        : "+f"((d)[0]), "+f"((d)[1]), "+f"((d)[2]), "+f"((d)[3]) \
        : "r"((a)[0]), "r"((a)[1]), "r"((a)[2]), "r"((a)[3]), "r"(b0), "r"(b1))

__device__ __forceinline__ void cvt_split2(float x, float y, uint32_t& h, uint32_t& l) {
    __nv_bfloat16 hx = __float2bfloat16(x);
    __nv_bfloat16 hy = __float2bfloat16(y);
    __nv_bfloat16 lx = __float2bfloat16(x - __bfloat162float(hx));
    __nv_bfloat16 ly = __float2bfloat16(y - __bfloat162float(hy));
    h = (uint32_t)__bfloat16_as_ushort(hx) | ((uint32_t)__bfloat16_as_ushort(hy) << 16);
    l = (uint32_t)__bfloat16_as_ushort(lx) | ((uint32_t)__bfloat16_as_ushort(ly) << 16);
}

// ---------------------------------------------------------------------------
// Bias table
// ---------------------------------------------------------------------------
__global__ void bias_kernel(const float* __restrict__ rel_emb) {
    int i = blockIdx.x * blockDim.x + threadIdx.x;
    if (i >= NBIAS) return;
    int d  = i - (SEQ - 1);
    int rb = (d > 0) ? 16 : 0;
    int ad = d < 0 ? -d : d;
    int bucket;
    if (ad < 8) bucket = ad;
    else {
        float v  = logf((float)ad * 0.125f) / 2.7725887f;
        int   lg = 8 + (int)(v * 8.0f);
        bucket = lg < 15 ? lg : 15;
    }
    int idx = rb + bucket;
    #pragma unroll
    for (int h = 0; h < NH; h++)
        g_bias[h * NBIAS + i] = rel_emb[idx * NH + h];
}

// ---------------------------------------------------------------------------
// HMMA GEMM (unchanged from R3): C = A[M,K] @ B[K,N], split-bf16 3 terms.
// ---------------------------------------------------------------------------
#define A_STRIDE 40
#define B_STRIDE 136
#define SM_AH 0
#define SM_AL (SM_AH + 128*A_STRIDE*2)
#define SM_BH (SM_AL + 128*A_STRIDE*2)
#define SM_BL (SM_BH + 32*B_STRIDE*2)
#define GEMM_SMEM (SM_BL + 32*B_STRIDE*2)

__global__ __launch_bounds__(256) void mma_gemm_kernel(
    const float* __restrict__ A, const float* __restrict__ B,
    float* __restrict__ C, int K, int N)
{
    __shared__ __align__(16) uint8_t smem[GEMM_SMEM];
    const uint32_t sb = smem_u32(smem);
    const int tid = threadIdx.x, wid = tid >> 5, lane = tid & 31;
    const int wm = wid & 3, wn = wid >> 2;
    const size_t m0 = (size_t)blockIdx.y * 128, n0 = (size_t)blockIdx.x * 128;

    float acc[2][8][4];
    #pragma unroll
    for (int i = 0; i < 2; i++)
        #pragma unroll
        for (int j = 0; j < 8; j++)
            #pragma unroll
            for (int r = 0; r < 4; r++) acc[i][j][r] = 0.f;

    const uint32_t a_base = sb + (wm * 32 + (lane & 15)) * (A_STRIDE * 2) + (lane >> 4) * 16;
    const uint32_t b_base = sb + SM_BH + (lane & 15) * (B_STRIDE * 2) + wn * 128 + (lane >> 4) * 16;

    for (int k0 = 0; k0 < K; k0 += 32) {
        __syncthreads();
        #pragma unroll
        for (int it = 0; it < 4; it++) {
            int i4 = tid + it * 256;
            int r = i4 >> 3, c4 = (i4 & 7) << 2;
            float4 v = *(const float4*)(A + (m0 + r) * K + k0 + c4);
            uint32_t h01, l01, h23, l23;
            cvt_split2(v.x, v.y, h01, l01);
            cvt_split2(v.z, v.w, h23, l23);
            int off = r * (A_STRIDE * 2) + c4 * 2;
            *(uint2*)(smem + SM_AH + off) = make_uint2(h01, h23);
            *(uint2*)(smem + SM_AL + off) = make_uint2(l01, l23);
        }
        #pragma unroll
        for (int it = 0; it < 4; it++) {
            int i4 = tid + it * 256;
            int r = i4 >> 5, c4 = (i4 & 31) << 2;
            float4 v = *(const float4*)(B + (size_t)(k0 + r) * N + n0 + c4);
            uint32_t h01, l01, h23, l23;
            cvt_split2(v.x, v.y, h01, l01);
            cvt_split2(v.z, v.w, h23, l23);
            int off = r * (B_STRIDE * 2) + c4 * 2;
            *(uint2*)(smem + SM_BH + off) = make_uint2(h01, h23);
            *(uint2*)(smem + SM_BL + off) = make_uint2(l01, l23);
        }
        __syncthreads();

        #pragma unroll
        for (int ks = 0; ks < 2; ks++) {
            uint32_t ah[2][4], al[2][4];
            #pragma unroll
            for (int i = 0; i < 2; i++) {
                uint32_t aa = a_base + i * 16 * (A_STRIDE * 2) + ks * 32;
                LDSM_X4(ah[i], SM_AH + aa);
                LDSM_X4(al[i], SM_AL + aa);
            }
            #pragma unroll
            for (int nh = 0; nh < 2; nh++) {
                uint32_t bh[2][4], bl[2][4];
                #pragma unroll
                for (int j16 = 0; j16 < 2; j16++) {
                    uint32_t ba = b_base + ks * 16 * (B_STRIDE * 2) + nh * 64 + j16 * 32;
                    LDSM_X4T(bh[j16], ba);
                    LDSM_X4T(bl[j16], ba + (SM_BL - SM_BH));
                }
                #pragma unroll
                for (int j16 = 0; j16 < 2; j16++) {
                    int nf = nh * 4 + j16 * 2;
                    #pragma unroll
                    for (int i = 0; i < 2; i++) {
                        MMA16816(acc[i][nf],     ah[i], bh[j16][0], bh[j16][1]);
                        MMA16816(acc[i][nf + 1], ah[i], bh[j16][2], bh[j16][3]);
                        MMA16816(acc[i][nf],     ah[i], bl[j16][0], bl[j16][1]);
                        MMA16816(acc[i][nf + 1], ah[i], bl[j16][2], bl[j16][3]);
                        MMA16816(acc[i][nf],     al[i], bh[j16][0], bh[j16][1]);
                        MMA16816(acc[i][nf + 1], al[i], bh[j16][2], bh[j16][3]);
                    }
                }
            }
        }
    }

    const int row_in = lane >> 2, col_in = (lane & 3) * 2;
    #pragma unroll
    for (int i = 0; i < 2; i++) {
        #pragma unroll
        for (int nf = 0; nf < 8; nf++) {
            float* p = C + (m0 + wm * 32 + i * 16 + row_in) * N + n0 + wn * 64 + nf * 8 + col_in;
            *(float2*)p                   = make_float2(acc[i][nf][0], acc[i][nf][1]);
            *(float2*)(p + 8 * (size_t)N) = make_float2(acc[i][nf][2], acc[i][nf][3]);
        }
    }
}

// ---------------------------------------------------------------------------
// HMMA flash attention: block = 64 q-rows of one (b,h), 4 warps.
// Warp w: q-rows [w*16, w*16+16). Split-bf16 3 terms for both QK^T and PV.
// Smem rows: 72 halves (144B) stride; bias band 127 floats per k-tile.
// ---------------------------------------------------------------------------
#define AT_STRIDE 144                          // bytes per 64-wide bf16 row
#define AQ_H 0
#define AQ_L (AQ_H + 64*AT_STRIDE)
#define AK_H (AQ_L + 64*AT_STRIDE)
#define AK_L (AK_H + 64*AT_STRIDE)
#define AV_H (AK_L + 64*AT_STRIDE)
#define AV_L (AV_H + 64*AT_STRIDE)
#define AB_OFF (AV_L + 64*AT_STRIDE)           // 55296
#define ATTN_SMEM (AB_OFF + 128*4)             // 55808

__global__ __launch_bounds__(128) void attn_mma_kernel() {
    extern __shared__ __align__(16) uint8_t sm8[];
    const uint32_t sb = smem_u32(sm8);
    float* sbias = (float*)(sm8 + AB_OFF);
    const int tid = threadIdx.x, wid = tid >> 5, lane = tid & 31;
    const int q0 = blockIdx.x * 64;
    const int b = blockIdx.y >> 4, h = blockIdx.y & 15;
    const size_t rowbase = (size_t)b * SEQ;
    const float* bias_h = g_bias + h * NBIAS;

    // ---- stage Q (split bf16) ----
    const float* Qg = g_qkv + (rowbase + q0) * E3 + h * HD;
    #pragma unroll
    for (int it = 0; it < 8; it++) {
        int i4 = tid + it * 128;
        int r = i4 >> 4, c4 = (i4 & 15) << 2;
        float4 v = *(const float4*)(Qg + (size_t)r * E3 + c4);
        uint32_t h01, l01, h23, l23;
        cvt_split2(v.x, v.y, h01, l01);
        cvt_split2(v.z, v.w, h23, l23);
        int off = r * AT_STRIDE + c4 * 2;
        *(uint2*)(sm8 + AQ_H + off) = make_uint2(h01, h23);
        *(uint2*)(sm8 + AQ_L + off) = make_uint2(l01, l23);
    }
    __syncthreads();

    // ---- hoist Q fragments (fixed for whole block) ----
    uint32_t qh[4][4], ql[4][4];
    {
        uint32_t qa = sb + (wid * 16 + (lane & 15)) * AT_STRIDE + (lane >> 4) * 16;
        #pragma unroll
        for (int ks = 0; ks < 4; ks++) {
            LDSM_X4(qh[ks], qa + AQ_H + ks * 32);
            LDSM_X4(ql[ks], qa + AQ_L + ks * 32);
        }
    }

    float m0 = -INFINITY, m1 = -INFINITY, l0 = 0.f, l1 = 0.f;
    float o[8][4];
    #pragma unroll
    for (int j = 0; j < 8; j++)
        #pragma unroll
        for (int r = 0; r < 4; r++) o[j][r] = 0.f;

    const uint32_t kfb = sb + AK_H + (lane & 15) * AT_STRIDE + (lane >> 4) * 16;
    const uint32_t vfb = sb + AV_H + (lane & 15) * AT_STRIDE + (lane >> 4) * 16;
    const int ccol = (lane & 3) * 2;
    const int r0 = wid * 16 + (lane >> 2);     // local q row (0..63)
    const int r1 = r0 + 8;

    for (int kt = 0; kt < SEQ / 64; kt++) {
        __syncthreads();
        // ---- stage K,V tile (split bf16) ----
        const float* Kg = g_qkv + (rowbase + kt * 64) * E3 + EMB + h * HD;
        #pragma unroll
        for (int it = 0; it < 8; it++) {
            int i4 = tid + it * 128;
            int r = i4 >> 4, c4 = (i4 & 15) << 2;
            int off = r * AT_STRIDE + c4 * 2;
            float4 kv = *(const float4*)(Kg + (size_t)r * E3 + c4);
            uint32_t h01, l01, h23, l23;
            cvt_split2(kv.x, kv.y, h01, l01);
            cvt_split2(kv.z, kv.w, h23, l23);
            *(uint2*)(sm8 + AK_H + off) = make_uint2(h01, h23);
            *(uint2*)(sm8 + AK_L + off) = make_uint2(l01, l23);
            float4 vv = *(const float4*)(Kg + EMB + (size_t)r * E3 + c4);
            cvt_split2(vv.x, vv.y, h01, l01);
            cvt_split2(vv.z, vv.w, h23, l23);
            *(uint2*)(sm8 + AV_H + off) = make_uint2(h01, h23);
            *(uint2*)(sm8 + AV_L + off) = make_uint2(l01, l23);
        }
        if (tid < 127) sbias[tid] = bias_h[kt * 64 - q0 + 1984 + tid];
        __syncthreads();

        // ---- S = Q @ K^T (3-term split) ----
        float s[8][4];
        #pragma unroll
        for (int j = 0; j < 8; j++)
            #pragma unroll
            for (int r = 0; r < 4; r++) s[j][r] = 0.f;

        #pragma unroll
        for (int ks = 0; ks < 4; ks++) {
            #pragma unroll
            for (int nb = 0; nb < 4; nb++) {
                uint32_t kh[4], kl[4];
                uint32_t ka = kfb + nb * 16 * AT_STRIDE + ks * 32;
                LDSM_X4(kh, ka);
                LDSM_X4(kl, ka + (AK_L - AK_H));
                MMA16816(s[2*nb],   qh[ks], kh[0], kh[2]);
                MMA16816(s[2*nb+1], qh[ks], kh[1], kh[3]);
                MMA16816(s[2*nb],   qh[ks], kl[0], kl[2]);
                MMA16816(s[2*nb+1], qh[ks], kl[1], kl[3]);
                MMA16816(s[2*nb],   ql[ks], kh[0], kh[2]);
                MMA16816(s[2*nb+1], ql[ks], kh[1], kh[3]);
            }
        }

        // ---- bias + online softmax ----
        float mx0 = -INFINITY, mx1 = -INFINITY;
        #pragma unroll
        for (int j = 0; j < 8; j++) {
            int c = j * 8 + ccol;
            s[j][0] += sbias[c - r0 + 63];
            s[j][1] += sbias[c + 1 - r0 + 63];
            s[j][2] += sbias[c - r1 + 63];
            s[j][3] += sbias[c + 1 - r1 + 63];
            mx0 = fmaxf(mx0, fmaxf(s[j][0], s[j][1]));
            mx1 = fmaxf(mx1, fmaxf(s[j][2], s[j][3]));
        }
        mx0 = fmaxf(mx0, __shfl_xor_sync(0xffffffffu, mx0, 1));
        mx0 = fmaxf(mx0, __shfl_xor_sync(0xffffffffu, mx0, 2));
        mx1 = fmaxf(mx1, __shfl_xor_sync(0xffffffffu, mx1, 1));
        mx1 = fmaxf(mx1, __shfl_xor_sync(0xffffffffu, mx1, 2));
        float m0n = fmaxf(m0, mx0), m1n = fmaxf(m1, mx1);
        float c0 = exp2f((m0 - m0n) * L2E), c1 = exp2f((m1 - m1n) * L2E);
        float rs0 = 0.f, rs1 = 0.f;
        #pragma unroll
        for (int j = 0; j < 8; j++) {
            s[j][0] = exp2f((s[j][0] - m0n) * L2E);
            s[j][1] = exp2f((s[j][1] - m0n) * L2E);
            s[j][2] = exp2f((s[j][2] - m1n) * L2E);
            s[j][3] = exp2f((s[j][3] - m1n) * L2E);
            rs0 += s[j][0] + s[j][1];
            rs1 += s[j][2] + s[j][3];
        }
        rs0 += __shfl_xor_sync(0xffffffffu, rs0, 1);
        rs0 += __shfl_xor_sync(0xffffffffu, rs0, 2);
        rs1 += __shfl_xor_sync(0xffffffffu, rs1, 1);
        rs1 += __shfl_xor_sync(0xffffffffu, rs1, 2);
        l0 = l0 * c0 + rs0; l1 = l1 * c1 + rs1;
        m0 = m0n; m1 = m1n;
        #pragma unroll
        for (int j = 0; j < 8; j++) {
            o[j][0] *= c0; o[j][1] *= c0; o[j][2] *= c1; o[j][3] *= c1;
        }

        // ---- O += P @ V (3-term split; P packed straight from regs) ----
        #pragma unroll
        for (int t = 0; t < 4; t++) {
            uint32_t ah[4], al[4];
            cvt_split2(s[2*t][0],   s[2*t][1],   ah[0], al[0]);
            cvt_split2(s[2*t][2],   s[2*t][3],   ah[1], al[1]);
            cvt_split2(s[2*t+1][0], s[2*t+1][1], ah[2], al[2]);
            cvt_split2(s[2*t+1][2], s[2*t+1][3], ah[3], al[3]);
            #pragma unroll
            for (int g = 0; g < 4; g++) {
                uint32_t vh[4], vl[4];
                uint32_t va = vfb + t * 16 * AT_STRIDE + g * 32;
                LDSM_X4T(vh, va);
                LDSM_X4T(vl, va + (AV_L - AV_H));
                MMA16816(o[2*g],   ah, vh[0], vh[1]);
                MMA16816(o[2*g+1], ah, vh[2], vh[3]);
                MMA16816(o[2*g],   ah, vl[0], vl[1]);
                MMA16816(o[2*g+1], ah, vl[2], vl[3]);
                MMA16816(o[2*g],   al, vh[0], vh[1]);
                MMA16816(o[2*g+1], al, vh[2], vh[3]);
            }
        }
    }

    // ---- epilogue ----
    float inv0 = 1.f / l0, inv1 = 1.f / l1;
    float* Og = g_attn + (rowbase + q0 + r0) * EMB + h * HD + ccol;
    #pragma unroll
    for (int j = 0; j < 8; j++) {
        *(float2*)(Og + j * 8)             = make_float2(o[j][0] * inv0, o[j][1] * inv0);
        *(float2*)(Og + 8 * EMB + j * 8)   = make_float2(o[j][2] * inv1, o[j][3] * inv1);
    }
}

// ---------------------------------------------------------------------------
extern "C" void kernel_launch(void* const* d_in, const int* in_sizes, int n_in,
                              void* d_out, int out_size) {
    const float* hidden = (const float*)d_in[0];   // [4096, 1024]
    const float* W_qkv  = (const float*)d_in[1];   // [1024, 3072]
    const float* W_out  = (const float*)d_in[2];   // [1024, 1024]
    const float* rel    = (const float*)d_in[3];   // [32, 16]
    float* out = (float*)d_out;                    // [4096, 1024]

    float *qkv_p, *attn_p;
    cudaGetSymbolAddress((void**)&qkv_p,  g_qkv);
    cudaGetSymbolAddress((void**)&attn_p, g_attn);
    cudaFuncSetAttribute(attn_mma_kernel, cudaFuncAttributeMaxDynamicSharedMemorySize, ATTN_SMEM);

    bias_kernel<<<(NBIAS + 255) / 256, 256>>>(rel);

    // QKV projection: [4096,1024] @ [1024,3072]
    mma_gemm_kernel<<<dim3(E3 / 128, NROWS / 128), 256>>>(hidden, W_qkv, qkv_p, EMB, E3);

    // attention (HMMA flash)
    attn_mma_kernel<<<dim3(SEQ / 64, BATCH * NH), 128, ATTN_SMEM>>>();

    // output projection: [4096,1024] @ [1024,1024]
    mma_gemm_kernel<<<dim3(EMB / 128, NROWS / 128), 256>>>(attn_p, W_out, out, EMB, EMB);
}

// round 5
// speedup vs baseline: 2.4555x; 1.3252x over previous
#include <cuda_runtime.h>
#include <cuda_bf16.h>
#include <math.h>
#include <cstdint>

#define SEQ   2048
#define BATCH 2
#define NH    16
#define HD    64
#define EMB   1024
#define E3    3072
#define NROWS (BATCH*SEQ)          // 4096
#define NBIAS (2*SEQ-1)            // 4095
#define NBP   4096                 // padded bias row stride
#define L2E   1.4426950408889634f

// ---------------- scratch (__device__ globals; no allocs allowed) ----------
__device__ __nv_bfloat16 g_ah[(size_t)NROWS * EMB];    // hidden split
__device__ __nv_bfloat16 g_al[(size_t)NROWS * EMB];
__device__ __nv_bfloat16 g_wqh[(size_t)EMB * E3];      // W_qkv split (row-major)
__device__ __nv_bfloat16 g_wql[(size_t)EMB * E3];
__device__ __nv_bfloat16 g_woh[(size_t)EMB * EMB];     // W_out split
__device__ __nv_bfloat16 g_wol[(size_t)EMB * EMB];
__device__ __nv_bfloat16 g_qkv_h[(size_t)NROWS * E3];  // QKV result split
__device__ __nv_bfloat16 g_qkv_l[(size_t)NROWS * E3];
__device__ __nv_bfloat16 g_attn_h[(size_t)NROWS * EMB];
__device__ __nv_bfloat16 g_attn_l[(size_t)NROWS * EMB];
__device__ float g_bias[NH * NBP];

// ---------------- PTX helpers ----------------------------------------------
__device__ __forceinline__ uint32_t smem_u32(const void* p) {
    uint32_t a;
    asm("{ .reg .u64 t; cvta.to.shared.u64 t, %1; cvt.u32.u64 %0, t; }" : "=r"(a) : "l"(p));
    return a;
}
#define LDSM_X4(r, a) \
    asm volatile("ldmatrix.sync.aligned.m8n8.x4.shared.b16 {%0,%1,%2,%3}, [%4];" \
        : "=r"((r)[0]), "=r"((r)[1]), "=r"((r)[2]), "=r"((r)[3]) : "r"(a))
#define LDSM_X4T(r, a) \
    asm volatile("ldmatrix.sync.aligned.m8n8.x4.trans.shared.b16 {%0,%1,%2,%3}, [%4];" \
        : "=r"((r)[0]), "=r"((r)[1]), "=r"((r)[2]), "=r"((r)[3]) : "r"(a))
#define MMA16816(d, a, b0, b1) \
    asm volatile("mma.sync.aligned.m16n8k16.row.col.f32.bf16.bf16.f32 " \
        "{%0,%1,%2,%3}, {%4,%5,%6,%7}, {%8,%9}, {%0,%1,%2,%3};" \
        : "+f"((d)[0]), "+f"((d)[1]), "+f"((d)[2]), "+f"((d)[3]) \
        : "r"((a)[0]), "r"((a)[1]), "r"((a)[2]), "r"((a)[3]), "r"(b0), "r"(b1))
#define CP16(d, s) asm volatile("cp.async.cg.shared.global [%0], [%1], 16;" :: "r"(d), "l"(s))
#define CP_COMMIT() asm volatile("cp.async.commit_group;" ::: "memory")
#define CP_WAIT0()  asm volatile("cp.async.wait_group 0;" ::: "memory")

__device__ __forceinline__ void cvt_split2(float x, float y, uint32_t& h, uint32_t& l) {
    __nv_bfloat16 hx = __float2bfloat16(x);
    __nv_bfloat16 hy = __float2bfloat16(y);
    __nv_bfloat16 lx = __float2bfloat16(x - __bfloat162float(hx));
    __nv_bfloat16 ly = __float2bfloat16(y - __bfloat162float(hy));
    h = (uint32_t)__bfloat16_as_ushort(hx) | ((uint32_t)__bfloat16_as_ushort(hy) << 16);
    l = (uint32_t)__bfloat16_as_ushort(lx) | ((uint32_t)__bfloat16_as_ushort(ly) << 16);
}

// ---------------------------------------------------------------------------
// Bias table (padded row stride NBP)
// ---------------------------------------------------------------------------
__global__ void bias_kernel(const float* __restrict__ rel_emb) {
    int i = blockIdx.x * blockDim.x + threadIdx.x;
    if (i >= NBIAS) return;
    int d  = i - (SEQ - 1);
    int rb = (d > 0) ? 16 : 0;
    int ad = d < 0 ? -d : d;
    int bucket;
    if (ad < 8) bucket = ad;
    else {
        float v  = logf((float)ad * 0.125f) / 2.7725887f;
        int   lg = 8 + (int)(v * 8.0f);
        bucket = lg < 15 ? lg : 15;
    }
    int idx = rb + bucket;
    #pragma unroll
    for (int h = 0; h < NH; h++)
        g_bias[h * NBP + i] = rel_emb[idx * NH + h];
}

// ---------------------------------------------------------------------------
// fp32 -> (hi,lo) bf16 split, elementwise x4
// ---------------------------------------------------------------------------
__global__ void split_kernel(const float* __restrict__ in,
                             __nv_bfloat16* __restrict__ hi,
                             __nv_bfloat16* __restrict__ lo, int n4) {
    int i = blockIdx.x * blockDim.x + threadIdx.x;
    if (i >= n4) return;
    float4 a = ((const float4*)in)[i];
    uint32_t h01, l01, h23, l23;
    cvt_split2(a.x, a.y, h01, l01);
    cvt_split2(a.z, a.w, h23, l23);
    ((uint2*)hi)[i] = make_uint2(h01, h23);
    ((uint2*)lo)[i] = make_uint2(l01, l23);
}

// ---------------------------------------------------------------------------
// Pipelined bf16 GEMM: C = (Ah+Al)[M,K] @ (Bh+Bl)[K,N], 3-term HMMA.
// 128x128 tile, BK=32, 8 warps, cp.async double-buffered.
// Output: fp32 (Cf) or split bf16 (Ch/Cl).
// ---------------------------------------------------------------------------
#define SG_AH 0
#define SG_AL 10240
#define SG_BH 20480
#define SG_BL 29184
#define SG_SIZE 37888
#define GEMM_SMEM (2*SG_SIZE)   // 75776

__device__ __forceinline__ void gemm_issue(
    uint32_t base, const __nv_bfloat16* Ah, const __nv_bfloat16* Al,
    const __nv_bfloat16* Bh, const __nv_bfloat16* Bl,
    int k0, int K, int N, int tid)
{
    #pragma unroll
    for (int t = 0; t < 2; t++) {
        int i = tid + t * 256;
        int r = i >> 2, c = i & 3;                 // A: 128 rows x 4 chunks
        uint32_t off = r * 80 + c * 16;
        size_t so = (size_t)r * K + k0 + c * 8;
        CP16(base + SG_AH + off, Ah + so);
        CP16(base + SG_AL + off, Al + so);
    }
    #pragma unroll
    for (int t = 0; t < 2; t++) {
        int i = tid + t * 256;
        int r = i >> 4, c = i & 15;                // B: 32 rows x 16 chunks
        uint32_t off = r * 272 + c * 16;
        size_t so = (size_t)(k0 + r) * N + c * 8;
        CP16(base + SG_BH + off, Bh + so);
        CP16(base + SG_BL + off, Bl + so);
    }
}

__global__ __launch_bounds__(256) void gemm_bf16_kernel(
    const __nv_bfloat16* __restrict__ Ah, const __nv_bfloat16* __restrict__ Al,
    const __nv_bfloat16* __restrict__ Bh, const __nv_bfloat16* __restrict__ Bl,
    int K, int N, float* __restrict__ Cf,
    __nv_bfloat16* __restrict__ Ch, __nv_bfloat16* __restrict__ Cl)
{
    extern __shared__ __align__(16) uint8_t smem[];
    const uint32_t sb = smem_u32(smem);
    const int tid = threadIdx.x, wid = tid >> 5, lane = tid & 31;
    const int wm = wid & 3, wn = wid >> 2;
    const size_t m0 = (size_t)blockIdx.y * 128, n0 = (size_t)blockIdx.x * 128;

    const __nv_bfloat16* Ahp = Ah + m0 * K;
    const __nv_bfloat16* Alp = Al + m0 * K;
    const __nv_bfloat16* Bhp = Bh + n0;
    const __nv_bfloat16* Blp = Bl + n0;

    float acc[2][8][4];
    #pragma unroll
    for (int i = 0; i < 2; i++)
        #pragma unroll
        for (int j = 0; j < 8; j++)
            #pragma unroll
            for (int r = 0; r < 4; r++) acc[i][j][r] = 0.f;

    const uint32_t a_fb = (wm * 32 + (lane & 15)) * 80 + (lane >> 4) * 16;
    const uint32_t b_fb = SG_BH + (lane & 15) * 272 + wn * 128 + (lane >> 4) * 16;

    gemm_issue(sb, Ahp, Alp, Bhp, Blp, 0, K, N, tid);
    CP_COMMIT();

    const int niter = K >> 5;
    for (int it = 0; it < niter; it++) {
        CP_WAIT0();
        __syncthreads();
        if (it + 1 < niter) {
            gemm_issue(sb + ((it + 1) & 1) * SG_SIZE, Ahp, Alp, Bhp, Blp,
                       (it + 1) << 5, K, N, tid);
            CP_COMMIT();
        }
        const uint32_t st = sb + (it & 1) * SG_SIZE;

        #pragma unroll
        for (int ks = 0; ks < 2; ks++) {
            uint32_t ah[2][4], al[2][4];
            #pragma unroll
            for (int i = 0; i < 2; i++) {
                uint32_t aa = st + a_fb + i * 16 * 80 + ks * 32;
                LDSM_X4(ah[i], aa + SG_AH);
                LDSM_X4(al[i], aa + SG_AL);
            }
            #pragma unroll
            for (int nh = 0; nh < 2; nh++) {
                uint32_t bh[2][4], bl[2][4];
                #pragma unroll
                for (int j16 = 0; j16 < 2; j16++) {
                    uint32_t ba = st + b_fb + ks * 16 * 272 + nh * 64 + j16 * 32;
                    LDSM_X4T(bh[j16], ba);
                    LDSM_X4T(bl[j16], ba + (SG_BL - SG_BH));
                }
                #pragma unroll
                for (int j16 = 0; j16 < 2; j16++) {
                    int nf = nh * 4 + j16 * 2;
                    #pragma unroll
                    for (int i = 0; i < 2; i++) {
                        MMA16816(acc[i][nf],     ah[i], bh[j16][0], bh[j16][1]);
                        MMA16816(acc[i][nf + 1], ah[i], bh[j16][2], bh[j16][3]);
                        MMA16816(acc[i][nf],     ah[i], bl[j16][0], bl[j16][1]);
                        MMA16816(acc[i][nf + 1], ah[i], bl[j16][2], bl[j16][3]);
                        MMA16816(acc[i][nf],     al[i], bh[j16][0], bh[j16][1]);
                        MMA16816(acc[i][nf + 1], al[i], bh[j16][2], bh[j16][3]);
                    }
                }
            }
        }
        __syncthreads();
    }

    const int row_in = lane >> 2, col_in = (lane & 3) * 2;
    if (Cf) {
        #pragma unroll
        for (int i = 0; i < 2; i++)
            #pragma unroll
            for (int nf = 0; nf < 8; nf++) {
                float* p = Cf + (m0 + wm * 32 + i * 16 + row_in) * N + n0 + wn * 64 + nf * 8 + col_in;
                *(float2*)p                   = make_float2(acc[i][nf][0], acc[i][nf][1]);
                *(float2*)(p + 8 * (size_t)N) = make_float2(acc[i][nf][2], acc[i][nf][3]);
            }
    } else {
        #pragma unroll
        for (int i = 0; i < 2; i++)
            #pragma unroll
            for (int nf = 0; nf < 8; nf++) {
                size_t o = (m0 + wm * 32 + i * 16 + row_in) * N + n0 + wn * 64 + nf * 8 + col_in;
                uint32_t h01, l01, h23, l23;
                cvt_split2(acc[i][nf][0], acc[i][nf][1], h01, l01);
                cvt_split2(acc[i][nf][2], acc[i][nf][3], h23, l23);
                *(uint32_t*)(Ch + o) = h01;
                *(uint32_t*)(Cl + o) = l01;
                *(uint32_t*)(Ch + o + 8 * (size_t)N) = h23;
                *(uint32_t*)(Cl + o + 8 * (size_t)N) = l23;
            }
    }
}

// ---------------------------------------------------------------------------
// HMMA flash attention, bf16-split inputs, cp.async double-buffered K/V+bias.
// Block: 128 q-rows of one (b,h), 8 warps (16 q-rows each).
// ---------------------------------------------------------------------------
#define AQ_H 0
#define AQ_L 18432
#define KV0  36864
#define KV_KH 0
#define KV_KL 9216
#define KV_VH 18432
#define KV_VL 27648
#define KV_BIAS 36864
#define KV_STG 37888
#define ATTN_SMEM (KV0 + 2*KV_STG)   // 112640

__device__ __forceinline__ void attn_issue(
    uint32_t base, const __nv_bfloat16* kh, const __nv_bfloat16* kl,
    const __nv_bfloat16* vh, const __nv_bfloat16* vl,
    const float* biasrc, int tid)
{
    #pragma unroll
    for (int t = 0; t < 2; t++) {
        int i = tid + t * 256;
        int r = i >> 3, c = i & 7;                 // 64 rows x 8 chunks
        uint32_t off = r * 144 + c * 16;
        size_t so = (size_t)r * E3 + c * 8;
        CP16(base + KV_KH + off, kh + so);
        CP16(base + KV_KL + off, kl + so);
        CP16(base + KV_VH + off, vh + so);
        CP16(base + KV_VL + off, vl + so);
    }
    if (tid < 48) CP16(base + KV_BIAS + tid * 16, biasrc + tid * 4);
}

__global__ __launch_bounds__(256) void attn_mma_kernel() {
    extern __shared__ __align__(16) uint8_t sm8[];
    const uint32_t sb = smem_u32(sm8);
    const int tid = threadIdx.x, wid = tid >> 5, lane = tid & 31;
    const int q0 = blockIdx.x * 128;
    const int b = blockIdx.y >> 4, h = blockIdx.y & 15;
    const size_t rowbase = (size_t)b * SEQ;
    const float* bias_h = g_bias + h * NBP;

    // ---- stage Q (plain copies, once) ----
    const __nv_bfloat16* Qh = g_qkv_h + (rowbase + q0) * E3 + h * HD;
    const __nv_bfloat16* Ql = g_qkv_l + (rowbase + q0) * E3 + h * HD;
    #pragma unroll
    for (int t = 0; t < 4; t++) {
        int i = tid + t * 256;
        int r = i >> 3, c = i & 7;                 // 128 rows x 8 chunks
        uint32_t off = r * 144 + c * 16;
        size_t so = (size_t)r * E3 + c * 8;
        *(uint4*)(sm8 + AQ_H + off) = *(const uint4*)(Qh + so);
        *(uint4*)(sm8 + AQ_L + off) = *(const uint4*)(Ql + so);
    }

    // ---- prologue: issue kv tile 0 ----
    const __nv_bfloat16* Kh0 = g_qkv_h + rowbase * E3 + EMB + h * HD;
    const __nv_bfloat16* Kl0 = g_qkv_l + rowbase * E3 + EMB + h * HD;
    attn_issue(sb + KV0, Kh0, Kl0, Kh0 + EMB, Kl0 + EMB,
               bias_h - q0 + 1920, tid);
    CP_COMMIT();

    __syncthreads();
    // ---- hoist Q fragments ----
    uint32_t qh[4][4], ql[4][4];
    {
        uint32_t qa = sb + (wid * 16 + (lane & 15)) * 144 + (lane >> 4) * 16;
        #pragma unroll
        for (int ks = 0; ks < 4; ks++) {
            LDSM_X4(qh[ks], qa + AQ_H + ks * 32);
            LDSM_X4(ql[ks], qa + AQ_L + ks * 32);
        }
    }

    float m0 = -INFINITY, m1 = -INFINITY, l0 = 0.f, l1 = 0.f;
    float o[8][4];
    #pragma unroll
    for (int j = 0; j < 8; j++)
        #pragma unroll
        for (int r = 0; r < 4; r++) o[j][r] = 0.f;

    const uint32_t kv_fb = (lane & 15) * 144 + (lane >> 4) * 16;
    const int ccol = (lane & 3) * 2;
    const int r0 = wid * 16 + (lane >> 2);
    const int r1 = r0 + 8;

    for (int kt = 0; kt < SEQ / 64; kt++) {
        CP_WAIT0();
        __syncthreads();
        if (kt + 1 < SEQ / 64) {
            const __nv_bfloat16* Khn = g_qkv_h + (rowbase + (kt + 1) * 64) * E3 + EMB + h * HD;
            const __nv_bfloat16* Kln = g_qkv_l + (rowbase + (kt + 1) * 64) * E3 + EMB + h * HD;
            attn_issue(sb + KV0 + ((kt + 1) & 1) * KV_STG, Khn, Kln, Khn + EMB, Kln + EMB,
                       bias_h + (kt + 1) * 64 - q0 + 1920, tid);
            CP_COMMIT();
        }
        const uint32_t st = sb + KV0 + (kt & 1) * KV_STG;
        const float* sbias = (const float*)(sm8 + KV0 + (kt & 1) * KV_STG + KV_BIAS);

        // ---- S = Q @ K^T (3-term) ----
        float s[8][4];
        #pragma unroll
        for (int j = 0; j < 8; j++)
            #pragma unroll
            for (int r = 0; r < 4; r++) s[j][r] = 0.f;

        #pragma unroll
        for (int ks = 0; ks < 4; ks++) {
            #pragma unroll
            for (int nb = 0; nb < 4; nb++) {
                uint32_t kh[4], kl[4];
                uint32_t ka = st + kv_fb + nb * 16 * 144 + ks * 32;
                LDSM_X4(kh, ka + KV_KH);
                LDSM_X4(kl, ka + KV_KL);
                MMA16816(s[2*nb],   qh[ks], kh[0], kh[2]);
                MMA16816(s[2*nb+1], qh[ks], kh[1], kh[3]);
                MMA16816(s[2*nb],   qh[ks], kl[0], kl[2]);
                MMA16816(s[2*nb+1], qh[ks], kl[1], kl[3]);
                MMA16816(s[2*nb],   ql[ks], kh[0], kh[2]);
                MMA16816(s[2*nb+1], ql[ks], kh[1], kh[3]);
            }
        }

        // ---- bias + online softmax ----
        float mx0 = -INFINITY, mx1 = -INFINITY;
        #pragma unroll
        for (int j = 0; j < 8; j++) {
            int c = j * 8 + ccol;
            s[j][0] += sbias[c - r0 + 127];
            s[j][1] += sbias[c + 1 - r0 + 127];
            s[j][2] += sbias[c - r1 + 127];
            s[j][3] += sbias[c + 1 - r1 + 127];
            mx0 = fmaxf(mx0, fmaxf(s[j][0], s[j][1]));
            mx1 = fmaxf(mx1, fmaxf(s[j][2], s[j][3]));
        }
        mx0 = fmaxf(mx0, __shfl_xor_sync(0xffffffffu, mx0, 1));
        mx0 = fmaxf(mx0, __shfl_xor_sync(0xffffffffu, mx0, 2));
        mx1 = fmaxf(mx1, __shfl_xor_sync(0xffffffffu, mx1, 1));
        mx1 = fmaxf(mx1, __shfl_xor_sync(0xffffffffu, mx1, 2));
        float m0n = fmaxf(m0, mx0), m1n = fmaxf(m1, mx1);
        float c0 = exp2f((m0 - m0n) * L2E), c1 = exp2f((m1 - m1n) * L2E);
        float rs0 = 0.f, rs1 = 0.f;
        #pragma unroll
        for (int j = 0; j < 8; j++) {
            s[j][0] = exp2f((s[j][0] - m0n) * L2E);
            s[j][1] = exp2f((s[j][1] - m0n) * L2E);
            s[j][2] = exp2f((s[j][2] - m1n) * L2E);
            s[j][3] = exp2f((s[j][3] - m1n) * L2E);
            rs0 += s[j][0] + s[j][1];
            rs1 += s[j][2] + s[j][3];
        }
        rs0 += __shfl_xor_sync(0xffffffffu, rs0, 1);
        rs0 += __shfl_xor_sync(0xffffffffu, rs0, 2);
        rs1 += __shfl_xor_sync(0xffffffffu, rs1, 1);
        rs1 += __shfl_xor_sync(0xffffffffu, rs1, 2);
        l0 = l0 * c0 + rs0; l1 = l1 * c1 + rs1;
        m0 = m0n; m1 = m1n;
        #pragma unroll
        for (int j = 0; j < 8; j++) {
            o[j][0] *= c0; o[j][1] *= c0; o[j][2] *= c1; o[j][3] *= c1;
        }

        // ---- O += P @ V (3-term) ----
        #pragma unroll
        for (int t = 0; t < 4; t++) {
            uint32_t ah[4], al[4];
            cvt_split2(s[2*t][0],   s[2*t][1],   ah[0], al[0]);
            cvt_split2(s[2*t][2],   s[2*t][3],   ah[1], al[1]);
            cvt_split2(s[2*t+1][0], s[2*t+1][1], ah[2], al[2]);
            cvt_split2(s[2*t+1][2], s[2*t+1][3], ah[3], al[3]);
            #pragma unroll
            for (int g = 0; g < 4; g++) {
                uint32_t vh[4], vl[4];
                uint32_t va = st + kv_fb + t * 16 * 144 + g * 32;
                LDSM_X4T(vh, va + KV_VH);
                LDSM_X4T(vl, va + KV_VL);
                MMA16816(o[2*g],   ah, vh[0], vh[1]);
                MMA16816(o[2*g+1], ah, vh[2], vh[3]);
                MMA16816(o[2*g],   ah, vl[0], vl[1]);
                MMA16816(o[2*g+1], ah, vl[2], vl[3]);
                MMA16816(o[2*g],   al, vh[0], vh[1]);
                MMA16816(o[2*g+1], al, vh[2], vh[3]);
            }
        }
        __syncthreads();
    }

    // ---- epilogue: split bf16 out ----
    float inv0 = 1.f / l0, inv1 = 1.f / l1;
    size_t ob = (rowbase + q0 + r0) * EMB + h * HD + ccol;
    #pragma unroll
    for (int j = 0; j < 8; j++) {
        uint32_t h01, l01, h23, l23;
        cvt_split2(o[j][0] * inv0, o[j][1] * inv0, h01, l01);
        cvt_split2(o[j][2] * inv1, o[j][3] * inv1, h23, l23);
        *(uint32_t*)(g_attn_h + ob + j * 8) = h01;
        *(uint32_t*)(g_attn_l + ob + j * 8) = l01;
        *(uint32_t*)(g_attn_h + ob + 8 * EMB + j * 8) = h23;
        *(uint32_t*)(g_attn_l + ob + 8 * EMB + j * 8) = l23;
    }
}

// ---------------------------------------------------------------------------
extern "C" void kernel_launch(void* const* d_in, const int* in_sizes, int n_in,
                              void* d_out, int out_size) {
    const float* hidden = (const float*)d_in[0];   // [4096, 1024]
    const float* W_qkv  = (const float*)d_in[1];   // [1024, 3072]
    const float* W_out  = (const float*)d_in[2];   // [1024, 1024]
    const float* rel    = (const float*)d_in[3];   // [32, 16]
    float* out = (float*)d_out;                    // [4096, 1024]

    __nv_bfloat16 *ah, *al, *wqh, *wql, *woh, *wol, *qh, *ql, *ath, *atl;
    cudaGetSymbolAddress((void**)&ah,  g_ah);
    cudaGetSymbolAddress((void**)&al,  g_al);
    cudaGetSymbolAddress((void**)&wqh, g_wqh);
    cudaGetSymbolAddress((void**)&wql, g_wql);
    cudaGetSymbolAddress((void**)&woh, g_woh);
    cudaGetSymbolAddress((void**)&wol, g_wol);
    cudaGetSymbolAddress((void**)&qh,  g_qkv_h);
    cudaGetSymbolAddress((void**)&ql,  g_qkv_l);
    cudaGetSymbolAddress((void**)&ath, g_attn_h);
    cudaGetSymbolAddress((void**)&atl, g_attn_l);

    cudaFuncSetAttribute(gemm_bf16_kernel, cudaFuncAttributeMaxDynamicSharedMemorySize, GEMM_SMEM);
    cudaFuncSetAttribute(attn_mma_kernel, cudaFuncAttributeMaxDynamicSharedMemorySize, ATTN_SMEM);

    bias_kernel<<<(NBIAS + 255) / 256, 256>>>(rel);
    split_kernel<<<NROWS * EMB / 4 / 256, 256>>>(hidden, ah, al, NROWS * EMB / 4);
    split_kernel<<<EMB * E3 / 4 / 256, 256>>>(W_qkv, wqh, wql, EMB * E3 / 4);
    split_kernel<<<EMB * EMB / 4 / 256, 256>>>(W_out, woh, wol, EMB * EMB / 4);

    // QKV projection -> split bf16
    gemm_bf16_kernel<<<dim3(E3 / 128, NROWS / 128), 256, GEMM_SMEM>>>(
        ah, al, wqh, wql, EMB, E3, nullptr, qh, ql);

    // attention
    attn_mma_kernel<<<dim3(SEQ / 128, BATCH * NH), 256, ATTN_SMEM>>>();

    // output projection -> fp32
    gemm_bf16_kernel<<<dim3(EMB / 128, NROWS / 128), 256, GEMM_SMEM>>>(
        ath, atl, woh, wol, EMB, EMB, out, nullptr, nullptr);
}

// round 6
// speedup vs baseline: 2.6693x; 1.0871x over previous
#include <cuda_runtime.h>
#include <cuda_bf16.h>
#include <math.h>
#include <cstdint>

#define SEQ   2048
#define BATCH 2
#define NH    16
#define HD    64
#define EMB   1024
#define E3    3072
#define NROWS (BATCH*SEQ)          // 4096
#define NBIAS (2*SEQ-1)            // 4095
#define NBP   4096                 // padded bias row stride
#define L2E   1.4426950408889634f

// ---------------- scratch (__device__ globals; no allocs allowed) ----------
__device__ __nv_bfloat16 g_ah[(size_t)NROWS * EMB];    // hidden split
__device__ __nv_bfloat16 g_al[(size_t)NROWS * EMB];
__device__ __nv_bfloat16 g_wqh[(size_t)EMB * E3];      // W_qkv split (row-major)
__device__ __nv_bfloat16 g_wql[(size_t)EMB * E3];
__device__ __nv_bfloat16 g_woh[(size_t)EMB * EMB];     // W_out split
__device__ __nv_bfloat16 g_wol[(size_t)EMB * EMB];
__device__ __nv_bfloat16 g_qkv_h[(size_t)NROWS * E3];  // QKV result split
__device__ __nv_bfloat16 g_qkv_l[(size_t)NROWS * E3];
__device__ __nv_bfloat16 g_attn_h[(size_t)NROWS * EMB];
__device__ __nv_bfloat16 g_attn_l[(size_t)NROWS * EMB];
__device__ float g_bias[NH * NBP];

// ---------------- PTX helpers ----------------------------------------------
__device__ __forceinline__ uint32_t smem_u32(const void* p) {
    uint32_t a;
    asm("{ .reg .u64 t; cvta.to.shared.u64 t, %1; cvt.u32.u64 %0, t; }" : "=r"(a) : "l"(p));
    return a;
}
#define LDSM_X4(r, a) \
    asm volatile("ldmatrix.sync.aligned.m8n8.x4.shared.b16 {%0,%1,%2,%3}, [%4];" \
        : "=r"((r)[0]), "=r"((r)[1]), "=r"((r)[2]), "=r"((r)[3]) : "r"(a))
#define LDSM_X4T(r, a) \
    asm volatile("ldmatrix.sync.aligned.m8n8.x4.trans.shared.b16 {%0,%1,%2,%3}, [%4];" \
        : "=r"((r)[0]), "=r"((r)[1]), "=r"((r)[2]), "=r"((r)[3]) : "r"(a))
#define MMA16816(d, a, b0, b1) \
    asm volatile("mma.sync.aligned.m16n8k16.row.col.f32.bf16.bf16.f32 " \
        "{%0,%1,%2,%3}, {%4,%5,%6,%7}, {%8,%9}, {%0,%1,%2,%3};" \
        : "+f"((d)[0]), "+f"((d)[1]), "+f"((d)[2]), "+f"((d)[3]) \
        : "r"((a)[0]), "r"((a)[1]), "r"((a)[2]), "r"((a)[3]), "r"(b0), "r"(b1))
#define CP16(d, s) asm volatile("cp.async.cg.shared.global [%0], [%1], 16;" :: "r"(d), "l"(s))
#define CP_COMMIT() asm volatile("cp.async.commit_group;" ::: "memory")
#define CP_WAIT0()  asm volatile("cp.async.wait_group 0;" ::: "memory")

__device__ __forceinline__ void cvt_split2(float x, float y, uint32_t& h, uint32_t& l) {
    __nv_bfloat16 hx = __float2bfloat16(x);
    __nv_bfloat16 hy = __float2bfloat16(y);
    __nv_bfloat16 lx = __float2bfloat16(x - __bfloat162float(hx));
    __nv_bfloat16 ly = __float2bfloat16(y - __bfloat162float(hy));
    h = (uint32_t)__bfloat16_as_ushort(hx) | ((uint32_t)__bfloat16_as_ushort(hy) << 16);
    l = (uint32_t)__bfloat16_as_ushort(lx) | ((uint32_t)__bfloat16_as_ushort(ly) << 16);
}

// ---------------------------------------------------------------------------
// Bias table (padded row stride NBP)
// ---------------------------------------------------------------------------
__global__ void bias_kernel(const float* __restrict__ rel_emb) {
    int i = blockIdx.x * blockDim.x + threadIdx.x;
    if (i >= NBIAS) return;
    int d  = i - (SEQ - 1);
    int rb = (d > 0) ? 16 : 0;
    int ad = d < 0 ? -d : d;
    int bucket;
    if (ad < 8) bucket = ad;
    else {
        float v  = logf((float)ad * 0.125f) / 2.7725887f;
        int   lg = 8 + (int)(v * 8.0f);
        bucket = lg < 15 ? lg : 15;
    }
    int idx = rb + bucket;
    #pragma unroll
    for (int h = 0; h < NH; h++)
        g_bias[h * NBP + i] = rel_emb[idx * NH + h];
}

// ---------------------------------------------------------------------------
// fp32 -> (hi,lo) bf16 split, elementwise x4
// ---------------------------------------------------------------------------
__global__ void split_kernel(const float* __restrict__ in,
                             __nv_bfloat16* __restrict__ hi,
                             __nv_bfloat16* __restrict__ lo, int n4) {
    int i = blockIdx.x * blockDim.x + threadIdx.x;
    if (i >= n4) return;
    float4 a = ((const float4*)in)[i];
    uint32_t h01, l01, h23, l23;
    cvt_split2(a.x, a.y, h01, l01);
    cvt_split2(a.z, a.w, h23, l23);
    ((uint2*)hi)[i] = make_uint2(h01, h23);
    ((uint2*)lo)[i] = make_uint2(l01, l23);
}

// ---------------------------------------------------------------------------
// Pipelined bf16 GEMM: C = (Ah+Al)[M,K] @ (Bh+Bl)[K,N], 3-term HMMA.
// 128x128 tile, BK=32, 8 warps, cp.async double-buffered, 2 CTAs/SM.
// ---------------------------------------------------------------------------
#define SG_AH 0
#define SG_AL 10240
#define SG_BH 20480
#define SG_BL 29184
#define SG_SIZE 37888
#define GEMM_SMEM (2*SG_SIZE)   // 75776

__device__ __forceinline__ void gemm_issue(
    uint32_t base, const __nv_bfloat16* Ah, const __nv_bfloat16* Al,
    const __nv_bfloat16* Bh, const __nv_bfloat16* Bl,
    int k0, int K, int N, int tid)
{
    #pragma unroll
    for (int t = 0; t < 2; t++) {
        int i = tid + t * 256;
        int r = i >> 2, c = i & 3;                 // A: 128 rows x 4 chunks
        uint32_t off = r * 80 + c * 16;
        size_t so = (size_t)r * K + k0 + c * 8;
        CP16(base + SG_AH + off, Ah + so);
        CP16(base + SG_AL + off, Al + so);
    }
    #pragma unroll
    for (int t = 0; t < 2; t++) {
        int i = tid + t * 256;
        int r = i >> 4, c = i & 15;                // B: 32 rows x 16 chunks
        uint32_t off = r * 272 + c * 16;
        size_t so = (size_t)(k0 + r) * N + c * 8;
        CP16(base + SG_BH + off, Bh + so);
        CP16(base + SG_BL + off, Bl + so);
    }
}

__global__ __launch_bounds__(256, 2) void gemm_bf16_kernel(
    const __nv_bfloat16* __restrict__ Ah, const __nv_bfloat16* __restrict__ Al,
    const __nv_bfloat16* __restrict__ Bh, const __nv_bfloat16* __restrict__ Bl,
    int K, int N, float* __restrict__ Cf,
    __nv_bfloat16* __restrict__ Ch, __nv_bfloat16* __restrict__ Cl)
{
    extern __shared__ __align__(16) uint8_t smem[];
    const uint32_t sb = smem_u32(smem);
    const int tid = threadIdx.x, wid = tid >> 5, lane = tid & 31;
    const int wm = wid & 3, wn = wid >> 2;
    const size_t m0 = (size_t)blockIdx.y * 128, n0 = (size_t)blockIdx.x * 128;

    const __nv_bfloat16* Ahp = Ah + m0 * K;
    const __nv_bfloat16* Alp = Al + m0 * K;
    const __nv_bfloat16* Bhp = Bh + n0;
    const __nv_bfloat16* Blp = Bl + n0;

    float acc[2][8][4];
    #pragma unroll
    for (int i = 0; i < 2; i++)
        #pragma unroll
        for (int j = 0; j < 8; j++)
            #pragma unroll
            for (int r = 0; r < 4; r++) acc[i][j][r] = 0.f;

    const uint32_t a_fb = (wm * 32 + (lane & 15)) * 80 + (lane >> 4) * 16;
    const uint32_t b_fb = SG_BH + (lane & 15) * 272 + wn * 128 + (lane >> 4) * 16;

    gemm_issue(sb, Ahp, Alp, Bhp, Blp, 0, K, N, tid);
    CP_COMMIT();

    const int niter = K >> 5;
    for (int it = 0; it < niter; it++) {
        CP_WAIT0();
        __syncthreads();
        if (it + 1 < niter) {
            gemm_issue(sb + ((it + 1) & 1) * SG_SIZE, Ahp, Alp, Bhp, Blp,
                       (it + 1) << 5, K, N, tid);
            CP_COMMIT();
        }
        const uint32_t st = sb + (it & 1) * SG_SIZE;

        #pragma unroll
        for (int ks = 0; ks < 2; ks++) {
            uint32_t ah[2][4], al[2][4];
            #pragma unroll
            for (int i = 0; i < 2; i++) {
                uint32_t aa = st + a_fb + i * 16 * 80 + ks * 32;
                LDSM_X4(ah[i], aa + SG_AH);
                LDSM_X4(al[i], aa + SG_AL);
            }
            #pragma unroll
            for (int nh = 0; nh < 2; nh++) {
                uint32_t bh[2][4], bl[2][4];
                #pragma unroll
                for (int j16 = 0; j16 < 2; j16++) {
                    uint32_t ba = st + b_fb + ks * 16 * 272 + nh * 64 + j16 * 32;
                    LDSM_X4T(bh[j16], ba);
                    LDSM_X4T(bl[j16], ba + (SG_BL - SG_BH));
                }
                #pragma unroll
                for (int j16 = 0; j16 < 2; j16++) {
                    int nf = nh * 4 + j16 * 2;
                    #pragma unroll
                    for (int i = 0; i < 2; i++) {
                        MMA16816(acc[i][nf],     ah[i], bh[j16][0], bh[j16][1]);
                        MMA16816(acc[i][nf + 1], ah[i], bh[j16][2], bh[j16][3]);
                        MMA16816(acc[i][nf],     ah[i], bl[j16][0], bl[j16][1]);
                        MMA16816(acc[i][nf + 1], ah[i], bl[j16][2], bl[j16][3]);
                        MMA16816(acc[i][nf],     al[i], bh[j16][0], bh[j16][1]);
                        MMA16816(acc[i][nf + 1], al[i], bh[j16][2], bh[j16][3]);
                    }
                }
            }
        }
        __syncthreads();
    }

    const int row_in = lane >> 2, col_in = (lane & 3) * 2;
    if (Cf) {
        #pragma unroll
        for (int i = 0; i < 2; i++)
            #pragma unroll
            for (int nf = 0; nf < 8; nf++) {
                float* p = Cf + (m0 + wm * 32 + i * 16 + row_in) * N + n0 + wn * 64 + nf * 8 + col_in;
                *(float2*)p                   = make_float2(acc[i][nf][0], acc[i][nf][1]);
                *(float2*)(p + 8 * (size_t)N) = make_float2(acc[i][nf][2], acc[i][nf][3]);
            }
    } else {
        #pragma unroll
        for (int i = 0; i < 2; i++)
            #pragma unroll
            for (int nf = 0; nf < 8; nf++) {
                size_t o = (m0 + wm * 32 + i * 16 + row_in) * N + n0 + wn * 64 + nf * 8 + col_in;
                uint32_t h01, l01, h23, l23;
                cvt_split2(acc[i][nf][0], acc[i][nf][1], h01, l01);
                cvt_split2(acc[i][nf][2], acc[i][nf][3], h23, l23);
                *(uint32_t*)(Ch + o) = h01;
                *(uint32_t*)(Cl + o) = l01;
                *(uint32_t*)(Ch + o + 8 * (size_t)N) = h23;
                *(uint32_t*)(Cl + o + 8 * (size_t)N) = l23;
            }
    }
}

// ---------------------------------------------------------------------------
// HMMA flash attention, bf16-split inputs, cp.async double-buffered K/V+bias.
// Block: 128 q-rows of one (b,h), 8 warps. Q is staged in the stage-1 buffer
// (consumed into register fragments before stage 1 is first overwritten).
// ---------------------------------------------------------------------------
#define KV_KH 0
#define KV_KL 9216
#define KV_VH 18432
#define KV_VL 27648
#define KV_BIAS 36864
#define KV_STG 37888
#define AQ_H KV_STG                 // Q hi in stage-1 area
#define AQ_L (KV_STG + 18432)       // Q lo
#define ATTN_SMEM (2*KV_STG)        // 75776

__device__ __forceinline__ void attn_issue(
    uint32_t base, const __nv_bfloat16* kh, const __nv_bfloat16* kl,
    const __nv_bfloat16* vh, const __nv_bfloat16* vl,
    const float* biasrc, int tid)
{
    #pragma unroll
    for (int t = 0; t < 2; t++) {
        int i = tid + t * 256;
        int r = i >> 3, c = i & 7;                 // 64 rows x 8 chunks
        uint32_t off = r * 144 + c * 16;
        size_t so = (size_t)r * E3 + c * 8;
        CP16(base + KV_KH + off, kh + so);
        CP16(base + KV_KL + off, kl + so);
        CP16(base + KV_VH + off, vh + so);
        CP16(base + KV_VL + off, vl + so);
    }
    if (tid < 48) CP16(base + KV_BIAS + tid * 16, biasrc + tid * 4);
}

__global__ __launch_bounds__(256, 2) void attn_mma_kernel() {
    extern __shared__ __align__(16) uint8_t sm8[];
    const uint32_t sb = smem_u32(sm8);
    const int tid = threadIdx.x, wid = tid >> 5, lane = tid & 31;
    const int q0 = blockIdx.x * 128;
    const int b = blockIdx.y >> 4, h = blockIdx.y & 15;
    const size_t rowbase = (size_t)b * SEQ;
    const float* bias_h = g_bias + h * NBP;

    // ---- stage Q into stage-1 area (plain copies, transient) ----
    const __nv_bfloat16* Qh = g_qkv_h + (rowbase + q0) * E3 + h * HD;
    const __nv_bfloat16* Ql = g_qkv_l + (rowbase + q0) * E3 + h * HD;
    #pragma unroll
    for (int t = 0; t < 4; t++) {
        int i = tid + t * 256;
        int r = i >> 3, c = i & 7;                 // 128 rows x 8 chunks
        uint32_t off = r * 144 + c * 16;
        size_t so = (size_t)r * E3 + c * 8;
        *(uint4*)(sm8 + AQ_H + off) = *(const uint4*)(Qh + so);
        *(uint4*)(sm8 + AQ_L + off) = *(const uint4*)(Ql + so);
    }

    // ---- prologue: issue kv tile 0 into stage 0 ----
    const __nv_bfloat16* Kh0 = g_qkv_h + rowbase * E3 + EMB + h * HD;
    const __nv_bfloat16* Kl0 = g_qkv_l + rowbase * E3 + EMB + h * HD;
    attn_issue(sb, Kh0, Kl0, Kh0 + EMB, Kl0 + EMB, bias_h - q0 + 1920, tid);
    CP_COMMIT();

    __syncthreads();
    // ---- hoist Q fragments (Q smem is dead after this) ----
    uint32_t qh[4][4], ql[4][4];
    {
        uint32_t qa = sb + (wid * 16 + (lane & 15)) * 144 + (lane >> 4) * 16;
        #pragma unroll
        for (int ks = 0; ks < 4; ks++) {
            LDSM_X4(qh[ks], qa + AQ_H + ks * 32);
            LDSM_X4(ql[ks], qa + AQ_L + ks * 32);
        }
    }

    float m0 = -INFINITY, m1 = -INFINITY, l0 = 0.f, l1 = 0.f;
    float o[8][4];
    #pragma unroll
    for (int j = 0; j < 8; j++)
        #pragma unroll
        for (int r = 0; r < 4; r++) o[j][r] = 0.f;

    const uint32_t kv_fb = (lane & 15) * 144 + (lane >> 4) * 16;
    const int ccol = (lane & 3) * 2;
    const int r0 = wid * 16 + (lane >> 2);
    const int r1 = r0 + 8;

    for (int kt = 0; kt < SEQ / 64; kt++) {
        CP_WAIT0();
        __syncthreads();   // all warps done with prev stage (and Q hoist at kt=0)
        if (kt + 1 < SEQ / 64) {
            const __nv_bfloat16* Khn = g_qkv_h + (rowbase + (kt + 1) * 64) * E3 + EMB + h * HD;
            const __nv_bfloat16* Kln = g_qkv_l + (rowbase + (kt + 1) * 64) * E3 + EMB + h * HD;
            attn_issue(sb + ((kt + 1) & 1) * KV_STG, Khn, Kln, Khn + EMB, Kln + EMB,
                       bias_h + (kt + 1) * 64 - q0 + 1920, tid);
            CP_COMMIT();
        }
        const uint32_t st = sb + (kt & 1) * KV_STG;
        const float* sbias = (const float*)(sm8 + (kt & 1) * KV_STG + KV_BIAS);

        // ---- S = Q @ K^T (3-term) ----
        float s[8][4];
        #pragma unroll
        for (int j = 0; j < 8; j++)
            #pragma unroll
            for (int r = 0; r < 4; r++) s[j][r] = 0.f;

        #pragma unroll
        for (int ks = 0; ks < 4; ks++) {
            #pragma unroll
            for (int nb = 0; nb < 4; nb++) {
                uint32_t kh[4], kl[4];
                uint32_t ka = st + kv_fb + nb * 16 * 144 + ks * 32;
                LDSM_X4(kh, ka + KV_KH);
                LDSM_X4(kl, ka + KV_KL);
                MMA16816(s[2*nb],   qh[ks], kh[0], kh[2]);
                MMA16816(s[2*nb+1], qh[ks], kh[1], kh[3]);
                MMA16816(s[2*nb],   qh[ks], kl[0], kl[2]);
                MMA16816(s[2*nb+1], qh[ks], kl[1], kl[3]);
                MMA16816(s[2*nb],   ql[ks], kh[0], kh[2]);
                MMA16816(s[2*nb+1], ql[ks], kh[1], kh[3]);
            }
        }

        // ---- bias + online softmax ----
        float mx0 = -INFINITY, mx1 = -INFINITY;
        #pragma unroll
        for (int j = 0; j < 8; j++) {
            int c = j * 8 + ccol;
            s[j][0] += sbias[c - r0 + 127];
            s[j][1] += sbias[c + 1 - r0 + 127];
            s[j][2] += sbias[c - r1 + 127];
            s[j][3] += sbias[c + 1 - r1 + 127];
            mx0 = fmaxf(mx0, fmaxf(s[j][0], s[j][1]));
            mx1 = fmaxf(mx1, fmaxf(s[j][2], s[j][3]));
        }
        mx0 = fmaxf(mx0, __shfl_xor_sync(0xffffffffu, mx0, 1));
        mx0 = fmaxf(mx0, __shfl_xor_sync(0xffffffffu, mx0, 2));
        mx1 = fmaxf(mx1, __shfl_xor_sync(0xffffffffu, mx1, 1));
        mx1 = fmaxf(mx1, __shfl_xor_sync(0xffffffffu, mx1, 2));
        float m0n = fmaxf(m0, mx0), m1n = fmaxf(m1, mx1);
        float c0 = exp2f((m0 - m0n) * L2E), c1 = exp2f((m1 - m1n) * L2E);
        float rs0 = 0.f, rs1 = 0.f;
        #pragma unroll
        for (int j = 0; j < 8; j++) {
            s[j][0] = exp2f((s[j][0] - m0n) * L2E);
            s[j][1] = exp2f((s[j][1] - m0n) * L2E);
            s[j][2] = exp2f((s[j][2] - m1n) * L2E);
            s[j][3] = exp2f((s[j][3] - m1n) * L2E);
            rs0 += s[j][0] + s[j][1];
            rs1 += s[j][2] + s[j][3];
        }
        rs0 += __shfl_xor_sync(0xffffffffu, rs0, 1);
        rs0 += __shfl_xor_sync(0xffffffffu, rs0, 2);
        rs1 += __shfl_xor_sync(0xffffffffu, rs1, 1);
        rs1 += __shfl_xor_sync(0xffffffffu, rs1, 2);
        l0 = l0 * c0 + rs0; l1 = l1 * c1 + rs1;
        m0 = m0n; m1 = m1n;
        #pragma unroll
        for (int j = 0; j < 8; j++) {
            o[j][0] *= c0; o[j][1] *= c0; o[j][2] *= c1; o[j][3] *= c1;
        }

        // ---- O += P @ V (3-term) ----
        #pragma unroll
        for (int t = 0; t < 4; t++) {
            uint32_t ah[4], al[4];
            cvt_split2(s[2*t][0],   s[2*t][1],   ah[0], al[0]);
            cvt_split2(s[2*t][2],   s[2*t][3],   ah[1], al[1]);
            cvt_split2(s[2*t+1][0], s[2*t+1][1], ah[2], al[2]);
            cvt_split2(s[2*t+1][2], s[2*t+1][3], ah[3], al[3]);
            #pragma unroll
            for (int g = 0; g < 4; g++) {
                uint32_t vh[4], vl[4];
                uint32_t va = st + kv_fb + t * 16 * 144 + g * 32;
                LDSM_X4T(vh, va + KV_VH);
                LDSM_X4T(vl, va + KV_VL);
                MMA16816(o[2*g],   ah, vh[0], vh[1]);
                MMA16816(o[2*g+1], ah, vh[2], vh[3]);
                MMA16816(o[2*g],   ah, vl[0], vl[1]);
                MMA16816(o[2*g+1], ah, vl[2], vl[3]);
                MMA16816(o[2*g],   al, vh[0], vh[1]);
                MMA16816(o[2*g+1], al, vh[2], vh[3]);
            }
        }
        __syncthreads();
    }

    // ---- epilogue: split bf16 out ----
    float inv0 = 1.f / l0, inv1 = 1.f / l1;
    size_t ob = (rowbase + q0 + r0) * EMB + h * HD + ccol;
    #pragma unroll
    for (int j = 0; j < 8; j++) {
        uint32_t h01, l01, h23, l23;
        cvt_split2(o[j][0] * inv0, o[j][1] * inv0, h01, l01);
        cvt_split2(o[j][2] * inv1, o[j][3] * inv1, h23, l23);
        *(uint32_t*)(g_attn_h + ob + j * 8) = h01;
        *(uint32_t*)(g_attn_l + ob + j * 8) = l01;
        *(uint32_t*)(g_attn_h + ob + 8 * EMB + j * 8) = h23;
        *(uint32_t*)(g_attn_l + ob + 8 * EMB + j * 8) = l23;
    }
}

// ---------------------------------------------------------------------------
extern "C" void kernel_launch(void* const* d_in, const int* in_sizes, int n_in,
                              void* d_out, int out_size) {
    const float* hidden = (const float*)d_in[0];   // [4096, 1024]
    const float* W_qkv  = (const float*)d_in[1];   // [1024, 3072]
    const float* W_out  = (const float*)d_in[2];   // [1024, 1024]
    const float* rel    = (const float*)d_in[3];   // [32, 16]
    float* out = (float*)d_out;                    // [4096, 1024]

    __nv_bfloat16 *ah, *al, *wqh, *wql, *woh, *wol, *qh, *ql, *ath, *atl;
    cudaGetSymbolAddress((void**)&ah,  g_ah);
    cudaGetSymbolAddress((void**)&al,  g_al);
    cudaGetSymbolAddress((void**)&wqh, g_wqh);
    cudaGetSymbolAddress((void**)&wql, g_wql);
    cudaGetSymbolAddress((void**)&woh, g_woh);
    cudaGetSymbolAddress((void**)&wol, g_wol);
    cudaGetSymbolAddress((void**)&qh,  g_qkv_h);
    cudaGetSymbolAddress((void**)&ql,  g_qkv_l);
    cudaGetSymbolAddress((void**)&ath, g_attn_h);
    cudaGetSymbolAddress((void**)&atl, g_attn_l);

    cudaFuncSetAttribute(gemm_bf16_kernel, cudaFuncAttributeMaxDynamicSharedMemorySize, GEMM_SMEM);
    cudaFuncSetAttribute(attn_mma_kernel, cudaFuncAttributeMaxDynamicSharedMemorySize, ATTN_SMEM);

    bias_kernel<<<(NBIAS + 255) / 256, 256>>>(rel);
    split_kernel<<<NROWS * EMB / 4 / 256, 256>>>(hidden, ah, al, NROWS * EMB / 4);
    split_kernel<<<EMB * E3 / 4 / 256, 256>>>(W_qkv, wqh, wql, EMB * E3 / 4);
    split_kernel<<<EMB * EMB / 4 / 256, 256>>>(W_out, woh, wol, EMB * EMB / 4);

    // QKV projection -> split bf16
    gemm_bf16_kernel<<<dim3(E3 / 128, NROWS / 128), 256, GEMM_SMEM>>>(
        ah, al, wqh, wql, EMB, E3, nullptr, qh, ql);

    // attention
    attn_mma_kernel<<<dim3(SEQ / 128, BATCH * NH), 256, ATTN_SMEM>>>();

    // output projection -> fp32
    gemm_bf16_kernel<<<dim3(EMB / 128, NROWS / 128), 256, GEMM_SMEM>>>(
        ath, atl, woh, wol, EMB, EMB, out, nullptr, nullptr);
}

// round 10
// speedup vs baseline: 3.0697x; 1.1500x over previous
#include <cuda_runtime.h>
#include <cuda_fp16.h>
#include <math.h>
#include <cstdint>

#define SEQ   2048
#define BATCH 2
#define NH    16
#define HD    64
#define EMB   1024
#define E3    3072
#define NROWS (BATCH*SEQ)          // 4096
#define NBIAS (2*SEQ-1)            // 4095
#define NBP   4096
#define L2E   1.4426950408889634f

// ---------------- scratch (__device__ globals) ------------------------------
__device__ __half g_ah[(size_t)NROWS * EMB];    // hidden split hi
__device__ __half g_al[(size_t)NROWS * EMB];    // hidden split lo
__device__ __half g_wqh[(size_t)EMB * E3];      // W_qkv hi
__device__ __half g_wql[(size_t)EMB * E3];      // W_qkv lo (used for Q,K cols)
__device__ __half g_woh[(size_t)EMB * EMB];     // W_out hi only
__device__ __half g_qkv_h[(size_t)NROWS * E3];  // QKV result hi
__device__ __half g_qkv_l[(size_t)NROWS * E3];  // QKV result lo (Q,K cols)
__device__ __half g_attn_h[(size_t)NROWS * EMB];
__device__ __half g_attn_l[(size_t)NROWS * EMB];
__device__ float g_bias[NH * NBP];

// ---------------- PTX helpers ----------------------------------------------
__device__ __forceinline__ uint32_t smem_u32(const void* p) {
    uint32_t a;
    asm("{ .reg .u64 t; cvta.to.shared.u64 t, %1; cvt.u32.u64 %0, t; }" : "=r"(a) : "l"(p));
    return a;
}
#define LDSM_X4(r, a) \
    asm volatile("ldmatrix.sync.aligned.m8n8.x4.shared.b16 {%0,%1,%2,%3}, [%4];" \
        : "=r"((r)[0]), "=r"((r)[1]), "=r"((r)[2]), "=r"((r)[3]) : "r"(a))
#define LDSM_X4T(r, a) \
    asm volatile("ldmatrix.sync.aligned.m8n8.x4.trans.shared.b16 {%0,%1,%2,%3}, [%4];" \
        : "=r"((r)[0]), "=r"((r)[1]), "=r"((r)[2]), "=r"((r)[3]) : "r"(a))
#define MMA16816(d, a, b0, b1) \
    asm volatile("mma.sync.aligned.m16n8k16.row.col.f32.f16.f16.f32 " \
        "{%0,%1,%2,%3}, {%4,%5,%6,%7}, {%8,%9}, {%0,%1,%2,%3};" \
        : "+f"((d)[0]), "+f"((d)[1]), "+f"((d)[2]), "+f"((d)[3]) \
        : "r"((a)[0]), "r"((a)[1]), "r"((a)[2]), "r"((a)[3]), "r"(b0), "r"(b1))
#define CP16(d, s) asm volatile("cp.async.cg.shared.global [%0], [%1], 16;" :: "r"(d), "l"(s))
#define CP_COMMIT() asm volatile("cp.async.commit_group;" ::: "memory")
#define CP_WAIT0()  asm volatile("cp.async.wait_group 0;" ::: "memory")

__device__ __forceinline__ void cvt_split2h(float x, float y, uint32_t& h, uint32_t& l) {
    __half hx = __float2half(x);
    __half hy = __float2half(y);
    __half lx = __float2half(x - __half2float(hx));
    __half ly = __float2half(y - __half2float(hy));
    h = (uint32_t)__half_as_ushort(hx) | ((uint32_t)__half_as_ushort(hy) << 16);
    l = (uint32_t)__half_as_ushort(lx) | ((uint32_t)__half_as_ushort(ly) << 16);
}
__device__ __forceinline__ uint32_t cvt2h(float x, float y) {
    return (uint32_t)__half_as_ushort(__float2half(x)) |
           ((uint32_t)__half_as_ushort(__float2half(y)) << 16);
}

// ---------------------------------------------------------------------------
// Bias table
// ---------------------------------------------------------------------------
__global__ void bias_kernel(const float* __restrict__ rel_emb) {
    int i = blockIdx.x * blockDim.x + threadIdx.x;
    if (i >= NBIAS) return;
    int d  = i - (SEQ - 1);
    int rb = (d > 0) ? 16 : 0;
    int ad = d < 0 ? -d : d;
    int bucket;
    if (ad < 8) bucket = ad;
    else {
        float v  = logf((float)ad * 0.125f) / 2.7725887f;
        int   lg = 8 + (int)(v * 8.0f);
        bucket = lg < 15 ? lg : 15;
    }
    int idx = rb + bucket;
    #pragma unroll
    for (int h = 0; h < NH; h++)
        g_bias[h * NBP + i] = rel_emb[idx * NH + h];
}

// ---------------------------------------------------------------------------
// fp32 -> (hi,lo) fp16 split
// ---------------------------------------------------------------------------
__global__ void split_kernel(const float* __restrict__ in,
                             __half* __restrict__ hi,
                             __half* __restrict__ lo, int n4) {
    int i = blockIdx.x * blockDim.x + threadIdx.x;
    if (i >= n4) return;
    float4 a = ((const float4*)in)[i];
    uint32_t h01, l01, h23, l23;
    cvt_split2h(a.x, a.y, h01, l01);
    cvt_split2h(a.z, a.w, h23, l23);
    ((uint2*)hi)[i] = make_uint2(h01, h23);
    ((uint2*)lo)[i] = make_uint2(l01, l23);
}

// fp32 -> fp16 hi only
__global__ void cvt_kernel(const float* __restrict__ in,
                           __half* __restrict__ out, int n4) {
    int i = blockIdx.x * blockDim.x + threadIdx.x;
    if (i >= n4) return;
    float4 a = ((const float4*)in)[i];
    ((uint2*)out)[i] = make_uint2(cvt2h(a.x, a.y), cvt2h(a.z, a.w));
}

// ---------------------------------------------------------------------------
// Pipelined fp16 GEMM. USE3: C = AhBh + AlBh + AhBl (3-term), else 2-term.
// 128x128 tile, BK=32, 8 warps, cp.async double-buffered, 2 CTAs/SM.
// ---------------------------------------------------------------------------
#define SG_AH 0
#define SG_AL 10240
#define SG_BH 20480
#define SG_BL 29184
#define GEMM_SMEM3 (2*37888)   // 75776
#define GEMM_SMEM2 (2*29184)   // 58368

template<bool USE3>
__device__ __forceinline__ void gemm_issue(
    uint32_t base, const __half* Ah, const __half* Al,
    const __half* Bh, const __half* Bl,
    int k0, int K, int N, int tid)
{
    #pragma unroll
    for (int t = 0; t < 2; t++) {
        int i = tid + t * 256;
        int r = i >> 2, c = i & 3;                 // A: 128 rows x 4 chunks
        uint32_t off = r * 80 + c * 16;
        size_t so = (size_t)r * K + k0 + c * 8;
        CP16(base + SG_AH + off, Ah + so);
        CP16(base + SG_AL + off, Al + so);
    }
    #pragma unroll
    for (int t = 0; t < 2; t++) {
        int i = tid + t * 256;
        int r = i >> 4, c = i & 15;                // B: 32 rows x 16 chunks
        uint32_t off = r * 272 + c * 16;
        size_t so = (size_t)(k0 + r) * N + c * 8;
        CP16(base + SG_BH + off, Bh + so);
        if (USE3) CP16(base + SG_BL + off, Bl + so);
    }
}

template<bool USE3>
__global__ __launch_bounds__(256, 2) void gemm_fp16_kernel(
    const __half* __restrict__ Ah, const __half* __restrict__ Al,
    const __half* __restrict__ Bh, const __half* __restrict__ Bl,
    int K, int N, int nbase, float* __restrict__ Cf,
    __half* __restrict__ Ch, __half* __restrict__ Cl)
{
    constexpr int SSZ = USE3 ? 37888 : 29184;
    extern __shared__ __align__(16) uint8_t smem[];
    const uint32_t sb = smem_u32(smem);
    const int tid = threadIdx.x, wid = tid >> 5, lane = tid & 31;
    const int wm = wid & 3, wn = wid >> 2;
    const size_t m0 = (size_t)blockIdx.y * 128;
    const size_t n0 = (size_t)nbase + blockIdx.x * 128;

    const __half* Ahp = Ah + m0 * K;
    const __half* Alp = Al + m0 * K;
    const __half* Bhp = Bh + n0;
    const __half* Blp = USE3 ? (Bl + n0) : nullptr;

    float acc[2][8][4];
    #pragma unroll
    for (int i = 0; i < 2; i++)
        #pragma unroll
        for (int j = 0; j < 8; j++)
            #pragma unroll
            for (int r = 0; r < 4; r++) acc[i][j][r] = 0.f;

    const uint32_t a_fb = (wm * 32 + (lane & 15)) * 80 + (lane >> 4) * 16;
    const uint32_t b_fb = SG_BH + (lane & 15) * 272 + wn * 128 + (lane >> 4) * 16;

    gemm_issue<USE3>(sb, Ahp, Alp, Bhp, Blp, 0, K, N, tid);
    CP_COMMIT();

    const int niter = K >> 5;
    for (int it = 0; it < niter; it++) {
        CP_WAIT0();
        __syncthreads();
        if (it + 1 < niter) {
            gemm_issue<USE3>(sb + ((it + 1) & 1) * SSZ, Ahp, Alp, Bhp, Blp,
                             (it + 1) << 5, K, N, tid);
            CP_COMMIT();
        }
        const uint32_t st = sb + (it & 1) * SSZ;

        #pragma unroll
        for (int ks = 0; ks < 2; ks++) {
            uint32_t ah[2][4], al[2][4];
            #pragma unroll
            for (int i = 0; i < 2; i++) {
                uint32_t aa = st + a_fb + i * 16 * 80 + ks * 32;
                LDSM_X4(ah[i], aa + SG_AH);
                LDSM_X4(al[i], aa + SG_AL);
            }
            #pragma unroll
            for (int nh = 0; nh < 2; nh++) {
                #pragma unroll
                for (int j16 = 0; j16 < 2; j16++) {
                    uint32_t ba = st + b_fb + ks * 16 * 272 + nh * 64 + j16 * 32;
                    uint32_t bh[4];
                    LDSM_X4T(bh, ba);
                    int nf = nh * 4 + j16 * 2;
                    #pragma unroll
                    for (int i = 0; i < 2; i++) {
                        MMA16816(acc[i][nf],     ah[i], bh[0], bh[1]);
                        MMA16816(acc[i][nf + 1], ah[i], bh[2], bh[3]);
                        MMA16816(acc[i][nf],     al[i], bh[0], bh[1]);
                        MMA16816(acc[i][nf + 1], al[i], bh[2], bh[3]);
                    }
                    if (USE3) {
                        uint32_t bl[4];
                        LDSM_X4T(bl, ba + (SG_BL - SG_BH));
                        #pragma unroll
                        for (int i = 0; i < 2; i++) {
                            MMA16816(acc[i][nf],     ah[i], bl[0], bl[1]);
                            MMA16816(acc[i][nf + 1], ah[i], bl[2], bl[3]);
                        }
                    }
                }
            }
        }
    }

    const int row_in = lane >> 2, col_in = (lane & 3) * 2;
    if (Cf) {
        #pragma unroll
        for (int i = 0; i < 2; i++)
            #pragma unroll
            for (int nf = 0; nf < 8; nf++) {
                float* p = Cf + (m0 + wm * 32 + i * 16 + row_in) * N + n0 + wn * 64 + nf * 8 + col_in;
                *(float2*)p                   = make_float2(acc[i][nf][0], acc[i][nf][1]);
                *(float2*)(p + 8 * (size_t)N) = make_float2(acc[i][nf][2], acc[i][nf][3]);
            }
    } else {
        #pragma unroll
        for (int i = 0; i < 2; i++)
            #pragma unroll
            for (int nf = 0; nf < 8; nf++) {
                size_t o = (m0 + wm * 32 + i * 16 + row_in) * N + n0 + wn * 64 + nf * 8 + col_in;
                uint32_t h01, l01, h23, l23;
                cvt_split2h(acc[i][nf][0], acc[i][nf][1], h01, l01);
                cvt_split2h(acc[i][nf][2], acc[i][nf][3], h23, l23);
                *(uint32_t*)(Ch + o) = h01;
                *(uint32_t*)(Ch + o + 8 * (size_t)N) = h23;
                if (Cl) {
                    *(uint32_t*)(Cl + o) = l01;
                    *(uint32_t*)(Cl + o + 8 * (size_t)N) = l23;
                }
            }
    }
}

// ---------------------------------------------------------------------------
// fp16 HMMA flash attention: QK 3-term (Qh/Ql x Kh + Qh x Kl), PV 2-term.
// Block: 128 q-rows of one (b,h), 8 warps, cp.async double-buffered K/V+bias.
// ---------------------------------------------------------------------------
#define KV_KH 0
#define KV_KL 9216
#define KV_VH 18432
#define KV_BIAS 27648
#define KV_STG 28672
#define AQ_H (2*KV_STG)             // 57344
#define AQ_L (AQ_H + 18432)
#define ATTN_SMEM (AQ_L + 18432)    // 94208

__device__ __forceinline__ void attn_issue(
    uint32_t base, const __half* kh, const __half* kl, const __half* vh,
    const float* biasrc, int tid)
{
    #pragma unroll
    for (int t = 0; t < 2; t++) {
        int i = tid + t * 256;
        int r = i >> 3, c = i & 7;                 // 64 rows x 8 chunks
        uint32_t off = r * 144 + c * 16;
        size_t so = (size_t)r * E3 + c * 8;
        CP16(base + KV_KH + off, kh + so);
        CP16(base + KV_KL + off, kl + so);
        CP16(base + KV_VH + off, vh + so);
    }
    if (tid < 48) CP16(base + KV_BIAS + tid * 16, biasrc + tid * 4);
}

__global__ __launch_bounds__(256, 2) void attn_mma_kernel() {
    extern __shared__ __align__(16) uint8_t sm8[];
    const uint32_t sb = smem_u32(sm8);
    const int tid = threadIdx.x, wid = tid >> 5, lane = tid & 31;
    const int q0 = blockIdx.x * 128;
    const int b = blockIdx.y >> 4, h = blockIdx.y & 15;
    const size_t rowbase = (size_t)b * SEQ;
    const float* bias_h = g_bias + h * NBP;

    // ---- stage Q hi/lo (plain copies) ----
    const __half* Qh = g_qkv_h + (rowbase + q0) * E3 + h * HD;
    const __half* Ql = g_qkv_l + (rowbase + q0) * E3 + h * HD;
    #pragma unroll
    for (int t = 0; t < 4; t++) {
        int i = tid + t * 256;
        int r = i >> 3, c = i & 7;
        uint32_t off = r * 144 + c * 16;
        size_t so = (size_t)r * E3 + c * 8;
        *(uint4*)(sm8 + AQ_H + off) = *(const uint4*)(Qh + so);
        *(uint4*)(sm8 + AQ_L + off) = *(const uint4*)(Ql + so);
    }

    // ---- prologue: issue kv tile 0 ----
    const __half* Kh0 = g_qkv_h + rowbase * E3 + EMB + h * HD;
    const __half* Kl0 = g_qkv_l + rowbase * E3 + EMB + h * HD;
    attn_issue(sb, Kh0, Kl0, Kh0 + EMB, bias_h - q0 + 1920, tid);
    CP_COMMIT();

    __syncthreads();
    // ---- hoist Q fragments ----
    uint32_t qh[4][4], ql[4][4];
    {
        uint32_t qa = sb + (wid * 16 + (lane & 15)) * 144 + (lane >> 4) * 16;
        #pragma unroll
        for (int ks = 0; ks < 4; ks++) {
            LDSM_X4(qh[ks], qa + AQ_H + ks * 32);
            LDSM_X4(ql[ks], qa + AQ_L + ks * 32);
        }
    }

    float m0 = -INFINITY, m1 = -INFINITY, l0 = 0.f, l1 = 0.f;
    float o[8][4];
    #pragma unroll
    for (int j = 0; j < 8; j++)
        #pragma unroll
        for (int r = 0; r < 4; r++) o[j][r] = 0.f;

    const uint32_t kv_fb = (lane & 15) * 144 + (lane >> 4) * 16;
    const int ccol = (lane & 3) * 2;
    const int r0 = wid * 16 + (lane >> 2);
    const int r1 = r0 + 8;

    for (int kt = 0; kt < SEQ / 64; kt++) {
        CP_WAIT0();
        __syncthreads();
        if (kt + 1 < SEQ / 64) {
            const __half* Khn = g_qkv_h + (rowbase + (kt + 1) * 64) * E3 + EMB + h * HD;
            const __half* Kln = g_qkv_l + (rowbase + (kt + 1) * 64) * E3 + EMB + h * HD;
            attn_issue(sb + ((kt + 1) & 1) * KV_STG, Khn, Kln, Khn + EMB,
                       bias_h + (kt + 1) * 64 - q0 + 1920, tid);
            CP_COMMIT();
        }
        const uint32_t st = sb + (kt & 1) * KV_STG;
        const float* sbias = (const float*)(sm8 + (kt & 1) * KV_STG + KV_BIAS);

        // ---- S = Q @ K^T (3-term) ----
        float s[8][4];
        #pragma unroll
        for (int j = 0; j < 8; j++)
            #pragma unroll
            for (int r = 0; r < 4; r++) s[j][r] = 0.f;

        #pragma unroll
        for (int ks = 0; ks < 4; ks++) {
            #pragma unroll
            for (int nb = 0; nb < 4; nb++) {
                uint32_t kh[4], kl[4];
                uint32_t ka = st + kv_fb + nb * 16 * 144 + ks * 32;
                LDSM_X4(kh, ka + KV_KH);
                LDSM_X4(kl, ka + KV_KL);
                MMA16816(s[2*nb],   qh[ks], kh[0], kh[2]);
                MMA16816(s[2*nb+1], qh[ks], kh[1], kh[3]);
                MMA16816(s[2*nb],   ql[ks], kh[0], kh[2]);
                MMA16816(s[2*nb+1], ql[ks], kh[1], kh[3]);
                MMA16816(s[2*nb],   qh[ks], kl[0], kl[2]);
                MMA16816(s[2*nb+1], qh[ks], kl[1], kl[3]);
            }
        }

        // ---- bias + online softmax ----
        float mx0 = -INFINITY, mx1 = -INFINITY;
        #pragma unroll
        for (int j = 0; j < 8; j++) {
            int c = j * 8 + ccol;
            s[j][0] += sbias[c - r0 + 127];
            s[j][1] += sbias[c + 1 - r0 + 127];
            s[j][2] += sbias[c - r1 + 127];
            s[j][3] += sbias[c + 1 - r1 + 127];
            mx0 = fmaxf(mx0, fmaxf(s[j][0], s[j][1]));
            mx1 = fmaxf(mx1, fmaxf(s[j][2], s[j][3]));
        }
        mx0 = fmaxf(mx0, __shfl_xor_sync(0xffffffffu, mx0, 1));
        mx0 = fmaxf(mx0, __shfl_xor_sync(0xffffffffu, mx0, 2));
        mx1 = fmaxf(mx1, __shfl_xor_sync(0xffffffffu, mx1, 1));
        mx1 = fmaxf(mx1, __shfl_xor_sync(0xffffffffu, mx1, 2));
        float m0n = fmaxf(m0, mx0), m1n = fmaxf(m1, mx1);
        float c0 = exp2f((m0 - m0n) * L2E), c1 = exp2f((m1 - m1n) * L2E);
        float rs0 = 0.f, rs1 = 0.f;
        #pragma unroll
        for (int j = 0; j < 8; j++) {
            s[j][0] = exp2f((s[j][0] - m0n) * L2E);
            s[j][1] = exp2f((s[j][1] - m0n) * L2E);
            s[j][2] = exp2f((s[j][2] - m1n) * L2E);
            s[j][3] = exp2f((s[j][3] - m1n) * L2E);
            rs0 += s[j][0] + s[j][1];
            rs1 += s[j][2] + s[j][3];
        }
        rs0 += __shfl_xor_sync(0xffffffffu, rs0, 1);
        rs0 += __shfl_xor_sync(0xffffffffu, rs0, 2);
        rs1 += __shfl_xor_sync(0xffffffffu, rs1, 1);
        rs1 += __shfl_xor_sync(0xffffffffu, rs1, 2);
        l0 = l0 * c0 + rs0; l1 = l1 * c1 + rs1;
        m0 = m0n; m1 = m1n;
        #pragma unroll
        for (int j = 0; j < 8; j++) {
            o[j][0] *= c0; o[j][1] *= c0; o[j][2] *= c1; o[j][3] *= c1;
        }

        // ---- O += P @ V (2-term) ----
        #pragma unroll
        for (int t = 0; t < 4; t++) {
            uint32_t ah[4], al[4];
            cvt_split2h(s[2*t][0],   s[2*t][1],   ah[0], al[0]);
            cvt_split2h(s[2*t][2],   s[2*t][3],   ah[1], al[1]);
            cvt_split2h(s[2*t+1][0], s[2*t+1][1], ah[2], al[2]);
            cvt_split2h(s[2*t+1][2], s[2*t+1][3], ah[3], al[3]);
            #pragma unroll
            for (int g = 0; g < 4; g++) {
                uint32_t vh[4];
                LDSM_X4T(vh, st + kv_fb + t * 16 * 144 + g * 32 + KV_VH);
                MMA16816(o[2*g],   ah, vh[0], vh[1]);
                MMA16816(o[2*g+1], ah, vh[2], vh[3]);
                MMA16816(o[2*g],   al, vh[0], vh[1]);
                MMA16816(o[2*g+1], al, vh[2], vh[3]);
            }
        }
    }

    // ---- epilogue: split fp16 out ----
    float inv0 = 1.f / l0, inv1 = 1.f / l1;
    size_t ob = (rowbase + q0 + r0) * EMB + h * HD + ccol;
    #pragma unroll
    for (int j = 0; j < 8; j++) {
        uint32_t h01, l01, h23, l23;
        cvt_split2h(o[j][0] * inv0, o[j][1] * inv0, h01, l01);
        cvt_split2h(o[j][2] * inv1, o[j][3] * inv1, h23, l23);
        *(uint32_t*)(g_attn_h + ob + j * 8) = h01;
        *(uint32_t*)(g_attn_l + ob + j * 8) = l01;
        *(uint32_t*)(g_attn_h + ob + 8 * EMB + j * 8) = h23;
        *(uint32_t*)(g_attn_l + ob + 8 * EMB + j * 8) = l23;
    }
}

// ---------------------------------------------------------------------------
extern "C" void kernel_launch(void* const* d_in, const int* in_sizes, int n_in,
                              void* d_out, int out_size) {
    const float* hidden = (const float*)d_in[0];   // [4096, 1024]
    const float* W_qkv  = (const float*)d_in[1];   // [1024, 3072]
    const float* W_out  = (const float*)d_in[2];   // [1024, 1024]
    const float* rel    = (const float*)d_in[3];   // [32, 16]
    float* out = (float*)d_out;                    // [4096, 1024]

    __half *ah, *al, *wqh, *wql, *woh, *qh, *ql, *ath, *atl;
    cudaGetSymbolAddress((void**)&ah,  g_ah);
    cudaGetSymbolAddress((void**)&al,  g_al);
    cudaGetSymbolAddress((void**)&wqh, g_wqh);
    cudaGetSymbolAddress((void**)&wql, g_wql);
    cudaGetSymbolAddress((void**)&woh, g_woh);
    cudaGetSymbolAddress((void**)&qh,  g_qkv_h);
    cudaGetSymbolAddress((void**)&ql,  g_qkv_l);
    cudaGetSymbolAddress((void**)&ath, g_attn_h);
    cudaGetSymbolAddress((void**)&atl, g_attn_l);

    cudaFuncSetAttribute(gemm_fp16_kernel<true>,
                         cudaFuncAttributeMaxDynamicSharedMemorySize, GEMM_SMEM3);
    cudaFuncSetAttribute(gemm_fp16_kernel<false>,
                         cudaFuncAttributeMaxDynamicSharedMemorySize, GEMM_SMEM2);
    cudaFuncSetAttribute(attn_mma_kernel,
                         cudaFuncAttributeMaxDynamicSharedMemorySize, ATTN_SMEM);

    bias_kernel<<<(NBIAS + 255) / 256, 256>>>(rel);
    split_kernel<<<NROWS * EMB / 4 / 256, 256>>>(hidden, ah, al, NROWS * EMB / 4);
    split_kernel<<<EMB * E3 / 4 / 256, 256>>>(W_qkv, wqh, wql, EMB * E3 / 4);
    cvt_kernel<<<EMB * EMB / 4 / 256, 256>>>(W_out, woh, EMB * EMB / 4);

    // QKV projection, Q+K columns (n < 2048): 3-term, store hi+lo
    gemm_fp16_kernel<true><<<dim3(16, NROWS / 128), 256, GEMM_SMEM3>>>(
        ah, al, wqh, wql, EMB, E3, 0, nullptr, qh, ql);
    // QKV projection, V columns (n >= 2048): 2-term, store hi only
    gemm_fp16_kernel<false><<<dim3(8, NROWS / 128), 256, GEMM_SMEM2>>>(
        ah, al, wqh, nullptr, EMB, E3, 2048, nullptr, qh, nullptr);

    // attention
    attn_mma_kernel<<<dim3(SEQ / 128, BATCH * NH), 256, ATTN_SMEM>>>();

    // output projection: 2-term -> fp32
    gemm_fp16_kernel<false><<<dim3(8, NROWS / 128), 256, GEMM_SMEM2>>>(
        ath, atl, woh, nullptr, EMB, EMB, 0, out, nullptr, nullptr);
}

// round 11
// speedup vs baseline: 3.3672x; 1.0969x over previous
#include <cuda_runtime.h>
#include <cuda_fp16.h>
#include <math.h>
#include <cstdint>

#define SEQ   2048
#define BATCH 2
#define NH    16
#define HD    64
#define EMB   1024
#define E3    3072
#define NROWS (BATCH*SEQ)          // 4096
#define NBIAS (2*SEQ-1)            // 4095
#define NBP   4096
#define L2E   1.4426950408889634f

// ---------------- scratch (__device__ globals) ------------------------------
__device__ __half g_ah[(size_t)NROWS * EMB];    // hidden split hi
__device__ __half g_al[(size_t)NROWS * EMB];    // hidden split lo
__device__ __half g_wqh[(size_t)EMB * E3];      // W_qkv hi
__device__ __half g_wql[(size_t)EMB * E3];      // W_qkv lo (used for Q,K cols)
__device__ __half g_woh[(size_t)EMB * EMB];     // W_out hi only
__device__ __half g_qkv_h[(size_t)NROWS * E3];  // QKV result hi
__device__ __half g_qkv_l[(size_t)NROWS * E3];  // QKV result lo (Q,K cols)
__device__ __half g_attn_h[(size_t)NROWS * EMB];
__device__ __half g_attn_l[(size_t)NROWS * EMB];
__device__ float g_bias[NH * NBP];

// ---------------- PTX helpers ----------------------------------------------
__device__ __forceinline__ uint32_t smem_u32(const void* p) {
    uint32_t a;
    asm("{ .reg .u64 t; cvta.to.shared.u64 t, %1; cvt.u32.u64 %0, t; }" : "=r"(a) : "l"(p));
    return a;
}
#define LDSM_X4(r, a) \
    asm volatile("ldmatrix.sync.aligned.m8n8.x4.shared.b16 {%0,%1,%2,%3}, [%4];" \
        : "=r"((r)[0]), "=r"((r)[1]), "=r"((r)[2]), "=r"((r)[3]) : "r"(a))
#define LDSM_X4T(r, a) \
    asm volatile("ldmatrix.sync.aligned.m8n8.x4.trans.shared.b16 {%0,%1,%2,%3}, [%4];" \
        : "=r"((r)[0]), "=r"((r)[1]), "=r"((r)[2]), "=r"((r)[3]) : "r"(a))
#define MMA16816(d, a, b0, b1) \
    asm volatile("mma.sync.aligned.m16n8k16.row.col.f32.f16.f16.f32 " \
        "{%0,%1,%2,%3}, {%4,%5,%6,%7}, {%8,%9}, {%0,%1,%2,%3};" \
        : "+f"((d)[0]), "+f"((d)[1]), "+f"((d)[2]), "+f"((d)[3]) \
        : "r"((a)[0]), "r"((a)[1]), "r"((a)[2]), "r"((a)[3]), "r"(b0), "r"(b1))
#define CP16(d, s) asm volatile("cp.async.cg.shared.global [%0], [%1], 16;" :: "r"(d), "l"(s))
#define CP_COMMIT() asm volatile("cp.async.commit_group;" ::: "memory")
#define CP_WAIT0()  asm volatile("cp.async.wait_group 0;" ::: "memory")

__device__ __forceinline__ void cvt_split2h(float x, float y, uint32_t& h, uint32_t& l) {
    __half hx = __float2half(x);
    __half hy = __float2half(y);
    __half lx = __float2half(x - __half2float(hx));
    __half ly = __float2half(y - __half2float(hy));
    h = (uint32_t)__half_as_ushort(hx) | ((uint32_t)__half_as_ushort(hy) << 16);
    l = (uint32_t)__half_as_ushort(lx) | ((uint32_t)__half_as_ushort(ly) << 16);
}
__device__ __forceinline__ uint32_t cvt2h(float x, float y) {
    return (uint32_t)__half_as_ushort(__float2half(x)) |
           ((uint32_t)__half_as_ushort(__float2half(y)) << 16);
}

// ---------------------------------------------------------------------------
// Bias table
// ---------------------------------------------------------------------------
__global__ void bias_kernel(const float* __restrict__ rel_emb) {
    int i = blockIdx.x * blockDim.x + threadIdx.x;
    if (i >= NBIAS) return;
    int d  = i - (SEQ - 1);
    int rb = (d > 0) ? 16 : 0;
    int ad = d < 0 ? -d : d;
    int bucket;
    if (ad < 8) bucket = ad;
    else {
        float v  = logf((float)ad * 0.125f) / 2.7725887f;
        int   lg = 8 + (int)(v * 8.0f);
        bucket = lg < 15 ? lg : 15;
    }
    int idx = rb + bucket;
    #pragma unroll
    for (int h = 0; h < NH; h++)
        g_bias[h * NBP + i] = rel_emb[idx * NH + h];
}

// ---------------------------------------------------------------------------
// fp32 -> (hi,lo) fp16 split
// ---------------------------------------------------------------------------
__global__ void split_kernel(const float* __restrict__ in,
                             __half* __restrict__ hi,
                             __half* __restrict__ lo, int n4) {
    int i = blockIdx.x * blockDim.x + threadIdx.x;
    if (i >= n4) return;
    float4 a = ((const float4*)in)[i];
    uint32_t h01, l01, h23, l23;
    cvt_split2h(a.x, a.y, h01, l01);
    cvt_split2h(a.z, a.w, h23, l23);
    ((uint2*)hi)[i] = make_uint2(h01, h23);
    ((uint2*)lo)[i] = make_uint2(l01, l23);
}

// fp32 -> fp16 hi only
__global__ void cvt_kernel(const float* __restrict__ in,
                           __half* __restrict__ out, int n4) {
    int i = blockIdx.x * blockDim.x + threadIdx.x;
    if (i >= n4) return;
    float4 a = ((const float4*)in)[i];
    ((uint2*)out)[i] = make_uint2(cvt2h(a.x, a.y), cvt2h(a.z, a.w));
}

// ---------------------------------------------------------------------------
// Pipelined fp16 GEMM. USE3: C = AhBh + AlBh + AhBl (3-term), else 2-term.
// 128x128 tile, BK=32, 8 warps, cp.async double-buffered, 2 CTAs/SM.
// ---------------------------------------------------------------------------
#define SG_AH 0
#define SG_AL 10240
#define SG_BH 20480
#define SG_BL 29184
#define GEMM_SMEM3 (2*37888)   // 75776
#define GEMM_SMEM2 (2*29184)   // 58368

template<bool USE3>
__device__ __forceinline__ void gemm_issue(
    uint32_t base, const __half* Ah, const __half* Al,
    const __half* Bh, const __half* Bl,
    int k0, int K, int N, int tid)
{
    #pragma unroll
    for (int t = 0; t < 2; t++) {
        int i = tid + t * 256;
        int r = i >> 2, c = i & 3;                 // A: 128 rows x 4 chunks
        uint32_t off = r * 80 + c * 16;
        size_t so = (size_t)r * K + k0 + c * 8;
        CP16(base + SG_AH + off, Ah + so);
        CP16(base + SG_AL + off, Al + so);
    }
    #pragma unroll
    for (int t = 0; t < 2; t++) {
        int i = tid + t * 256;
        int r = i >> 4, c = i & 15;                // B: 32 rows x 16 chunks
        uint32_t off = r * 272 + c * 16;
        size_t so = (size_t)(k0 + r) * N + c * 8;
        CP16(base + SG_BH + off, Bh + so);
        if (USE3) CP16(base + SG_BL + off, Bl + so);
    }
}

template<bool USE3>
__global__ __launch_bounds__(256, 2) void gemm_fp16_kernel(
    const __half* __restrict__ Ah, const __half* __restrict__ Al,
    const __half* __restrict__ Bh, const __half* __restrict__ Bl,
    int K, int N, int nbase, float* __restrict__ Cf,
    __half* __restrict__ Ch, __half* __restrict__ Cl)
{
    constexpr int SSZ = USE3 ? 37888 : 29184;
    extern __shared__ __align__(16) uint8_t smem[];
    const uint32_t sb = smem_u32(smem);
    const int tid = threadIdx.x, wid = tid >> 5, lane = tid & 31;
    const int wm = wid & 3, wn = wid >> 2;
    const size_t m0 = (size_t)blockIdx.y * 128;
    const size_t n0 = (size_t)nbase + blockIdx.x * 128;

    const __half* Ahp = Ah + m0 * K;
    const __half* Alp = Al + m0 * K;
    const __half* Bhp = Bh + n0;
    const __half* Blp = USE3 ? (Bl + n0) : nullptr;

    float acc[2][8][4];
    #pragma unroll
    for (int i = 0; i < 2; i++)
        #pragma unroll
        for (int j = 0; j < 8; j++)
            #pragma unroll
            for (int r = 0; r < 4; r++) acc[i][j][r] = 0.f;

    const uint32_t a_fb = (wm * 32 + (lane & 15)) * 80 + (lane >> 4) * 16;
    const uint32_t b_fb = SG_BH + (lane & 15) * 272 + wn * 128 + (lane >> 4) * 16;

    gemm_issue<USE3>(sb, Ahp, Alp, Bhp, Blp, 0, K, N, tid);
    CP_COMMIT();

    const int niter = K >> 5;
    for (int it = 0; it < niter; it++) {
        CP_WAIT0();
        __syncthreads();
        if (it + 1 < niter) {
            gemm_issue<USE3>(sb + ((it + 1) & 1) * SSZ, Ahp, Alp, Bhp, Blp,
                             (it + 1) << 5, K, N, tid);
            CP_COMMIT();
        }
        const uint32_t st = sb + (it & 1) * SSZ;

        #pragma unroll
        for (int ks = 0; ks < 2; ks++) {
            uint32_t ah[2][4], al[2][4];
            #pragma unroll
            for (int i = 0; i < 2; i++) {
                uint32_t aa = st + a_fb + i * 16 * 80 + ks * 32;
                LDSM_X4(ah[i], aa + SG_AH);
                LDSM_X4(al[i], aa + SG_AL);
            }
            #pragma unroll
            for (int nh = 0; nh < 2; nh++) {
                #pragma unroll
                for (int j16 = 0; j16 < 2; j16++) {
                    uint32_t ba = st + b_fb + ks * 16 * 272 + nh * 64 + j16 * 32;
                    uint32_t bh[4];
                    LDSM_X4T(bh, ba);
                    int nf = nh * 4 + j16 * 2;
                    #pragma unroll
                    for (int i = 0; i < 2; i++) {
                        MMA16816(acc[i][nf],     ah[i], bh[0], bh[1]);
                        MMA16816(acc[i][nf + 1], ah[i], bh[2], bh[3]);
                        MMA16816(acc[i][nf],     al[i], bh[0], bh[1]);
                        MMA16816(acc[i][nf + 1], al[i], bh[2], bh[3]);
                    }
                    if (USE3) {
                        uint32_t bl[4];
                        LDSM_X4T(bl, ba + (SG_BL - SG_BH));
                        #pragma unroll
                        for (int i = 0; i < 2; i++) {
                            MMA16816(acc[i][nf],     ah[i], bl[0], bl[1]);
                            MMA16816(acc[i][nf + 1], ah[i], bl[2], bl[3]);
                        }
                    }
                }
            }
        }
    }

    const int row_in = lane >> 2, col_in = (lane & 3) * 2;
    if (Cf) {
        #pragma unroll
        for (int i = 0; i < 2; i++)
            #pragma unroll
            for (int nf = 0; nf < 8; nf++) {
                float* p = Cf + (m0 + wm * 32 + i * 16 + row_in) * N + n0 + wn * 64 + nf * 8 + col_in;
                *(float2*)p                   = make_float2(acc[i][nf][0], acc[i][nf][1]);
                *(float2*)(p + 8 * (size_t)N) = make_float2(acc[i][nf][2], acc[i][nf][3]);
            }
    } else {
        #pragma unroll
        for (int i = 0; i < 2; i++)
            #pragma unroll
            for (int nf = 0; nf < 8; nf++) {
                size_t o = (m0 + wm * 32 + i * 16 + row_in) * N + n0 + wn * 64 + nf * 8 + col_in;
                uint32_t h01, l01, h23, l23;
                cvt_split2h(acc[i][nf][0], acc[i][nf][1], h01, l01);
                cvt_split2h(acc[i][nf][2], acc[i][nf][3], h23, l23);
                *(uint32_t*)(Ch + o) = h01;
                *(uint32_t*)(Ch + o + 8 * (size_t)N) = h23;
                if (Cl) {
                    *(uint32_t*)(Cl + o) = l01;
                    *(uint32_t*)(Cl + o + 8 * (size_t)N) = l23;
                }
            }
    }
}

// ---------------------------------------------------------------------------
// fp16 HMMA flash attention: QK 3-term (Qh/Ql x Kh + Qh x Kl), PV 1-term.
// Block: 128 q-rows of one (b,h), 8 warps, cp.async double-buffered K/V+bias.
// ---------------------------------------------------------------------------
#define KV_KH 0
#define KV_KL 9216
#define KV_VH 18432
#define KV_BIAS 27648
#define KV_STG 28672
#define AQ_H (2*KV_STG)             // 57344
#define AQ_L (AQ_H + 18432)
#define ATTN_SMEM (AQ_L + 18432)    // 94208

__device__ __forceinline__ void attn_issue(
    uint32_t base, const __half* kh, const __half* kl, const __half* vh,
    const float* biasrc, int tid)
{
    #pragma unroll
    for (int t = 0; t < 2; t++) {
        int i = tid + t * 256;
        int r = i >> 3, c = i & 7;                 // 64 rows x 8 chunks
        uint32_t off = r * 144 + c * 16;
        size_t so = (size_t)r * E3 + c * 8;
        CP16(base + KV_KH + off, kh + so);
        CP16(base + KV_KL + off, kl + so);
        CP16(base + KV_VH + off, vh + so);
    }
    if (tid < 48) CP16(base + KV_BIAS + tid * 16, biasrc + tid * 4);
}

__global__ __launch_bounds__(256, 2) void attn_mma_kernel() {
    extern __shared__ __align__(16) uint8_t sm8[];
    const uint32_t sb = smem_u32(sm8);
    const int tid = threadIdx.x, wid = tid >> 5, lane = tid & 31;
    const int q0 = blockIdx.x * 128;
    const int b = blockIdx.y >> 4, h = blockIdx.y & 15;
    const size_t rowbase = (size_t)b * SEQ;
    const float* bias_h = g_bias + h * NBP;

    // ---- stage Q hi/lo (plain copies) ----
    const __half* Qh = g_qkv_h + (rowbase + q0) * E3 + h * HD;
    const __half* Ql = g_qkv_l + (rowbase + q0) * E3 + h * HD;
    #pragma unroll
    for (int t = 0; t < 4; t++) {
        int i = tid + t * 256;
        int r = i >> 3, c = i & 7;
        uint32_t off = r * 144 + c * 16;
        size_t so = (size_t)r * E3 + c * 8;
        *(uint4*)(sm8 + AQ_H + off) = *(const uint4*)(Qh + so);
        *(uint4*)(sm8 + AQ_L + off) = *(const uint4*)(Ql + so);
    }

    // ---- prologue: issue kv tile 0 ----
    const __half* Kh0 = g_qkv_h + rowbase * E3 + EMB + h * HD;
    const __half* Kl0 = g_qkv_l + rowbase * E3 + EMB + h * HD;
    attn_issue(sb, Kh0, Kl0, Kh0 + EMB, bias_h - q0 + 1920, tid);
    CP_COMMIT();

    __syncthreads();
    // ---- hoist Q fragments ----
    uint32_t qh[4][4], ql[4][4];
    {
        uint32_t qa = sb + (wid * 16 + (lane & 15)) * 144 + (lane >> 4) * 16;
        #pragma unroll
        for (int ks = 0; ks < 4; ks++) {
            LDSM_X4(qh[ks], qa + AQ_H + ks * 32);
            LDSM_X4(ql[ks], qa + AQ_L + ks * 32);
        }
    }

    float m0 = -INFINITY, m1 = -INFINITY, l0 = 0.f, l1 = 0.f;
    float o[8][4];
    #pragma unroll
    for (int j = 0; j < 8; j++)
        #pragma unroll
        for (int r = 0; r < 4; r++) o[j][r] = 0.f;

    const uint32_t kv_fb = (lane & 15) * 144 + (lane >> 4) * 16;
    const int ccol = (lane & 3) * 2;
    const int r0 = wid * 16 + (lane >> 2);
    const int r1 = r0 + 8;

    for (int kt = 0; kt < SEQ / 64; kt++) {
        CP_WAIT0();
        __syncthreads();
        if (kt + 1 < SEQ / 64) {
            const __half* Khn = g_qkv_h + (rowbase + (kt + 1) * 64) * E3 + EMB + h * HD;
            const __half* Kln = g_qkv_l + (rowbase + (kt + 1) * 64) * E3 + EMB + h * HD;
            attn_issue(sb + ((kt + 1) & 1) * KV_STG, Khn, Kln, Khn + EMB,
                       bias_h + (kt + 1) * 64 - q0 + 1920, tid);
            CP_COMMIT();
        }
        const uint32_t st = sb + (kt & 1) * KV_STG;
        const float* sbias = (const float*)(sm8 + (kt & 1) * KV_STG + KV_BIAS);

        // ---- S = Q @ K^T (3-term) ----
        float s[8][4];
        #pragma unroll
        for (int j = 0; j < 8; j++)
            #pragma unroll
            for (int r = 0; r < 4; r++) s[j][r] = 0.f;

        #pragma unroll
        for (int ks = 0; ks < 4; ks++) {
            #pragma unroll
            for (int nb = 0; nb < 4; nb++) {
                uint32_t kh[4], kl[4];
                uint32_t ka = st + kv_fb + nb * 16 * 144 + ks * 32;
                LDSM_X4(kh, ka + KV_KH);
                LDSM_X4(kl, ka + KV_KL);
                MMA16816(s[2*nb],   qh[ks], kh[0], kh[2]);
                MMA16816(s[2*nb+1], qh[ks], kh[1], kh[3]);
                MMA16816(s[2*nb],   ql[ks], kh[0], kh[2]);
                MMA16816(s[2*nb+1], ql[ks], kh[1], kh[3]);
                MMA16816(s[2*nb],   qh[ks], kl[0], kl[2]);
                MMA16816(s[2*nb+1], qh[ks], kl[1], kl[3]);
            }
        }

        // ---- bias + online softmax ----
        float mx0 = -INFINITY, mx1 = -INFINITY;
        #pragma unroll
        for (int j = 0; j < 8; j++) {
            int c = j * 8 + ccol;
            s[j][0] += sbias[c - r0 + 127];
            s[j][1] += sbias[c + 1 - r0 + 127];
            s[j][2] += sbias[c - r1 + 127];
            s[j][3] += sbias[c + 1 - r1 + 127];
            mx0 = fmaxf(mx0, fmaxf(s[j][0], s[j][1]));
            mx1 = fmaxf(mx1, fmaxf(s[j][2], s[j][3]));
        }
        mx0 = fmaxf(mx0, __shfl_xor_sync(0xffffffffu, mx0, 1));
        mx0 = fmaxf(mx0, __shfl_xor_sync(0xffffffffu, mx0, 2));
        mx1 = fmaxf(mx1, __shfl_xor_sync(0xffffffffu, mx1, 1));
        mx1 = fmaxf(mx1, __shfl_xor_sync(0xffffffffu, mx1, 2));
        float m0n = fmaxf(m0, mx0), m1n = fmaxf(m1, mx1);
        float c0 = exp2f((m0 - m0n) * L2E), c1 = exp2f((m1 - m1n) * L2E);
        float rs0 = 0.f, rs1 = 0.f;
        #pragma unroll
        for (int j = 0; j < 8; j++) {
            s[j][0] = exp2f((s[j][0] - m0n) * L2E);
            s[j][1] = exp2f((s[j][1] - m0n) * L2E);
            s[j][2] = exp2f((s[j][2] - m1n) * L2E);
            s[j][3] = exp2f((s[j][3] - m1n) * L2E);
            rs0 += s[j][0] + s[j][1];
            rs1 += s[j][2] + s[j][3];
        }
        rs0 += __shfl_xor_sync(0xffffffffu, rs0, 1);
        rs0 += __shfl_xor_sync(0xffffffffu, rs0, 2);
        rs1 += __shfl_xor_sync(0xffffffffu, rs1, 1);
        rs1 += __shfl_xor_sync(0xffffffffu, rs1, 2);
        l0 = l0 * c0 + rs0; l1 = l1 * c1 + rs1;
        m0 = m0n; m1 = m1n;
        #pragma unroll
        for (int j = 0; j < 8; j++) {
            o[j][0] *= c0; o[j][1] *= c0; o[j][2] *= c1; o[j][3] *= c1;
        }

        // ---- O += P @ V (1-term, P hi only) ----
        #pragma unroll
        for (int t = 0; t < 4; t++) {
            uint32_t ap[4];
            ap[0] = cvt2h(s[2*t][0],   s[2*t][1]);
            ap[1] = cvt2h(s[2*t][2],   s[2*t][3]);
            ap[2] = cvt2h(s[2*t+1][0], s[2*t+1][1]);
            ap[3] = cvt2h(s[2*t+1][2], s[2*t+1][3]);
            #pragma unroll
            for (int g = 0; g < 4; g++) {
                uint32_t vh[4];
                LDSM_X4T(vh, st + kv_fb + t * 16 * 144 + g * 32 + KV_VH);
                MMA16816(o[2*g],   ap, vh[0], vh[1]);
                MMA16816(o[2*g+1], ap, vh[2], vh[3]);
            }
        }
    }

    // ---- epilogue: split fp16 out ----
    float inv0 = 1.f / l0, inv1 = 1.f / l1;
    size_t ob = (rowbase + q0 + r0) * EMB + h * HD + ccol;
    #pragma unroll
    for (int j = 0; j < 8; j++) {
        uint32_t h01, l01, h23, l23;
        cvt_split2h(o[j][0] * inv0, o[j][1] * inv0, h01, l01);
        cvt_split2h(o[j][2] * inv1, o[j][3] * inv1, h23, l23);
        *(uint32_t*)(g_attn_h + ob + j * 8) = h01;
        *(uint32_t*)(g_attn_l + ob + j * 8) = l01;
        *(uint32_t*)(g_attn_h + ob + 8 * EMB + j * 8) = h23;
        *(uint32_t*)(g_attn_l + ob + 8 * EMB + j * 8) = l23;
    }
}

// ---------------------------------------------------------------------------
extern "C" void kernel_launch(void* const* d_in, const int* in_sizes, int n_in,
                              void* d_out, int out_size) {
    const float* hidden = (const float*)d_in[0];   // [4096, 1024]
    const float* W_qkv  = (const float*)d_in[1];   // [1024, 3072]
    const float* W_out  = (const float*)d_in[2];   // [1024, 1024]
    const float* rel    = (const float*)d_in[3];   // [32, 16]
    float* out = (float*)d_out;                    // [4096, 1024]

    __half *ah, *al, *wqh, *wql, *woh, *qh, *ql, *ath, *atl;
    cudaGetSymbolAddress((void**)&ah,  g_ah);
    cudaGetSymbolAddress((void**)&al,  g_al);
    cudaGetSymbolAddress((void**)&wqh, g_wqh);
    cudaGetSymbolAddress((void**)&wql, g_wql);
    cudaGetSymbolAddress((void**)&woh, g_woh);
    cudaGetSymbolAddress((void**)&qh,  g_qkv_h);
    cudaGetSymbolAddress((void**)&ql,  g_qkv_l);
    cudaGetSymbolAddress((void**)&ath, g_attn_h);
    cudaGetSymbolAddress((void**)&atl, g_attn_l);

    cudaFuncSetAttribute(gemm_fp16_kernel<true>,
                         cudaFuncAttributeMaxDynamicSharedMemorySize, GEMM_SMEM3);
    cudaFuncSetAttribute(gemm_fp16_kernel<false>,
                         cudaFuncAttributeMaxDynamicSharedMemorySize, GEMM_SMEM2);
    cudaFuncSetAttribute(attn_mma_kernel,
                         cudaFuncAttributeMaxDynamicSharedMemorySize, ATTN_SMEM);

    bias_kernel<<<(NBIAS + 255) / 256, 256>>>(rel);
    split_kernel<<<NROWS * EMB / 4 / 256, 256>>>(hidden, ah, al, NROWS * EMB / 4);
    split_kernel<<<EMB * E3 / 4 / 256, 256>>>(W_qkv, wqh, wql, EMB * E3 / 4);
    cvt_kernel<<<EMB * EMB / 4 / 256, 256>>>(W_out, woh, EMB * EMB / 4);

    // QKV projection, Q+K columns (n < 2048): 3-term, store hi+lo
    gemm_fp16_kernel<true><<<dim3(16, NROWS / 128), 256, GEMM_SMEM3>>>(
        ah, al, wqh, wql, EMB, E3, 0, nullptr, qh, ql);
    // QKV projection, V columns (n >= 2048): 2-term, store hi only
    gemm_fp16_kernel<false><<<dim3(8, NROWS / 128), 256, GEMM_SMEM2>>>(
        ah, al, wqh, nullptr, EMB, E3, 2048, nullptr, qh, nullptr);

    // attention
    attn_mma_kernel<<<dim3(SEQ / 128, BATCH * NH), 256, ATTN_SMEM>>>();

    // output projection: 2-term -> fp32
    gemm_fp16_kernel<false><<<dim3(8, NROWS / 128), 256, GEMM_SMEM2>>>(
        ath, atl, woh, nullptr, EMB, EMB, 0, out, nullptr, nullptr);
}

// round 13
// speedup vs baseline: 3.5330x; 1.0492x over previous
#include <cuda_runtime.h>
#include <cuda_fp16.h>
#include <math.h>
#include <cstdint>

#define SEQ   2048
#define BATCH 2
#define NH    16
#define HD    64
#define EMB   1024
#define E3    3072
#define NROWS (BATCH*SEQ)          // 4096
#define NBIAS (2*SEQ-1)            // 4095
#define NBP   4096
#define L2E   1.4426950408889634f

// ---------------- scratch (__device__ globals) ------------------------------
__device__ __half g_ah[(size_t)NROWS * EMB];    // hidden split hi
__device__ __half g_al[(size_t)NROWS * EMB];    // hidden split lo
__device__ __half g_wqh[(size_t)EMB * E3];      // W_qkv hi
__device__ __half g_wql[(size_t)EMB * E3];      // W_qkv lo (used for Q,K cols)
__device__ __half g_woh[(size_t)EMB * EMB];     // W_out hi only
__device__ __half g_qkv_h[(size_t)NROWS * E3];  // QKV result hi
__device__ __half g_qkv_l[(size_t)NROWS * E3];  // QKV result lo (Q,K cols)
__device__ __half g_attn_h[(size_t)NROWS * EMB];
__device__ float g_bias[NH * NBP];

// ---------------- PTX helpers ----------------------------------------------
__device__ __forceinline__ uint32_t smem_u32(const void* p) {
    uint32_t a;
    asm("{ .reg .u64 t; cvta.to.shared.u64 t, %1; cvt.u32.u64 %0, t; }" : "=r"(a) : "l"(p));
    return a;
}
#define LDSM_X4(r, a) \
    asm volatile("ldmatrix.sync.aligned.m8n8.x4.shared.b16 {%0,%1,%2,%3}, [%4];" \
        : "=r"((r)[0]), "=r"((r)[1]), "=r"((r)[2]), "=r"((r)[3]) : "r"(a))
#define LDSM_X4T(r, a) \
    asm volatile("ldmatrix.sync.aligned.m8n8.x4.trans.shared.b16 {%0,%1,%2,%3}, [%4];" \
        : "=r"((r)[0]), "=r"((r)[1]), "=r"((r)[2]), "=r"((r)[3]) : "r"(a))
#define MMA16816(d, a, b0, b1) \
    asm volatile("mma.sync.aligned.m16n8k16.row.col.f32.f16.f16.f32 " \
        "{%0,%1,%2,%3}, {%4,%5,%6,%7}, {%8,%9}, {%0,%1,%2,%3};" \
        : "+f"((d)[0]), "+f"((d)[1]), "+f"((d)[2]), "+f"((d)[3]) \
        : "r"((a)[0]), "r"((a)[1]), "r"((a)[2]), "r"((a)[3]), "r"(b0), "r"(b1))
#define CP16(d, s) asm volatile("cp.async.cg.shared.global [%0], [%1], 16;" :: "r"(d), "l"(s))
#define CP_COMMIT() asm volatile("cp.async.commit_group;" ::: "memory")
#define CP_WAIT0()  asm volatile("cp.async.wait_group 0;" ::: "memory")

__device__ __forceinline__ void cvt_split2h(float x, float y, uint32_t& h, uint32_t& l) {
    __half hx = __float2half(x);
    __half hy = __float2half(y);
    __half lx = __float2half(x - __half2float(hx));
    __half ly = __float2half(y - __half2float(hy));
    h = (uint32_t)__half_as_ushort(hx) | ((uint32_t)__half_as_ushort(hy) << 16);
    l = (uint32_t)__half_as_ushort(lx) | ((uint32_t)__half_as_ushort(ly) << 16);
}
__device__ __forceinline__ uint32_t cvt2h(float x, float y) {
    return (uint32_t)__half_as_ushort(__float2half(x)) |
           ((uint32_t)__half_as_ushort(__float2half(y)) << 16);
}

// ---------------------------------------------------------------------------
// Bias table
// ---------------------------------------------------------------------------
__global__ void bias_kernel(const float* __restrict__ rel_emb) {
    int i = blockIdx.x * blockDim.x + threadIdx.x;
    if (i >= NBIAS) return;
    int d  = i - (SEQ - 1);
    int rb = (d > 0) ? 16 : 0;
    int ad = d < 0 ? -d : d;
    int bucket;
    if (ad < 8) bucket = ad;
    else {
        float v  = logf((float)ad * 0.125f) / 2.7725887f;
        int   lg = 8 + (int)(v * 8.0f);
        bucket = lg < 15 ? lg : 15;
    }
    int idx = rb + bucket;
    #pragma unroll
    for (int h = 0; h < NH; h++)
        g_bias[h * NBP + i] = rel_emb[idx * NH + h];
}

// ---------------------------------------------------------------------------
// fp32 -> (hi,lo) fp16 split
// ---------------------------------------------------------------------------
__global__ void split_kernel(const float* __restrict__ in,
                             __half* __restrict__ hi,
                             __half* __restrict__ lo, int n4) {
    int i = blockIdx.x * blockDim.x + threadIdx.x;
    if (i >= n4) return;
    float4 a = ((const float4*)in)[i];
    uint32_t h01, l01, h23, l23;
    cvt_split2h(a.x, a.y, h01, l01);
    cvt_split2h(a.z, a.w, h23, l23);
    ((uint2*)hi)[i] = make_uint2(h01, h23);
    ((uint2*)lo)[i] = make_uint2(l01, l23);
}

// fp32 -> fp16 hi only
__global__ void cvt_kernel(const float* __restrict__ in,
                           __half* __restrict__ out, int n4) {
    int i = blockIdx.x * blockDim.x + threadIdx.x;
    if (i >= n4) return;
    float4 a = ((const float4*)in)[i];
    ((uint2*)out)[i] = make_uint2(cvt2h(a.x, a.y), cvt2h(a.z, a.w));
}

// ---------------------------------------------------------------------------
// Pipelined fp16 GEMM, TERMS in {1,2,3}:
//   1: C = AhBh      2: + AlBh      3: + AhBl
// 128x128 tile, BK=32, 8 warps, cp.async double-buffered, 2 CTAs/SM.
// ---------------------------------------------------------------------------
#define GEMM_SMEM3 (2*37888)
#define GEMM_SMEM2 (2*29184)
#define GEMM_SMEM1 (2*18944)

template<int TERMS>
struct GLay {
    static constexpr uint32_t AH = 0;
    static constexpr uint32_t AL = 10240;                        // valid if TERMS>=2
    static constexpr uint32_t BH = (TERMS >= 2) ? 20480 : 10240;
    static constexpr uint32_t BL = BH + 8704;                    // valid if TERMS==3
    static constexpr uint32_t SSZ = BH + 8704u * (TERMS == 3 ? 2 : 1);
};

template<int TERMS>
__device__ __forceinline__ void gemm_issue(
    uint32_t base, const __half* Ah, const __half* Al,
    const __half* Bh, const __half* Bl,
    int k0, int K, int N, int tid)
{
    using L = GLay<TERMS>;
    #pragma unroll
    for (int t = 0; t < 2; t++) {
        int i = tid + t * 256;
        int r = i >> 2, c = i & 3;                 // A: 128 rows x 4 chunks
        uint32_t off = r * 80 + c * 16;
        size_t so = (size_t)r * K + k0 + c * 8;
        CP16(base + L::AH + off, Ah + so);
        if (TERMS >= 2) CP16(base + L::AL + off, Al + so);
    }
    #pragma unroll
    for (int t = 0; t < 2; t++) {
        int i = tid + t * 256;
        int r = i >> 4, c = i & 15;                // B: 32 rows x 16 chunks
        uint32_t off = r * 272 + c * 16;
        size_t so = (size_t)(k0 + r) * N + c * 8;
        CP16(base + L::BH + off, Bh + so);
        if (TERMS == 3) CP16(base + L::BL + off, Bl + so);
    }
}

template<int TERMS>
__global__ __launch_bounds__(256, 2) void gemm_fp16_kernel(
    const __half* __restrict__ Ah, const __half* __restrict__ Al,
    const __half* __restrict__ Bh, const __half* __restrict__ Bl,
    int K, int N, int nbase, float* __restrict__ Cf,
    __half* __restrict__ Ch, __half* __restrict__ Cl)
{
    using L = GLay<TERMS>;
    extern __shared__ __align__(16) uint8_t smem[];
    const uint32_t sb = smem_u32(smem);
    const int tid = threadIdx.x, wid = tid >> 5, lane = tid & 31;
    const int wm = wid & 3, wn = wid >> 2;
    const size_t m0 = (size_t)blockIdx.y * 128;
    const size_t n0 = (size_t)nbase + blockIdx.x * 128;

    const __half* Ahp = Ah + m0 * K;
    const __half* Alp = (TERMS >= 2) ? (Al + m0 * K) : nullptr;
    const __half* Bhp = Bh + n0;
    const __half* Blp = (TERMS == 3) ? (Bl + n0) : nullptr;

    float acc[2][8][4];
    #pragma unroll
    for (int i = 0; i < 2; i++)
        #pragma unroll
        for (int j = 0; j < 8; j++)
            #pragma unroll
            for (int r = 0; r < 4; r++) acc[i][j][r] = 0.f;

    const uint32_t a_fb = (wm * 32 + (lane & 15)) * 80 + (lane >> 4) * 16;
    const uint32_t b_fb = L::BH + (lane & 15) * 272 + wn * 128 + (lane >> 4) * 16;

    gemm_issue<TERMS>(sb, Ahp, Alp, Bhp, Blp, 0, K, N, tid);
    CP_COMMIT();

    const int niter = K >> 5;
    for (int it = 0; it < niter; it++) {
        CP_WAIT0();
        __syncthreads();
        if (it + 1 < niter) {
            gemm_issue<TERMS>(sb + ((it + 1) & 1) * L::SSZ, Ahp, Alp, Bhp, Blp,
                              (it + 1) << 5, K, N, tid);
            CP_COMMIT();
        }
        const uint32_t st = sb + (it & 1) * L::SSZ;

        #pragma unroll
        for (int ks = 0; ks < 2; ks++) {
            uint32_t ah[2][4], al[2][4];
            #pragma unroll
            for (int i = 0; i < 2; i++) {
                uint32_t aa = st + a_fb + i * 16 * 80 + ks * 32;
                LDSM_X4(ah[i], aa + L::AH);
                if (TERMS >= 2) LDSM_X4(al[i], aa + L::AL);
            }
            #pragma unroll
            for (int nh = 0; nh < 2; nh++) {
                #pragma unroll
                for (int j16 = 0; j16 < 2; j16++) {
                    uint32_t ba = st + b_fb + ks * 16 * 272 + nh * 64 + j16 * 32;
                    uint32_t bh[4];
                    LDSM_X4T(bh, ba);
                    int nf = nh * 4 + j16 * 2;
                    #pragma unroll
                    for (int i = 0; i < 2; i++) {
                        MMA16816(acc[i][nf],     ah[i], bh[0], bh[1]);
                        MMA16816(acc[i][nf + 1], ah[i], bh[2], bh[3]);
                        if (TERMS >= 2) {
                            MMA16816(acc[i][nf],     al[i], bh[0], bh[1]);
                            MMA16816(acc[i][nf + 1], al[i], bh[2], bh[3]);
                        }
                    }
                    if (TERMS == 3) {
                        uint32_t bl[4];
                        LDSM_X4T(bl, ba + (L::BL - L::BH));
                        #pragma unroll
                        for (int i = 0; i < 2; i++) {
                            MMA16816(acc[i][nf],     ah[i], bl[0], bl[1]);
                            MMA16816(acc[i][nf + 1], ah[i], bl[2], bl[3]);
                        }
                    }
                }
            }
        }
    }

    const int row_in = lane >> 2, col_in = (lane & 3) * 2;
    if (Cf) {
        #pragma unroll
        for (int i = 0; i < 2; i++)
            #pragma unroll
            for (int nf = 0; nf < 8; nf++) {
                float* p = Cf + (m0 + wm * 32 + i * 16 + row_in) * N + n0 + wn * 64 + nf * 8 + col_in;
                *(float2*)p                   = make_float2(acc[i][nf][0], acc[i][nf][1]);
                *(float2*)(p + 8 * (size_t)N) = make_float2(acc[i][nf][2], acc[i][nf][3]);
            }
    } else {
        #pragma unroll
        for (int i = 0; i < 2; i++)
            #pragma unroll
            for (int nf = 0; nf < 8; nf++) {
                size_t o = (m0 + wm * 32 + i * 16 + row_in) * N + n0 + wn * 64 + nf * 8 + col_in;
                uint32_t h01, l01, h23, l23;
                cvt_split2h(acc[i][nf][0], acc[i][nf][1], h01, l01);
                cvt_split2h(acc[i][nf][2], acc[i][nf][3], h23, l23);
                *(uint32_t*)(Ch + o) = h01;
                *(uint32_t*)(Ch + o + 8 * (size_t)N) = h23;
                if (Cl) {
                    *(uint32_t*)(Cl + o) = l01;
                    *(uint32_t*)(Cl + o + 8 * (size_t)N) = l23;
                }
            }
    }
}

// ---------------------------------------------------------------------------
// fp16 HMMA flash attention: QK 3-term (Qh/Ql x Kh + Qh x Kl), PV 1-term.
// Block: 128 q-rows of one (b,h), 8 warps, cp.async double-buffered K/V+bias.
// Epilogue: hi-only fp16 (out-proj is 1-term).
// ---------------------------------------------------------------------------
#define KV_KH 0
#define KV_KL 9216
#define KV_VH 18432
#define KV_BIAS 27648
#define KV_STG 28672
#define AQ_H (2*KV_STG)             // 57344
#define AQ_L (AQ_H + 18432)
#define ATTN_SMEM (AQ_L + 18432)    // 94208

__device__ __forceinline__ void attn_issue(
    uint32_t base, const __half* kh, const __half* kl, const __half* vh,
    const float* biasrc, int tid)
{
    #pragma unroll
    for (int t = 0; t < 2; t++) {
        int i = tid + t * 256;
        int r = i >> 3, c = i & 7;                 // 64 rows x 8 chunks
        uint32_t off = r * 144 + c * 16;
        size_t so = (size_t)r * E3 + c * 8;
        CP16(base + KV_KH + off, kh + so);
        CP16(base + KV_KL + off, kl + so);
        CP16(base + KV_VH + off, vh + so);
    }
    if (tid < 48) CP16(base + KV_BIAS + tid * 16, biasrc + tid * 4);
}

__global__ __launch_bounds__(256, 2) void attn_mma_kernel() {
    extern __shared__ __align__(16) uint8_t sm8[];
    const uint32_t sb = smem_u32(sm8);
    const int tid = threadIdx.x, wid = tid >> 5, lane = tid & 31;
    const int q0 = blockIdx.x * 128;
    const int b = blockIdx.y >> 4, h = blockIdx.y & 15;
    const size_t rowbase = (size_t)b * SEQ;
    const float* bias_h = g_bias + h * NBP;

    // ---- stage Q hi/lo (plain copies) ----
    const __half* Qh = g_qkv_h + (rowbase + q0) * E3 + h * HD;
    const __half* Ql = g_qkv_l + (rowbase + q0) * E3 + h * HD;
    #pragma unroll
    for (int t = 0; t < 4; t++) {
        int i = tid + t * 256;
        int r = i >> 3, c = i & 7;
        uint32_t off = r * 144 + c * 16;
        size_t so = (size_t)r * E3 + c * 8;
        *(uint4*)(sm8 + AQ_H + off) = *(const uint4*)(Qh + so);
        *(uint4*)(sm8 + AQ_L + off) = *(const uint4*)(Ql + so);
    }

    // ---- prologue: issue kv tile 0 ----
    const __half* Kh0 = g_qkv_h + rowbase * E3 + EMB + h * HD;
    const __half* Kl0 = g_qkv_l + rowbase * E3 + EMB + h * HD;
    attn_issue(sb, Kh0, Kl0, Kh0 + EMB, bias_h - q0 + 1920, tid);
    CP_COMMIT();

    __syncthreads();
    // ---- hoist Q fragments ----
    uint32_t qh[4][4], ql[4][4];
    {
        uint32_t qa = sb + (wid * 16 + (lane & 15)) * 144 + (lane >> 4) * 16;
        #pragma unroll
        for (int ks = 0; ks < 4; ks++) {
            LDSM_X4(qh[ks], qa + AQ_H + ks * 32);
            LDSM_X4(ql[ks], qa + AQ_L + ks * 32);
        }
    }

    float m0 = -INFINITY, m1 = -INFINITY, l0 = 0.f, l1 = 0.f;
    float o[8][4];
    #pragma unroll
    for (int j = 0; j < 8; j++)
        #pragma unroll
        for (int r = 0; r < 4; r++) o[j][r] = 0.f;

    const uint32_t kv_fb = (lane & 15) * 144 + (lane >> 4) * 16;
    const int ccol = (lane & 3) * 2;
    const int r0 = wid * 16 + (lane >> 2);
    const int r1 = r0 + 8;

    for (int kt = 0; kt < SEQ / 64; kt++) {
        CP_WAIT0();
        __syncthreads();
        if (kt + 1 < SEQ / 64) {
            const __half* Khn = g_qkv_h + (rowbase + (kt + 1) * 64) * E3 + EMB + h * HD;
            const __half* Kln = g_qkv_l + (rowbase + (kt + 1) * 64) * E3 + EMB + h * HD;
            attn_issue(sb + ((kt + 1) & 1) * KV_STG, Khn, Kln, Khn + EMB,
                       bias_h + (kt + 1) * 64 - q0 + 1920, tid);
            CP_COMMIT();
        }
        const uint32_t st = sb + (kt & 1) * KV_STG;
        const float* sbias = (const float*)(sm8 + (kt & 1) * KV_STG + KV_BIAS);

        // ---- S = Q @ K^T (3-term) ----
        float s[8][4];
        #pragma unroll
        for (int j = 0; j < 8; j++)
            #pragma unroll
            for (int r = 0; r < 4; r++) s[j][r] = 0.f;

        #pragma unroll
        for (int ks = 0; ks < 4; ks++) {
            #pragma unroll
            for (int nb = 0; nb < 4; nb++) {
                uint32_t kh[4], kl[4];
                uint32_t ka = st + kv_fb + nb * 16 * 144 + ks * 32;
                LDSM_X4(kh, ka + KV_KH);
                LDSM_X4(kl, ka + KV_KL);
                MMA16816(s[2*nb],   qh[ks], kh[0], kh[2]);
                MMA16816(s[2*nb+1], qh[ks], kh[1], kh[3]);
                MMA16816(s[2*nb],   ql[ks], kh[0], kh[2]);
                MMA16816(s[2*nb+1], ql[ks], kh[1], kh[3]);
                MMA16816(s[2*nb],   qh[ks], kl[0], kl[2]);
                MMA16816(s[2*nb+1], qh[ks], kl[1], kl[3]);
            }
        }

        // ---- bias + online softmax ----
        float mx0 = -INFINITY, mx1 = -INFINITY;
        #pragma unroll
        for (int j = 0; j < 8; j++) {
            int c = j * 8 + ccol;
            s[j][0] += sbias[c - r0 + 127];
            s[j][1] += sbias[c + 1 - r0 + 127];
            s[j][2] += sbias[c - r1 + 127];
            s[j][3] += sbias[c + 1 - r1 + 127];
            mx0 = fmaxf(mx0, fmaxf(s[j][0], s[j][1]));
            mx1 = fmaxf(mx1, fmaxf(s[j][2], s[j][3]));
        }
        mx0 = fmaxf(mx0, __shfl_xor_sync(0xffffffffu, mx0, 1));
        mx0 = fmaxf(mx0, __shfl_xor_sync(0xffffffffu, mx0, 2));
        mx1 = fmaxf(mx1, __shfl_xor_sync(0xffffffffu, mx1, 1));
        mx1 = fmaxf(mx1, __shfl_xor_sync(0xffffffffu, mx1, 2));
        float m0n = fmaxf(m0, mx0), m1n = fmaxf(m1, mx1);
        float c0 = exp2f((m0 - m0n) * L2E), c1 = exp2f((m1 - m1n) * L2E);
        float rs0 = 0.f, rs1 = 0.f;
        #pragma unroll
        for (int j = 0; j < 8; j++) {
            s[j][0] = exp2f((s[j][0] - m0n) * L2E);
            s[j][1] = exp2f((s[j][1] - m0n) * L2E);
            s[j][2] = exp2f((s[j][2] - m1n) * L2E);
            s[j][3] = exp2f((s[j][3] - m1n) * L2E);
            rs0 += s[j][0] + s[j][1];
            rs1 += s[j][2] + s[j][3];
        }
        rs0 += __shfl_xor_sync(0xffffffffu, rs0, 1);
        rs0 += __shfl_xor_sync(0xffffffffu, rs0, 2);
        rs1 += __shfl_xor_sync(0xffffffffu, rs1, 1);
        rs1 += __shfl_xor_sync(0xffffffffu, rs1, 2);
        l0 = l0 * c0 + rs0; l1 = l1 * c1 + rs1;
        m0 = m0n; m1 = m1n;
        #pragma unroll
        for (int j = 0; j < 8; j++) {
            o[j][0] *= c0; o[j][1] *= c0; o[j][2] *= c1; o[j][3] *= c1;
        }

        // ---- O += P @ V (1-term, P hi only) ----
        #pragma unroll
        for (int t = 0; t < 4; t++) {
            uint32_t ap[4];
            ap[0] = cvt2h(s[2*t][0],   s[2*t][1]);
            ap[1] = cvt2h(s[2*t][2],   s[2*t][3]);
            ap[2] = cvt2h(s[2*t+1][0], s[2*t+1][1]);
            ap[3] = cvt2h(s[2*t+1][2], s[2*t+1][3]);
            #pragma unroll
            for (int g = 0; g < 4; g++) {
                uint32_t vh[4];
                LDSM_X4T(vh, st + kv_fb + t * 16 * 144 + g * 32 + KV_VH);
                MMA16816(o[2*g],   ap, vh[0], vh[1]);
                MMA16816(o[2*g+1], ap, vh[2], vh[3]);
            }
        }
    }

    // ---- epilogue: hi-only fp16 out ----
    float inv0 = 1.f / l0, inv1 = 1.f / l1;
    size_t ob = (rowbase + q0 + r0) * EMB + h * HD + ccol;
    #pragma unroll
    for (int j = 0; j < 8; j++) {
        *(uint32_t*)(g_attn_h + ob + j * 8)           = cvt2h(o[j][0] * inv0, o[j][1] * inv0);
        *(uint32_t*)(g_attn_h + ob + 8 * EMB + j * 8) = cvt2h(o[j][2] * inv1, o[j][3] * inv1);
    }
}

// ---------------------------------------------------------------------------
extern "C" void kernel_launch(void* const* d_in, const int* in_sizes, int n_in,
                              void* d_out, int out_size) {
    const float* hidden = (const float*)d_in[0];   // [4096, 1024]
    const float* W_qkv  = (const float*)d_in[1];   // [1024, 3072]
    const float* W_out  = (const float*)d_in[2];   // [1024, 1024]
    const float* rel    = (const float*)d_in[3];   // [32, 16]
    float* out = (float*)d_out;                    // [4096, 1024]

    __half *ah, *al, *wqh, *wql, *woh, *qh, *ql, *ath;
    cudaGetSymbolAddress((void**)&ah,  g_ah);
    cudaGetSymbolAddress((void**)&al,  g_al);
    cudaGetSymbolAddress((void**)&wqh, g_wqh);
    cudaGetSymbolAddress((void**)&wql, g_wql);
    cudaGetSymbolAddress((void**)&woh, g_woh);
    cudaGetSymbolAddress((void**)&qh,  g_qkv_h);
    cudaGetSymbolAddress((void**)&ql,  g_qkv_l);
    cudaGetSymbolAddress((void**)&ath, g_attn_h);

    cudaFuncSetAttribute(gemm_fp16_kernel<3>,
                         cudaFuncAttributeMaxDynamicSharedMemorySize, GEMM_SMEM3);
    cudaFuncSetAttribute(gemm_fp16_kernel<2>,
                         cudaFuncAttributeMaxDynamicSharedMemorySize, GEMM_SMEM2);
    cudaFuncSetAttribute(gemm_fp16_kernel<1>,
                         cudaFuncAttributeMaxDynamicSharedMemorySize, GEMM_SMEM1);
    cudaFuncSetAttribute(attn_mma_kernel,
                         cudaFuncAttributeMaxDynamicSharedMemorySize, ATTN_SMEM);

    bias_kernel<<<(NBIAS + 255) / 256, 256>>>(rel);
    split_kernel<<<NROWS * EMB / 4 / 256, 256>>>(hidden, ah, al, NROWS * EMB / 4);
    split_kernel<<<EMB * E3 / 4 / 256, 256>>>(W_qkv, wqh, wql, EMB * E3 / 4);
    cvt_kernel<<<EMB * EMB / 4 / 256, 256>>>(W_out, woh, EMB * EMB / 4);

    // QKV projection, Q+K columns (n < 2048): 3-term, store hi+lo
    gemm_fp16_kernel<3><<<dim3(16, NROWS / 128), 256, GEMM_SMEM3>>>(
        ah, al, wqh, wql, EMB, E3, 0, nullptr, qh, ql);
    // QKV projection, V columns (n >= 2048): 2-term, store hi only
    gemm_fp16_kernel<2><<<dim3(8, NROWS / 128), 256, GEMM_SMEM2>>>(
        ah, al, wqh, nullptr, EMB, E3, 2048, nullptr, qh, nullptr);

    // attention
    attn_mma_kernel<<<dim3(SEQ / 128, BATCH * NH), 256, ATTN_SMEM>>>();

    // output projection: 1-term -> fp32
    gemm_fp16_kernel<1><<<dim3(8, NROWS / 128), 256, GEMM_SMEM1>>>(
        ath, nullptr, woh, nullptr, EMB, EMB, 0, out, nullptr, nullptr);
}

// round 14
// speedup vs baseline: 3.6345x; 1.0287x over previous
#include <cuda_runtime.h>
#include <cuda_fp16.h>
#include <math.h>
#include <cstdint>

#define SEQ   2048
#define BATCH 2
#define NH    16
#define HD    64
#define EMB   1024
#define E3    3072
#define NROWS (BATCH*SEQ)          // 4096
#define NBIAS (2*SEQ-1)            // 4095
#define NBP   4096
#define L2E   1.4426950408889634f

// ---------------- scratch (__device__ globals) ------------------------------
__device__ __half g_ah[(size_t)NROWS * EMB];    // hidden split hi
__device__ __half g_al[(size_t)NROWS * EMB];    // hidden split lo
__device__ __half g_wqh[(size_t)EMB * E3];      // W_qkv hi
__device__ __half g_wql[(size_t)EMB * E3];      // W_qkv lo (used for Q,K cols)
__device__ __half g_woh[(size_t)EMB * EMB];     // W_out hi only
__device__ __half g_qkv_h[(size_t)NROWS * E3];  // QKV result hi
__device__ __half g_qkv_l[(size_t)NROWS * E3];  // QKV result lo (Q,K cols)
__device__ __half g_attn_h[(size_t)NROWS * EMB];
__device__ float g_bias[NH * NBP];

// ---------------- PTX helpers ----------------------------------------------
__device__ __forceinline__ uint32_t smem_u32(const void* p) {
    uint32_t a;
    asm("{ .reg .u64 t; cvta.to.shared.u64 t, %1; cvt.u32.u64 %0, t; }" : "=r"(a) : "l"(p));
    return a;
}
#define LDSM_X4(r, a) \
    asm volatile("ldmatrix.sync.aligned.m8n8.x4.shared.b16 {%0,%1,%2,%3}, [%4];" \
        : "=r"((r)[0]), "=r"((r)[1]), "=r"((r)[2]), "=r"((r)[3]) : "r"(a))
#define LDSM_X4T(r, a) \
    asm volatile("ldmatrix.sync.aligned.m8n8.x4.trans.shared.b16 {%0,%1,%2,%3}, [%4];" \
        : "=r"((r)[0]), "=r"((r)[1]), "=r"((r)[2]), "=r"((r)[3]) : "r"(a))
#define MMA16816(d, a, b0, b1) \
    asm volatile("mma.sync.aligned.m16n8k16.row.col.f32.f16.f16.f32 " \
        "{%0,%1,%2,%3}, {%4,%5,%6,%7}, {%8,%9}, {%0,%1,%2,%3};" \
        : "+f"((d)[0]), "+f"((d)[1]), "+f"((d)[2]), "+f"((d)[3]) \
        : "r"((a)[0]), "r"((a)[1]), "r"((a)[2]), "r"((a)[3]), "r"(b0), "r"(b1))
#define CP16(d, s) asm volatile("cp.async.cg.shared.global [%0], [%1], 16;" :: "r"(d), "l"(s))
#define CP_COMMIT() asm volatile("cp.async.commit_group;" ::: "memory")
#define CP_WAIT0()  asm volatile("cp.async.wait_group 0;" ::: "memory")
#define CP_WAIT1()  asm volatile("cp.async.wait_group 1;" ::: "memory")

__device__ __forceinline__ void cvt_split2h(float x, float y, uint32_t& h, uint32_t& l) {
    __half hx = __float2half(x);
    __half hy = __float2half(y);
    __half lx = __float2half(x - __half2float(hx));
    __half ly = __float2half(y - __half2float(hy));
    h = (uint32_t)__half_as_ushort(hx) | ((uint32_t)__half_as_ushort(hy) << 16);
    l = (uint32_t)__half_as_ushort(lx) | ((uint32_t)__half_as_ushort(ly) << 16);
}
__device__ __forceinline__ uint32_t cvt2h(float x, float y) {
    return (uint32_t)__half_as_ushort(__float2half(x)) |
           ((uint32_t)__half_as_ushort(__float2half(y)) << 16);
}

// ---------------------------------------------------------------------------
// Bias table
// ---------------------------------------------------------------------------
__global__ void bias_kernel(const float* __restrict__ rel_emb) {
    int i = blockIdx.x * blockDim.x + threadIdx.x;
    if (i >= NBIAS) return;
    int d  = i - (SEQ - 1);
    int rb = (d > 0) ? 16 : 0;
    int ad = d < 0 ? -d : d;
    int bucket;
    if (ad < 8) bucket = ad;
    else {
        float v  = logf((float)ad * 0.125f) / 2.7725887f;
        int   lg = 8 + (int)(v * 8.0f);
        bucket = lg < 15 ? lg : 15;
    }
    int idx = rb + bucket;
    #pragma unroll
    for (int h = 0; h < NH; h++)
        g_bias[h * NBP + i] = rel_emb[idx * NH + h];
}

// ---------------------------------------------------------------------------
// Merged prepass: split hidden + W_qkv, convert W_out. One launch.
// ---------------------------------------------------------------------------
#define P1 (NROWS*EMB/4)       // 1048576 float4s
#define P2 (EMB*E3/4)          // 786432
#define P3 (EMB*EMB/4)         // 262144

__global__ void prep_kernel(const float* __restrict__ hidden,
                            const float* __restrict__ wq,
                            const float* __restrict__ wo) {
    int i = blockIdx.x * blockDim.x + threadIdx.x;
    if (i < P1) {
        float4 a = ((const float4*)hidden)[i];
        uint32_t h01, l01, h23, l23;
        cvt_split2h(a.x, a.y, h01, l01);
        cvt_split2h(a.z, a.w, h23, l23);
        ((uint2*)g_ah)[i] = make_uint2(h01, h23);
        ((uint2*)g_al)[i] = make_uint2(l01, l23);
    } else if (i < P1 + P2) {
        int j = i - P1;
        float4 a = ((const float4*)wq)[j];
        uint32_t h01, l01, h23, l23;
        cvt_split2h(a.x, a.y, h01, l01);
        cvt_split2h(a.z, a.w, h23, l23);
        ((uint2*)g_wqh)[j] = make_uint2(h01, h23);
        ((uint2*)g_wql)[j] = make_uint2(l01, l23);
    } else {
        int j = i - P1 - P2;
        float4 a = ((const float4*)wo)[j];
        ((uint2*)g_woh)[j] = make_uint2(cvt2h(a.x, a.y), cvt2h(a.z, a.w));
    }
}

// ---------------------------------------------------------------------------
// Pipelined fp16 GEMM body. TERMS in {1,2,3}:
//   1: C = AhBh      2: + AlBh      3: + AhBl
// STAGES in {2,3}. 128x128 tile, BK=32, 8 warps.
// ---------------------------------------------------------------------------
template<int TERMS>
struct GLay {
    static constexpr uint32_t AH = 0;
    static constexpr uint32_t AL = 10240;                        // valid if TERMS>=2
    static constexpr uint32_t BH = (TERMS >= 2) ? 20480 : 10240;
    static constexpr uint32_t BL = BH + 8704;                    // valid if TERMS==3
    static constexpr uint32_t SSZ = BH + 8704u * (TERMS == 3 ? 2 : 1);
};

#define QKV_SMEM 87552u   // max(2*37888, 3*29184)
#define OUT_SMEM 56832u   // 3*18944

template<int TERMS>
__device__ __forceinline__ void gemm_issue(
    uint32_t base, const __half* Ah, const __half* Al,
    const __half* Bh, const __half* Bl,
    int k0, int K, int N, int tid)
{
    using L = GLay<TERMS>;
    #pragma unroll
    for (int t = 0; t < 2; t++) {
        int i = tid + t * 256;
        int r = i >> 2, c = i & 3;                 // A: 128 rows x 4 chunks
        uint32_t off = r * 80 + c * 16;
        size_t so = (size_t)r * K + k0 + c * 8;
        CP16(base + L::AH + off, Ah + so);
        if (TERMS >= 2) CP16(base + L::AL + off, Al + so);
    }
    #pragma unroll
    for (int t = 0; t < 2; t++) {
        int i = tid + t * 256;
        int r = i >> 4, c = i & 15;                // B: 32 rows x 16 chunks
        uint32_t off = r * 272 + c * 16;
        size_t so = (size_t)(k0 + r) * N + c * 8;
        CP16(base + L::BH + off, Bh + so);
        if (TERMS == 3) CP16(base + L::BL + off, Bl + so);
    }
}

template<int TERMS, int STAGES>
__device__ __forceinline__ void gemm_body(
    const __half* __restrict__ Ah, const __half* __restrict__ Al,
    const __half* __restrict__ Bh, const __half* __restrict__ Bl,
    int K, int N, size_t n0, float* __restrict__ Cf,
    __half* __restrict__ Ch, __half* __restrict__ Cl)
{
    using L = GLay<TERMS>;
    extern __shared__ __align__(16) uint8_t smem[];
    const uint32_t sb = smem_u32(smem);
    const int tid = threadIdx.x, wid = tid >> 5, lane = tid & 31;
    const int wm = wid & 3, wn = wid >> 2;
    const size_t m0 = (size_t)blockIdx.y * 128;

    const __half* Ahp = Ah + m0 * K;
    const __half* Alp = (TERMS >= 2) ? (Al + m0 * K) : nullptr;
    const __half* Bhp = Bh + n0;
    const __half* Blp = (TERMS == 3) ? (Bl + n0) : nullptr;

    float acc[2][8][4];
    #pragma unroll
    for (int i = 0; i < 2; i++)
        #pragma unroll
        for (int j = 0; j < 8; j++)
            #pragma unroll
            for (int r = 0; r < 4; r++) acc[i][j][r] = 0.f;

    const uint32_t a_fb = (wm * 32 + (lane & 15)) * 80 + (lane >> 4) * 16;
    const uint32_t b_fb = L::BH + (lane & 15) * 272 + wn * 128 + (lane >> 4) * 16;

    const int niter = K >> 5;
    #pragma unroll
    for (int p = 0; p < STAGES - 1; p++) {
        gemm_issue<TERMS>(sb + p * L::SSZ, Ahp, Alp, Bhp, Blp, p << 5, K, N, tid);
        CP_COMMIT();
    }

    for (int it = 0; it < niter; it++) {
        if (STAGES == 3 && it + 2 <= niter) CP_WAIT1(); else CP_WAIT0();
        __syncthreads();
        if (it + STAGES - 1 < niter) {
            gemm_issue<TERMS>(sb + ((it + STAGES - 1) % STAGES) * L::SSZ,
                              Ahp, Alp, Bhp, Blp, (it + STAGES - 1) << 5, K, N, tid);
            CP_COMMIT();
        }
        const uint32_t st = sb + (it % STAGES) * L::SSZ;

        #pragma unroll
        for (int ks = 0; ks < 2; ks++) {
            uint32_t ah[2][4], al[2][4];
            #pragma unroll
            for (int i = 0; i < 2; i++) {
                uint32_t aa = st + a_fb + i * 16 * 80 + ks * 32;
                LDSM_X4(ah[i], aa + L::AH);
                if (TERMS >= 2) LDSM_X4(al[i], aa + L::AL);
            }
            #pragma unroll
            for (int nh = 0; nh < 2; nh++) {
                #pragma unroll
                for (int j16 = 0; j16 < 2; j16++) {
                    uint32_t ba = st + b_fb + ks * 16 * 272 + nh * 64 + j16 * 32;
                    uint32_t bh[4];
                    LDSM_X4T(bh, ba);
                    int nf = nh * 4 + j16 * 2;
                    #pragma unroll
                    for (int i = 0; i < 2; i++) {
                        MMA16816(acc[i][nf],     ah[i], bh[0], bh[1]);
                        MMA16816(acc[i][nf + 1], ah[i], bh[2], bh[3]);
                        if (TERMS >= 2) {
                            MMA16816(acc[i][nf],     al[i], bh[0], bh[1]);
                            MMA16816(acc[i][nf + 1], al[i], bh[2], bh[3]);
                        }
                    }
                    if (TERMS == 3) {
                        uint32_t bl[4];
                        LDSM_X4T(bl, ba + (L::BL - L::BH));
                        #pragma unroll
                        for (int i = 0; i < 2; i++) {
                            MMA16816(acc[i][nf],     ah[i], bl[0], bl[1]);
                            MMA16816(acc[i][nf + 1], ah[i], bl[2], bl[3]);
                        }
                    }
                }
            }
        }
    }

    const int row_in = lane >> 2, col_in = (lane & 3) * 2;
    if (Cf) {
        #pragma unroll
        for (int i = 0; i < 2; i++)
            #pragma unroll
            for (int nf = 0; nf < 8; nf++) {
                float* p = Cf + (m0 + wm * 32 + i * 16 + row_in) * N + n0 + wn * 64 + nf * 8 + col_in;
                *(float2*)p                   = make_float2(acc[i][nf][0], acc[i][nf][1]);
                *(float2*)(p + 8 * (size_t)N) = make_float2(acc[i][nf][2], acc[i][nf][3]);
            }
    } else {
        #pragma unroll
        for (int i = 0; i < 2; i++)
            #pragma unroll
            for (int nf = 0; nf < 8; nf++) {
                size_t o = (m0 + wm * 32 + i * 16 + row_in) * N + n0 + wn * 64 + nf * 8 + col_in;
                uint32_t h01, l01, h23, l23;
                cvt_split2h(acc[i][nf][0], acc[i][nf][1], h01, l01);
                cvt_split2h(acc[i][nf][2], acc[i][nf][3], h23, l23);
                *(uint32_t*)(Ch + o) = h01;
                *(uint32_t*)(Ch + o + 8 * (size_t)N) = h23;
                if (Cl) {
                    *(uint32_t*)(Cl + o) = l01;
                    *(uint32_t*)(Cl + o + 8 * (size_t)N) = l23;
                }
            }
    }
}

// Merged QKV: blockIdx.x<16 -> Q,K cols 3-term depth-2; else V cols 2-term depth-3.
__global__ __launch_bounds__(256, 2) void qkv_kernel(
    const __half* __restrict__ Ah, const __half* __restrict__ Al,
    const __half* __restrict__ Bh, const __half* __restrict__ Bl,
    __half* __restrict__ Ch, __half* __restrict__ Cl)
{
    size_t n0 = (size_t)blockIdx.x * 128;
    if (blockIdx.x < 16)
        gemm_body<3, 2>(Ah, Al, Bh, Bl, EMB, E3, n0, nullptr, Ch, Cl);
    else
        gemm_body<2, 3>(Ah, Al, Bh, nullptr, EMB, E3, n0, nullptr, Ch, nullptr);
}

// Out-projection: 1-term depth-3 -> fp32.
__global__ __launch_bounds__(256, 2) void outproj_kernel(
    const __half* __restrict__ Ah, const __half* __restrict__ Bh,
    float* __restrict__ Cf)
{
    gemm_body<1, 3>(Ah, nullptr, Bh, nullptr, EMB, EMB,
                    (size_t)blockIdx.x * 128, Cf, nullptr, nullptr);
}

// ---------------------------------------------------------------------------
// fp16 HMMA flash attention: QK 3-term (Qh/Ql x Kh + Qh x Kl), PV 1-term.
// Block: 128 q-rows of one (b,h), 8 warps, cp.async double-buffered K/V+bias.
// ---------------------------------------------------------------------------
#define KV_KH 0
#define KV_KL 9216
#define KV_VH 18432
#define KV_BIAS 27648
#define KV_STG 28672
#define AQ_H (2*KV_STG)             // 57344
#define AQ_L (AQ_H + 18432)
#define ATTN_SMEM (AQ_L + 18432)    // 94208

__device__ __forceinline__ void attn_issue(
    uint32_t base, const __half* kh, const __half* kl, const __half* vh,
    const float* biasrc, int tid)
{
    #pragma unroll
    for (int t = 0; t < 2; t++) {
        int i = tid + t * 256;
        int r = i >> 3, c = i & 7;                 // 64 rows x 8 chunks
        uint32_t off = r * 144 + c * 16;
        size_t so = (size_t)r * E3 + c * 8;
        CP16(base + KV_KH + off, kh + so);
        CP16(base + KV_KL + off, kl + so);
        CP16(base + KV_VH + off, vh + so);
    }
    if (tid < 48) CP16(base + KV_BIAS + tid * 16, biasrc + tid * 4);
}

__global__ __launch_bounds__(256, 2) void attn_mma_kernel() {
    extern __shared__ __align__(16) uint8_t sm8[];
    const uint32_t sb = smem_u32(sm8);
    const int tid = threadIdx.x, wid = tid >> 5, lane = tid & 31;
    const int q0 = blockIdx.x * 128;
    const int b = blockIdx.y >> 4, h = blockIdx.y & 15;
    const size_t rowbase = (size_t)b * SEQ;
    const float* bias_h = g_bias + h * NBP;

    // ---- stage Q hi/lo (plain copies) ----
    const __half* Qh = g_qkv_h + (rowbase + q0) * E3 + h * HD;
    const __half* Ql = g_qkv_l + (rowbase + q0) * E3 + h * HD;
    #pragma unroll
    for (int t = 0; t < 4; t++) {
        int i = tid + t * 256;
        int r = i >> 3, c = i & 7;
        uint32_t off = r * 144 + c * 16;
        size_t so = (size_t)r * E3 + c * 8;
        *(uint4*)(sm8 + AQ_H + off) = *(const uint4*)(Qh + so);
        *(uint4*)(sm8 + AQ_L + off) = *(const uint4*)(Ql + so);
    }

    // ---- prologue: issue kv tile 0 ----
    const __half* Kh0 = g_qkv_h + rowbase * E3 + EMB + h * HD;
    const __half* Kl0 = g_qkv_l + rowbase * E3 + EMB + h * HD;
    attn_issue(sb, Kh0, Kl0, Kh0 + EMB, bias_h - q0 + 1920, tid);
    CP_COMMIT();

    __syncthreads();
    // ---- hoist Q fragments ----
    uint32_t qh[4][4], ql[4][4];
    {
        uint32_t qa = sb + (wid * 16 + (lane & 15)) * 144 + (lane >> 4) * 16;
        #pragma unroll
        for (int ks = 0; ks < 4; ks++) {
            LDSM_X4(qh[ks], qa + AQ_H + ks * 32);
            LDSM_X4(ql[ks], qa + AQ_L + ks * 32);
        }
    }

    float m0 = -INFINITY, m1 = -INFINITY, l0 = 0.f, l1 = 0.f;
    float o[8][4];
    #pragma unroll
    for (int j = 0; j < 8; j++)
        #pragma unroll
        for (int r = 0; r < 4; r++) o[j][r] = 0.f;

    const uint32_t kv_fb = (lane & 15) * 144 + (lane >> 4) * 16;
    const int ccol = (lane & 3) * 2;
    const int r0 = wid * 16 + (lane >> 2);
    const int r1 = r0 + 8;

    for (int kt = 0; kt < SEQ / 64; kt++) {
        CP_WAIT0();
        __syncthreads();
        if (kt + 1 < SEQ / 64) {
            const __half* Khn = g_qkv_h + (rowbase + (kt + 1) * 64) * E3 + EMB + h * HD;
            const __half* Kln = g_qkv_l + (rowbase + (kt + 1) * 64) * E3 + EMB + h * HD;
            attn_issue(sb + ((kt + 1) & 1) * KV_STG, Khn, Kln, Khn + EMB,
                       bias_h + (kt + 1) * 64 - q0 + 1920, tid);
            CP_COMMIT();
        }
        const uint32_t st = sb + (kt & 1) * KV_STG;
        const float* sbias = (const float*)(sm8 + (kt & 1) * KV_STG + KV_BIAS);

        // ---- S = Q @ K^T (3-term) ----
        float s[8][4];
        #pragma unroll
        for (int j = 0; j < 8; j++)
            #pragma unroll
            for (int r = 0; r < 4; r++) s[j][r] = 0.f;

        #pragma unroll
        for (int ks = 0; ks < 4; ks++) {
            #pragma unroll
            for (int nb = 0; nb < 4; nb++) {
                uint32_t kh[4], kl[4];
                uint32_t ka = st + kv_fb + nb * 16 * 144 + ks * 32;
                LDSM_X4(kh, ka + KV_KH);
                LDSM_X4(kl, ka + KV_KL);
                MMA16816(s[2*nb],   qh[ks], kh[0], kh[2]);
                MMA16816(s[2*nb+1], qh[ks], kh[1], kh[3]);
                MMA16816(s[2*nb],   ql[ks], kh[0], kh[2]);
                MMA16816(s[2*nb+1], ql[ks], kh[1], kh[3]);
                MMA16816(s[2*nb],   qh[ks], kl[0], kl[2]);
                MMA16816(s[2*nb+1], qh[ks], kl[1], kl[3]);
            }
        }

        // ---- bias + online softmax ----
        float mx0 = -INFINITY, mx1 = -INFINITY;
        #pragma unroll
        for (int j = 0; j < 8; j++) {
            int c = j * 8 + ccol;
            s[j][0] += sbias[c - r0 + 127];
            s[j][1] += sbias[c + 1 - r0 + 127];
            s[j][2] += sbias[c - r1 + 127];
            s[j][3] += sbias[c + 1 - r1 + 127];
            mx0 = fmaxf(mx0, fmaxf(s[j][0], s[j][1]));
            mx1 = fmaxf(mx1, fmaxf(s[j][2], s[j][3]));
        }
        mx0 = fmaxf(mx0, __shfl_xor_sync(0xffffffffu, mx0, 1));
        mx0 = fmaxf(mx0, __shfl_xor_sync(0xffffffffu, mx0, 2));
        mx1 = fmaxf(mx1, __shfl_xor_sync(0xffffffffu, mx1, 1));
        mx1 = fmaxf(mx1, __shfl_xor_sync(0xffffffffu, mx1, 2));
        float m0n = fmaxf(m0, mx0), m1n = fmaxf(m1, mx1);
        float c0 = exp2f((m0 - m0n) * L2E), c1 = exp2f((m1 - m1n) * L2E);
        float rs0 = 0.f, rs1 = 0.f;
        #pragma unroll
        for (int j = 0; j < 8; j++) {
            s[j][0] = exp2f((s[j][0] - m0n) * L2E);
            s[j][1] = exp2f((s[j][1] - m0n) * L2E);
            s[j][2] = exp2f((s[j][2] - m1n) * L2E);
            s[j][3] = exp2f((s[j][3] - m1n) * L2E);
            rs0 += s[j][0] + s[j][1];
            rs1 += s[j][2] + s[j][3];
        }
        rs0 += __shfl_xor_sync(0xffffffffu, rs0, 1);
        rs0 += __shfl_xor_sync(0xffffffffu, rs0, 2);
        rs1 += __shfl_xor_sync(0xffffffffu, rs1, 1);
        rs1 += __shfl_xor_sync(0xffffffffu, rs1, 2);
        l0 = l0 * c0 + rs0; l1 = l1 * c1 + rs1;
        m0 = m0n; m1 = m1n;
        #pragma unroll
        for (int j = 0; j < 8; j++) {
            o[j][0] *= c0; o[j][1] *= c0; o[j][2] *= c1; o[j][3] *= c1;
        }

        // ---- O += P @ V (1-term, P hi only) ----
        #pragma unroll
        for (int t = 0; t < 4; t++) {
            uint32_t ap[4];
            ap[0] = cvt2h(s[2*t][0],   s[2*t][1]);
            ap[1] = cvt2h(s[2*t][2],   s[2*t][3]);
            ap[2] = cvt2h(s[2*t+1][0], s[2*t+1][1]);
            ap[3] = cvt2h(s[2*t+1][2], s[2*t+1][3]);
            #pragma unroll
            for (int g = 0; g < 4; g++) {
                uint32_t vh[4];
                LDSM_X4T(vh, st + kv_fb + t * 16 * 144 + g * 32 + KV_VH);
                MMA16816(o[2*g],   ap, vh[0], vh[1]);
                MMA16816(o[2*g+1], ap, vh[2], vh[3]);
            }
        }
    }

    // ---- epilogue: hi-only fp16 out ----
    float inv0 = 1.f / l0, inv1 = 1.f / l1;
    size_t ob = (rowbase + q0 + r0) * EMB + h * HD + ccol;
    #pragma unroll
    for (int j = 0; j < 8; j++) {
        *(uint32_t*)(g_attn_h + ob + j * 8)           = cvt2h(o[j][0] * inv0, o[j][1] * inv0);
        *(uint32_t*)(g_attn_h + ob + 8 * EMB + j * 8) = cvt2h(o[j][2] * inv1, o[j][3] * inv1);
    }
}

// ---------------------------------------------------------------------------
extern "C" void kernel_launch(void* const* d_in, const int* in_sizes, int n_in,
                              void* d_out, int out_size) {
    const float* hidden = (const float*)d_in[0];   // [4096, 1024]
    const float* W_qkv  = (const float*)d_in[1];   // [1024, 3072]
    const float* W_out  = (const float*)d_in[2];   // [1024, 1024]
    const float* rel    = (const float*)d_in[3];   // [32, 16]
    float* out = (float*)d_out;                    // [4096, 1024]

    __half *ah, *al, *wqh, *wql, *woh, *qh, *ql, *ath;
    cudaGetSymbolAddress((void**)&ah,  g_ah);
    cudaGetSymbolAddress((void**)&al,  g_al);
    cudaGetSymbolAddress((void**)&wqh, g_wqh);
    cudaGetSymbolAddress((void**)&wql, g_wql);
    cudaGetSymbolAddress((void**)&woh, g_woh);
    cudaGetSymbolAddress((void**)&qh,  g_qkv_h);
    cudaGetSymbolAddress((void**)&ql,  g_qkv_l);
    cudaGetSymbolAddress((void**)&ath, g_attn_h);

    cudaFuncSetAttribute(qkv_kernel,
                         cudaFuncAttributeMaxDynamicSharedMemorySize, QKV_SMEM);
    cudaFuncSetAttribute(outproj_kernel,
                         cudaFuncAttributeMaxDynamicSharedMemorySize, OUT_SMEM);
    cudaFuncSetAttribute(attn_mma_kernel,
                         cudaFuncAttributeMaxDynamicSharedMemorySize, ATTN_SMEM);

    bias_kernel<<<(NBIAS + 255) / 256, 256>>>(rel);
    prep_kernel<<<(P1 + P2 + P3) / 256, 256>>>(hidden, W_qkv, W_out);

    // QKV projection: Q,K cols 3-term + V cols 2-term in one launch
    qkv_kernel<<<dim3(E3 / 128, NROWS / 128), 256, QKV_SMEM>>>(
        ah, al, wqh, wql, qh, ql);

    // attention
    attn_mma_kernel<<<dim3(SEQ / 128, BATCH * NH), 256, ATTN_SMEM>>>();

    // output projection: 1-term depth-3 -> fp32
    outproj_kernel<<<dim3(EMB / 128, NROWS / 128), 256, OUT_SMEM>>>(
        ath, woh, out);
}